// round 1
// baseline (speedup 1.0000x reference)
#include <cuda_runtime.h>
#include <cuda_bf16.h>
#include <math_constants.h>

// ---------------------------------------------------------------------------
// Problem constants
// ---------------------------------------------------------------------------
#define SEQ      2048
#define DIM      4096
#define NQH      32
#define NKVH     8
#define HD       128
#define SEG_LEN  512
#define N_SEG    4
#define QDIM     (NQH * HD)    // 4096
#define KVDIM    (NKVH * HD)   // 1024

// Scratch (device globals — no allocation allowed)
__device__ float g_q[SEQ * QDIM];
__device__ float g_k[SEQ * KVDIM];
__device__ float g_v[SEQ * KVDIM];
__device__ float g_o[SEQ * QDIM];

// ---------------------------------------------------------------------------
// SGEMM: C[M,N] = A[M,K] * B[N,K]^T   (both row-major, K inner — "NT" layout)
// BM=BN=128, BK=16, 256 threads, 8x8 register tile per thread.
// ---------------------------------------------------------------------------
__global__ __launch_bounds__(256) void sgemm_nt(const float* __restrict__ A,
                                                const float* __restrict__ B,
                                                float* __restrict__ C,
                                                int M, int N, int K) {
    const int BM = 128, BN = 128, BK = 16;
    __shared__ float As[BK][BM];
    __shared__ float Bs[BK][BN];

    const int bm = blockIdx.y * BM;
    const int bn = blockIdx.x * BN;
    const int tid = threadIdx.x;
    const int tx = tid & 15;       // 0..15 -> N
    const int ty = tid >> 4;       // 0..15 -> M

    const int lr = tid >> 2;       // 0..63 load row
    const int lc = tid & 3;        // 0..3  float4 col group

    float acc[8][8];
#pragma unroll
    for (int i = 0; i < 8; i++)
#pragma unroll
        for (int j = 0; j < 8; j++) acc[i][j] = 0.f;

    for (int k0 = 0; k0 < K; k0 += BK) {
#pragma unroll
        for (int i = 0; i < 2; i++) {
            int row = lr + i * 64;
            float4 va = *(const float4*)&A[(size_t)(bm + row) * K + k0 + lc * 4];
            As[lc * 4 + 0][row] = va.x;
            As[lc * 4 + 1][row] = va.y;
            As[lc * 4 + 2][row] = va.z;
            As[lc * 4 + 3][row] = va.w;
            float4 vb = *(const float4*)&B[(size_t)(bn + row) * K + k0 + lc * 4];
            Bs[lc * 4 + 0][row] = vb.x;
            Bs[lc * 4 + 1][row] = vb.y;
            Bs[lc * 4 + 2][row] = vb.z;
            Bs[lc * 4 + 3][row] = vb.w;
        }
        __syncthreads();

#pragma unroll
        for (int kk = 0; kk < BK; kk++) {
            float a[8], b[8];
            *(float4*)&a[0] = *(const float4*)&As[kk][ty * 8];
            *(float4*)&a[4] = *(const float4*)&As[kk][ty * 8 + 4];
            *(float4*)&b[0] = *(const float4*)&Bs[kk][tx * 8];
            *(float4*)&b[4] = *(const float4*)&Bs[kk][tx * 8 + 4];
#pragma unroll
            for (int i = 0; i < 8; i++)
#pragma unroll
                for (int j = 0; j < 8; j++)
                    acc[i][j] = fmaf(a[i], b[j], acc[i][j]);
        }
        __syncthreads();
    }

#pragma unroll
    for (int i = 0; i < 8; i++) {
        int row = bm + ty * 8 + i;
        float4* p = (float4*)&C[(size_t)row * N + bn + tx * 8];
        p[0] = make_float4(acc[i][0], acc[i][1], acc[i][2], acc[i][3]);
        p[1] = make_float4(acc[i][4], acc[i][5], acc[i][6], acc[i][7]);
    }
}

// ---------------------------------------------------------------------------
// Fused per-head RMSNorm + RoPE (in place).
// grid (SEQ, n_heads), block 128 threads (= HD).
// ---------------------------------------------------------------------------
__global__ __launch_bounds__(128) void rmsnorm_rope(float* __restrict__ data,
                                                    const float* __restrict__ w,
                                                    const float* __restrict__ rope,   // [SEQ][64][2]
                                                    const int* __restrict__ pos,      // [SEQ]
                                                    int stride) {
    const int tok = blockIdx.x;
    const int h = blockIdx.y;
    const int t = threadIdx.x;

    float* p = data + (size_t)tok * stride + h * HD;
    float v = p[t];

    // sum of squares over 128 lanes (4 warps)
    float ss = v * v;
#pragma unroll
    for (int off = 16; off; off >>= 1) ss += __shfl_xor_sync(0xffffffffu, ss, off);
    __shared__ float red[4];
    if ((t & 31) == 0) red[t >> 5] = ss;
    __syncthreads();
    float tot = red[0] + red[1] + red[2] + red[3];
    float inv = rsqrtf(tot * (1.0f / HD) + 1e-6f);
    float nv = v * inv * w[t];

    __shared__ float sh[HD];
    sh[t] = nv;
    __syncthreads();

    int pp = pos[tok];
    float out;
    if (t < 64) {
        float c = rope[(pp * 64 + t) * 2 + 0];
        float s = rope[(pp * 64 + t) * 2 + 1];
        out = nv * c - sh[t + 64] * s;       // x1*cos - x2*sin
    } else {
        int f = t - 64;
        float c = rope[(pp * 64 + f) * 2 + 0];
        float s = rope[(pp * 64 + f) * 2 + 1];
        out = nv * c + sh[f] * s;            // x2*cos + x1*sin
    }
    p[t] = out;
}

// ---------------------------------------------------------------------------
// Flash attention, segmented causal. BQ=BK=64, 256 threads.
// grid = (8 qblocks, 4 segs, 32 heads)
// smem: Qs[64][128] | Kt[128][65] | Vs[64][128] | Ps[64][64]
// ---------------------------------------------------------------------------
#define KT_PITCH 65
#define SMEM_ATTN ((64 * 128 + 128 * KT_PITCH + 64 * 128 + 64 * 64) * 4)

__global__ __launch_bounds__(256) void attn_kernel(const float* __restrict__ Q,
                                                   const float* __restrict__ K,
                                                   const float* __restrict__ V,
                                                   float* __restrict__ O) {
    const int qb = blockIdx.x;
    const int seg = blockIdx.y;
    const int qh = blockIdx.z;
    const int kvh = qh >> 2;

    extern __shared__ float sm[];
    float* Qs = sm;                        // [64][128]
    float* Kt = Qs + 64 * 128;             // [128][65]
    float* Vs = Kt + 128 * KT_PITCH;       // [64][128]
    float* Ps = Vs + 64 * 128;             // [64][64]

    const int tid = threadIdx.x;
    const int tx = tid & 15;
    const int ty = tid >> 4;

    const float scale = 0.08838834764831845f;   // 1/sqrt(128)
    const int qtok0 = seg * SEG_LEN + qb * 64;

    // Load Q tile (scaled)
    for (int i = tid; i < 64 * 32; i += 256) {
        int r = i >> 5, c4 = i & 31;
        float4 v = *(const float4*)&Q[(size_t)(qtok0 + r) * QDIM + qh * HD + c4 * 4];
        v.x *= scale; v.y *= scale; v.z *= scale; v.w *= scale;
        *(float4*)&Qs[r * 128 + c4 * 4] = v;
    }

    float m[4], l[4], o[4][8];
#pragma unroll
    for (int rr = 0; rr < 4; rr++) {
        m[rr] = -CUDART_INF_F;
        l[rr] = 0.f;
#pragma unroll
        for (int j = 0; j < 8; j++) o[rr][j] = 0.f;
    }

    const int nkb = qb + 1;
    for (int kb = 0; kb < nkb; kb++) {
        __syncthreads();   // prev O-phase done (and, for kb=0, cheap)
        const int ktok0 = seg * SEG_LEN + kb * 64;
        for (int i = tid; i < 64 * 32; i += 256) {
            int r = i >> 5, c4 = i & 31;
            float4 kv = *(const float4*)&K[(size_t)(ktok0 + r) * KVDIM + kvh * HD + c4 * 4];
            Kt[(c4 * 4 + 0) * KT_PITCH + r] = kv.x;
            Kt[(c4 * 4 + 1) * KT_PITCH + r] = kv.y;
            Kt[(c4 * 4 + 2) * KT_PITCH + r] = kv.z;
            Kt[(c4 * 4 + 3) * KT_PITCH + r] = kv.w;
            float4 vv = *(const float4*)&V[(size_t)(ktok0 + r) * KVDIM + kvh * HD + c4 * 4];
            *(float4*)&Vs[r * 128 + c4 * 4] = vv;
        }
        __syncthreads();

        // S = Qs @ Kt^T ; thread owns rows ty*4+rr, cols tx + cc*16
        float s[4][4];
#pragma unroll
        for (int rr = 0; rr < 4; rr++)
#pragma unroll
            for (int cc = 0; cc < 4; cc++) s[rr][cc] = 0.f;

        for (int d = 0; d < HD; d++) {
            float a[4], b[4];
#pragma unroll
            for (int rr = 0; rr < 4; rr++) a[rr] = Qs[(ty * 4 + rr) * 128 + d];
#pragma unroll
            for (int cc = 0; cc < 4; cc++) b[cc] = Kt[d * KT_PITCH + tx + cc * 16];
#pragma unroll
            for (int rr = 0; rr < 4; rr++)
#pragma unroll
                for (int cc = 0; cc < 4; cc++)
                    s[rr][cc] = fmaf(a[rr], b[cc], s[rr][cc]);
        }

        if (kb == qb) {
#pragma unroll
            for (int rr = 0; rr < 4; rr++)
#pragma unroll
                for (int cc = 0; cc < 4; cc++) {
                    int r = ty * 4 + rr, c = tx + cc * 16;
                    if (c > r) s[rr][cc] = -CUDART_INF_F;
                }
        }

        // online softmax per row (16-lane reduce; lanes tx share a row group)
#pragma unroll
        for (int rr = 0; rr < 4; rr++) {
            float mx = s[rr][0];
#pragma unroll
            for (int cc = 1; cc < 4; cc++) mx = fmaxf(mx, s[rr][cc]);
#pragma unroll
            for (int off = 8; off; off >>= 1)
                mx = fmaxf(mx, __shfl_xor_sync(0xffffffffu, mx, off));
            float mnew = fmaxf(m[rr], mx);
            float alpha = (m[rr] == -CUDART_INF_F) ? 0.f : __expf(m[rr] - mnew);
            float psum = 0.f;
#pragma unroll
            for (int cc = 0; cc < 4; cc++) {
                float pv = (s[rr][cc] == -CUDART_INF_F) ? 0.f : __expf(s[rr][cc] - mnew);
                s[rr][cc] = pv;
                psum += pv;
            }
#pragma unroll
            for (int off = 8; off; off >>= 1)
                psum += __shfl_xor_sync(0xffffffffu, psum, off);
            l[rr] = l[rr] * alpha + psum;
            m[rr] = mnew;
#pragma unroll
            for (int j = 0; j < 8; j++) o[rr][j] *= alpha;
        }

        // write P to smem
#pragma unroll
        for (int rr = 0; rr < 4; rr++)
#pragma unroll
            for (int cc = 0; cc < 4; cc++)
                Ps[(ty * 4 + rr) * 64 + tx + cc * 16] = s[rr][cc];
        __syncthreads();

        // O += P @ V ; thread owns rows ty*4+rr, cols tx + j*16
        for (int c = 0; c < 64; c++) {
            float b[8];
#pragma unroll
            for (int j = 0; j < 8; j++) b[j] = Vs[c * 128 + tx + j * 16];
#pragma unroll
            for (int rr = 0; rr < 4; rr++) {
                float pv = Ps[(ty * 4 + rr) * 64 + c];
#pragma unroll
                for (int j = 0; j < 8; j++) o[rr][j] = fmaf(pv, b[j], o[rr][j]);
            }
        }
    }

    // epilogue
#pragma unroll
    for (int rr = 0; rr < 4; rr++) {
        float linv = 1.0f / l[rr];
        int row = qtok0 + ty * 4 + rr;
#pragma unroll
        for (int j = 0; j < 8; j++)
            O[(size_t)row * QDIM + qh * HD + tx + j * 16] = o[rr][j] * linv;
    }
}

// ---------------------------------------------------------------------------
// Launch
// ---------------------------------------------------------------------------
extern "C" void kernel_launch(void* const* d_in, const int* in_sizes, int n_in,
                              void* d_out, int out_size) {
    const float* x    = (const float*)d_in[0];
    const float* wq   = (const float*)d_in[1];
    const float* wk   = (const float*)d_in[2];
    const float* wv   = (const float*)d_in[3];
    const float* wo   = (const float*)d_in[4];
    const float* qnw  = (const float*)d_in[5];
    const float* knw  = (const float*)d_in[6];
    const float* rope = (const float*)d_in[7];
    const int*   pos  = (const int*)d_in[8];
    // d_in[9] = cu_seqlens (uniform segments, constants hardcoded)

    float *q, *k, *v, *o;
    cudaGetSymbolAddress((void**)&q, g_q);
    cudaGetSymbolAddress((void**)&k, g_k);
    cudaGetSymbolAddress((void**)&v, g_v);
    cudaGetSymbolAddress((void**)&o, g_o);

    // QKV projections
    sgemm_nt<<<dim3(QDIM / 128, SEQ / 128), 256>>>(x, wq, q, SEQ, QDIM, DIM);
    sgemm_nt<<<dim3(KVDIM / 128, SEQ / 128), 256>>>(x, wk, k, SEQ, KVDIM, DIM);
    sgemm_nt<<<dim3(KVDIM / 128, SEQ / 128), 256>>>(x, wv, v, SEQ, KVDIM, DIM);

    // RMSNorm + RoPE on q and k
    rmsnorm_rope<<<dim3(SEQ, NQH), 128>>>(q, qnw, rope, pos, QDIM);
    rmsnorm_rope<<<dim3(SEQ, NKVH), 128>>>(k, knw, rope, pos, KVDIM);

    // Attention
    cudaFuncSetAttribute(attn_kernel, cudaFuncAttributeMaxDynamicSharedMemorySize, SMEM_ATTN);
    attn_kernel<<<dim3(SEG_LEN / 64, N_SEG, NQH), 256, SMEM_ATTN>>>(q, k, v, o);

    // Output projection
    sgemm_nt<<<dim3(DIM / 128, SEQ / 128), 256>>>(o, wo, (float*)d_out, SEQ, DIM, QDIM);
}

// round 3
// speedup vs baseline: 2.2238x; 2.2238x over previous
#include <cuda_runtime.h>
#include <cuda_bf16.h>
#include <math_constants.h>
#include <cstdint>

// ---------------------------------------------------------------------------
// Problem constants
// ---------------------------------------------------------------------------
#define SEQ      2048
#define DIM      4096
#define NQH      32
#define NKVH     8
#define HD       128
#define SEG_LEN  512
#define N_SEG    4
#define QDIM     (NQH * HD)    // 4096
#define KVDIM    (NKVH * HD)   // 1024

// fp32 scratch
__device__ float g_q[SEQ * QDIM];
__device__ float g_k[SEQ * KVDIM];
__device__ float g_v[SEQ * KVDIM];
__device__ float g_o[SEQ * QDIM];

// bf16 split scratch (hi/lo)
__device__ __nv_bfloat16 g_xh[SEQ * DIM],    g_xl[SEQ * DIM];
__device__ __nv_bfloat16 g_wqh[QDIM * DIM],  g_wql[QDIM * DIM];
__device__ __nv_bfloat16 g_wkh[KVDIM * DIM], g_wkl[KVDIM * DIM];
__device__ __nv_bfloat16 g_wvh[KVDIM * DIM], g_wvl[KVDIM * DIM];
__device__ __nv_bfloat16 g_woh[DIM * QDIM],  g_wol[DIM * QDIM];
__device__ __nv_bfloat16 g_oh[SEQ * QDIM],   g_ol[SEQ * QDIM];

// ---------------------------------------------------------------------------
// Portable-ISA helpers (sm_80+ — assemble fine for base sm_103 target)
// ---------------------------------------------------------------------------
__device__ __forceinline__ uint32_t smem_u32(const void* p) {
    uint32_t a;
    asm("{ .reg .u64 t; cvta.to.shared.u64 t, %1; cvt.u32.u64 %0, t; }" : "=r"(a) : "l"(p));
    return a;
}
__device__ __forceinline__ void cp_async16(uint32_t dst, const void* src) {
    asm volatile("cp.async.cg.shared.global [%0], [%1], 16;" :: "r"(dst), "l"(src) : "memory");
}
__device__ __forceinline__ void cp_commit() {
    asm volatile("cp.async.commit_group;" ::: "memory");
}
__device__ __forceinline__ void cp_wait2() {
    asm volatile("cp.async.wait_group 2;" ::: "memory");
}
__device__ __forceinline__ void ldsm_x4(uint32_t addr, uint32_t& r0, uint32_t& r1,
                                        uint32_t& r2, uint32_t& r3) {
    asm volatile("ldmatrix.sync.aligned.m8n8.x4.shared.b16 {%0,%1,%2,%3}, [%4];"
                 : "=r"(r0), "=r"(r1), "=r"(r2), "=r"(r3) : "r"(addr));
}
__device__ __forceinline__ void mma_bf16(float* d, const uint32_t* a, const uint32_t* b) {
    asm volatile("mma.sync.aligned.m16n8k16.row.col.f32.bf16.bf16.f32 "
                 "{%0,%1,%2,%3}, {%4,%5,%6,%7}, {%8,%9}, {%0,%1,%2,%3};"
                 : "+f"(d[0]), "+f"(d[1]), "+f"(d[2]), "+f"(d[3])
                 : "r"(a[0]), "r"(a[1]), "r"(a[2]), "r"(a[3]), "r"(b[0]), "r"(b[1]));
}

// ---------------------------------------------------------------------------
// Split-bf16 tensor-core GEMM: C[M,N] = A[M,K] * B[N,K]^T, fp32-accurate via
// Ah*Bh + Ah*Bl + Al*Bh. CTA tile 128x128, BK=32, 8 warps (2x4) of 64x32.
// 3-stage cp.async pipeline. 256 threads. grid = (N/128, M/128).
// ---------------------------------------------------------------------------
#define BM 128
#define BN 128
#define BK 32
#define TPITCH 80                      // 64B data + 16B pad; conflict-free ldmatrix
#define TILE_BYTES (128 * TPITCH)      // 10240
#define STG_BYTES  (4 * TILE_BYTES)    // Ah|Al|Bh|Bl = 40960
#define NSTAGE 3
#define GEMM_SMEM (NSTAGE * STG_BYTES) // 122880

__global__ __launch_bounds__(256) void gemm_splitbf16(
    const __nv_bfloat16* __restrict__ Ah, const __nv_bfloat16* __restrict__ Al,
    const __nv_bfloat16* __restrict__ Bh, const __nv_bfloat16* __restrict__ Bl,
    float* __restrict__ C, int M, int N, int K)
{
    extern __shared__ char smg[];
    const uint32_t sbase = smem_u32(smg);

    const int tid = threadIdx.x;
    const int wid = tid >> 5;
    const int lane = tid & 31;
    const int wm = wid & 1;            // 2 m-slabs of 64
    const int wn = wid >> 1;           // 4 n-slabs of 32
    const int bm = blockIdx.y * BM;
    const int bn = blockIdx.x * BN;

    float acc[4][4][4];
#pragma unroll
    for (int mt = 0; mt < 4; mt++)
#pragma unroll
        for (int nt = 0; nt < 4; nt++)
#pragma unroll
            for (int j = 0; j < 4; j++) acc[mt][nt][j] = 0.f;

    const int NC = K / BK;

    auto prefetch = [&](int c, int s) {
        const int k0 = c * BK;
        const uint32_t sb = sbase + s * STG_BYTES;
#pragma unroll
        for (int i = tid; i < 512; i += 256) {
            int row = i >> 2, q = i & 3;
            uint32_t d = sb + row * TPITCH + q * 16;
            size_t ga = (size_t)(bm + row) * K + k0 + q * 8;
            size_t gb = (size_t)(bn + row) * K + k0 + q * 8;
            cp_async16(d,                  Ah + ga);
            cp_async16(d + TILE_BYTES,     Al + ga);
            cp_async16(d + 2 * TILE_BYTES, Bh + gb);
            cp_async16(d + 3 * TILE_BYTES, Bl + gb);
        }
        cp_commit();
    };

    auto compute = [&](int s) {
        const uint32_t aB = sbase + s * STG_BYTES;
        const uint32_t bB = aB + 2 * TILE_BYTES;
        const int g = lane >> 3, r = lane & 7;
#pragma unroll
        for (int ks = 0; ks < 2; ks++) {
            const int kb = ks * 32;
            // B fragments: 2 x ldmatrix.x4 each for hi and lo (4 n-tiles)
            uint32_t bh[4][2], bl[4][2];
#pragma unroll
            for (int p = 0; p < 2; p++) {
                int nt = 2 * p + (g >> 1);
                uint32_t addr = bB + (wn * 32 + nt * 8 + r) * TPITCH + kb + (g & 1) * 16;
                ldsm_x4(addr, bh[2 * p][0], bh[2 * p][1], bh[2 * p + 1][0], bh[2 * p + 1][1]);
                ldsm_x4(addr + TILE_BYTES, bl[2 * p][0], bl[2 * p][1], bl[2 * p + 1][0], bl[2 * p + 1][1]);
            }
#pragma unroll
            for (int mt = 0; mt < 4; mt++) {
                int arow = wm * 64 + mt * 16 + (g & 1) * 8 + r;
                uint32_t aaddr = aB + arow * TPITCH + kb + (g >> 1) * 16;
                uint32_t ah[4], al[4];
                ldsm_x4(aaddr, ah[0], ah[1], ah[2], ah[3]);
                ldsm_x4(aaddr + TILE_BYTES, al[0], al[1], al[2], al[3]);
#pragma unroll
                for (int nt = 0; nt < 4; nt++) {
                    mma_bf16(acc[mt][nt], ah, bh[nt]);
                    mma_bf16(acc[mt][nt], ah, bl[nt]);
                    mma_bf16(acc[mt][nt], al, bh[nt]);
                }
            }
        }
    };

    prefetch(0, 0);
    prefetch(1, 1);
    prefetch(2, 2);

    for (int c = 0; c < NC; c++) {
        int s = c % 3;
        cp_wait2();
        __syncthreads();
        compute(s);
        __syncthreads();
        if (c + 3 < NC) prefetch(c + 3, s);
        else cp_commit();   // keep group accounting uniform
    }

    // epilogue
    const int er = lane >> 2, ec = (lane & 3) * 2;
#pragma unroll
    for (int mt = 0; mt < 4; mt++) {
#pragma unroll
        for (int nt = 0; nt < 4; nt++) {
            int row = bm + wm * 64 + mt * 16 + er;
            int col = bn + wn * 32 + nt * 8 + ec;
            *(float2*)&C[(size_t)row * N + col]       = make_float2(acc[mt][nt][0], acc[mt][nt][1]);
            *(float2*)&C[(size_t)(row + 8) * N + col] = make_float2(acc[mt][nt][2], acc[mt][nt][3]);
        }
    }
}

// ---------------------------------------------------------------------------
// fp32 -> (bf16 hi, bf16 lo) split conversion, vectorized by 4
// ---------------------------------------------------------------------------
__global__ __launch_bounds__(256) void split_bf16(const float4* __restrict__ in,
                                                  uint2* __restrict__ hi,
                                                  uint2* __restrict__ lo, int n4) {
    int i = blockIdx.x * blockDim.x + threadIdx.x;
    if (i >= n4) return;
    float4 v = in[i];
    __nv_bfloat16 h0 = __float2bfloat16(v.x), h1 = __float2bfloat16(v.y);
    __nv_bfloat16 h2 = __float2bfloat16(v.z), h3 = __float2bfloat16(v.w);
    __nv_bfloat16 l0 = __float2bfloat16(v.x - __bfloat162float(h0));
    __nv_bfloat16 l1 = __float2bfloat16(v.y - __bfloat162float(h1));
    __nv_bfloat16 l2 = __float2bfloat16(v.z - __bfloat162float(h2));
    __nv_bfloat16 l3 = __float2bfloat16(v.w - __bfloat162float(h3));
    unsigned short u0 = *(unsigned short*)&h0, u1 = *(unsigned short*)&h1;
    unsigned short u2 = *(unsigned short*)&h2, u3 = *(unsigned short*)&h3;
    hi[i] = make_uint2((uint32_t)u0 | ((uint32_t)u1 << 16), (uint32_t)u2 | ((uint32_t)u3 << 16));
    u0 = *(unsigned short*)&l0; u1 = *(unsigned short*)&l1;
    u2 = *(unsigned short*)&l2; u3 = *(unsigned short*)&l3;
    lo[i] = make_uint2((uint32_t)u0 | ((uint32_t)u1 << 16), (uint32_t)u2 | ((uint32_t)u3 << 16));
}

// ---------------------------------------------------------------------------
// Fused per-head RMSNorm + RoPE (in place). grid (SEQ, n_heads), 128 threads.
// ---------------------------------------------------------------------------
__global__ __launch_bounds__(128) void rmsnorm_rope(float* __restrict__ data,
                                                    const float* __restrict__ w,
                                                    const float* __restrict__ rope,
                                                    const int* __restrict__ pos,
                                                    int stride) {
    const int tok = blockIdx.x;
    const int h = blockIdx.y;
    const int t = threadIdx.x;

    float* p = data + (size_t)tok * stride + h * HD;
    float v = p[t];

    float ss = v * v;
#pragma unroll
    for (int off = 16; off; off >>= 1) ss += __shfl_xor_sync(0xffffffffu, ss, off);
    __shared__ float red[4];
    if ((t & 31) == 0) red[t >> 5] = ss;
    __syncthreads();
    float tot = red[0] + red[1] + red[2] + red[3];
    float inv = rsqrtf(tot * (1.0f / HD) + 1e-6f);
    float nv = v * inv * w[t];

    __shared__ float sh[HD];
    sh[t] = nv;
    __syncthreads();

    int pp = pos[tok];
    float out;
    if (t < 64) {
        float c = rope[(pp * 64 + t) * 2 + 0];
        float s = rope[(pp * 64 + t) * 2 + 1];
        out = nv * c - sh[t + 64] * s;
    } else {
        int f = t - 64;
        float c = rope[(pp * 64 + f) * 2 + 0];
        float s = rope[(pp * 64 + f) * 2 + 1];
        out = nv * c + sh[f] * s;
    }
    p[t] = out;
}

// ---------------------------------------------------------------------------
// Flash attention, segmented causal. BQ=BK=64, 256 threads.
// ---------------------------------------------------------------------------
#define KT_PITCH 65
#define SMEM_ATTN ((64 * 128 + 128 * KT_PITCH + 64 * 128 + 64 * 64) * 4)

__global__ __launch_bounds__(256) void attn_kernel(const float* __restrict__ Q,
                                                   const float* __restrict__ K,
                                                   const float* __restrict__ V,
                                                   float* __restrict__ O) {
    const int qb = blockIdx.x;
    const int seg = blockIdx.y;
    const int qh = blockIdx.z;
    const int kvh = qh >> 2;

    extern __shared__ float sm[];
    float* Qs = sm;
    float* Kt = Qs + 64 * 128;
    float* Vs = Kt + 128 * KT_PITCH;
    float* Ps = Vs + 64 * 128;

    const int tid = threadIdx.x;
    const int tx = tid & 15;
    const int ty = tid >> 4;

    const float scale = 0.08838834764831845f;
    const int qtok0 = seg * SEG_LEN + qb * 64;

    for (int i = tid; i < 64 * 32; i += 256) {
        int r = i >> 5, c4 = i & 31;
        float4 v = *(const float4*)&Q[(size_t)(qtok0 + r) * QDIM + qh * HD + c4 * 4];
        v.x *= scale; v.y *= scale; v.z *= scale; v.w *= scale;
        *(float4*)&Qs[r * 128 + c4 * 4] = v;
    }

    float m[4], l[4], o[4][8];
#pragma unroll
    for (int rr = 0; rr < 4; rr++) {
        m[rr] = -CUDART_INF_F;
        l[rr] = 0.f;
#pragma unroll
        for (int j = 0; j < 8; j++) o[rr][j] = 0.f;
    }

    const int nkb = qb + 1;
    for (int kb = 0; kb < nkb; kb++) {
        __syncthreads();
        const int ktok0 = seg * SEG_LEN + kb * 64;
        for (int i = tid; i < 64 * 32; i += 256) {
            int r = i >> 5, c4 = i & 31;
            float4 kv = *(const float4*)&K[(size_t)(ktok0 + r) * KVDIM + kvh * HD + c4 * 4];
            Kt[(c4 * 4 + 0) * KT_PITCH + r] = kv.x;
            Kt[(c4 * 4 + 1) * KT_PITCH + r] = kv.y;
            Kt[(c4 * 4 + 2) * KT_PITCH + r] = kv.z;
            Kt[(c4 * 4 + 3) * KT_PITCH + r] = kv.w;
            float4 vv = *(const float4*)&V[(size_t)(ktok0 + r) * KVDIM + kvh * HD + c4 * 4];
            *(float4*)&Vs[r * 128 + c4 * 4] = vv;
        }
        __syncthreads();

        float s[4][4];
#pragma unroll
        for (int rr = 0; rr < 4; rr++)
#pragma unroll
            for (int cc = 0; cc < 4; cc++) s[rr][cc] = 0.f;

        for (int d = 0; d < HD; d++) {
            float a[4], b[4];
#pragma unroll
            for (int rr = 0; rr < 4; rr++) a[rr] = Qs[(ty * 4 + rr) * 128 + d];
#pragma unroll
            for (int cc = 0; cc < 4; cc++) b[cc] = Kt[d * KT_PITCH + tx + cc * 16];
#pragma unroll
            for (int rr = 0; rr < 4; rr++)
#pragma unroll
                for (int cc = 0; cc < 4; cc++)
                    s[rr][cc] = fmaf(a[rr], b[cc], s[rr][cc]);
        }

        if (kb == qb) {
#pragma unroll
            for (int rr = 0; rr < 4; rr++)
#pragma unroll
                for (int cc = 0; cc < 4; cc++) {
                    int r = ty * 4 + rr, c = tx + cc * 16;
                    if (c > r) s[rr][cc] = -CUDART_INF_F;
                }
        }

#pragma unroll
        for (int rr = 0; rr < 4; rr++) {
            float mx = s[rr][0];
#pragma unroll
            for (int cc = 1; cc < 4; cc++) mx = fmaxf(mx, s[rr][cc]);
#pragma unroll
            for (int off = 8; off; off >>= 1)
                mx = fmaxf(mx, __shfl_xor_sync(0xffffffffu, mx, off));
            float mnew = fmaxf(m[rr], mx);
            float alpha = (m[rr] == -CUDART_INF_F) ? 0.f : __expf(m[rr] - mnew);
            float psum = 0.f;
#pragma unroll
            for (int cc = 0; cc < 4; cc++) {
                float pv = (s[rr][cc] == -CUDART_INF_F) ? 0.f : __expf(s[rr][cc] - mnew);
                s[rr][cc] = pv;
                psum += pv;
            }
#pragma unroll
            for (int off = 8; off; off >>= 1)
                psum += __shfl_xor_sync(0xffffffffu, psum, off);
            l[rr] = l[rr] * alpha + psum;
            m[rr] = mnew;
#pragma unroll
            for (int j = 0; j < 8; j++) o[rr][j] *= alpha;
        }

#pragma unroll
        for (int rr = 0; rr < 4; rr++)
#pragma unroll
            for (int cc = 0; cc < 4; cc++)
                Ps[(ty * 4 + rr) * 64 + tx + cc * 16] = s[rr][cc];
        __syncthreads();

        for (int c = 0; c < 64; c++) {
            float b[8];
#pragma unroll
            for (int j = 0; j < 8; j++) b[j] = Vs[c * 128 + tx + j * 16];
#pragma unroll
            for (int rr = 0; rr < 4; rr++) {
                float pv = Ps[(ty * 4 + rr) * 64 + c];
#pragma unroll
                for (int j = 0; j < 8; j++) o[rr][j] = fmaf(pv, b[j], o[rr][j]);
            }
        }
    }

#pragma unroll
    for (int rr = 0; rr < 4; rr++) {
        float linv = 1.0f / l[rr];
        int row = qtok0 + ty * 4 + rr;
#pragma unroll
        for (int j = 0; j < 8; j++)
            O[(size_t)row * QDIM + qh * HD + tx + j * 16] = o[rr][j] * linv;
    }
}

// ---------------------------------------------------------------------------
// Launch
// ---------------------------------------------------------------------------
static void run_split(const float* src, __nv_bfloat16* hi, __nv_bfloat16* lo, int n) {
    int n4 = n / 4;
    split_bf16<<<(n4 + 255) / 256, 256>>>((const float4*)src, (uint2*)hi, (uint2*)lo, n4);
}

extern "C" void kernel_launch(void* const* d_in, const int* in_sizes, int n_in,
                              void* d_out, int out_size) {
    const float* x    = (const float*)d_in[0];
    const float* wq   = (const float*)d_in[1];
    const float* wk   = (const float*)d_in[2];
    const float* wv   = (const float*)d_in[3];
    const float* wo   = (const float*)d_in[4];
    const float* qnw  = (const float*)d_in[5];
    const float* knw  = (const float*)d_in[6];
    const float* rope = (const float*)d_in[7];
    const int*   pos  = (const int*)d_in[8];

    float *q, *k, *v, *o;
    cudaGetSymbolAddress((void**)&q, g_q);
    cudaGetSymbolAddress((void**)&k, g_k);
    cudaGetSymbolAddress((void**)&v, g_v);
    cudaGetSymbolAddress((void**)&o, g_o);

    __nv_bfloat16 *xh, *xl, *wqh, *wql, *wkh, *wkl, *wvh, *wvl, *woh, *wol, *oh, *ol;
    cudaGetSymbolAddress((void**)&xh, g_xh);   cudaGetSymbolAddress((void**)&xl, g_xl);
    cudaGetSymbolAddress((void**)&wqh, g_wqh); cudaGetSymbolAddress((void**)&wql, g_wql);
    cudaGetSymbolAddress((void**)&wkh, g_wkh); cudaGetSymbolAddress((void**)&wkl, g_wkl);
    cudaGetSymbolAddress((void**)&wvh, g_wvh); cudaGetSymbolAddress((void**)&wvl, g_wvl);
    cudaGetSymbolAddress((void**)&woh, g_woh); cudaGetSymbolAddress((void**)&wol, g_wol);
    cudaGetSymbolAddress((void**)&oh, g_oh);   cudaGetSymbolAddress((void**)&ol, g_ol);

    cudaFuncSetAttribute(gemm_splitbf16, cudaFuncAttributeMaxDynamicSharedMemorySize, GEMM_SMEM);
    cudaFuncSetAttribute(attn_kernel, cudaFuncAttributeMaxDynamicSharedMemorySize, SMEM_ATTN);

    // Conversions
    run_split(x, xh, xl, SEQ * DIM);
    run_split(wq, wqh, wql, QDIM * DIM);
    run_split(wk, wkh, wkl, KVDIM * DIM);
    run_split(wv, wvh, wvl, KVDIM * DIM);
    run_split(wo, woh, wol, DIM * QDIM);

    // QKV projections (tensor cores, split-bf16)
    gemm_splitbf16<<<dim3(QDIM / BN, SEQ / BM), 256, GEMM_SMEM>>>(xh, xl, wqh, wql, q, SEQ, QDIM, DIM);
    gemm_splitbf16<<<dim3(KVDIM / BN, SEQ / BM), 256, GEMM_SMEM>>>(xh, xl, wkh, wkl, k, SEQ, KVDIM, DIM);
    gemm_splitbf16<<<dim3(KVDIM / BN, SEQ / BM), 256, GEMM_SMEM>>>(xh, xl, wvh, wvl, v, SEQ, KVDIM, DIM);

    // RMSNorm + RoPE
    rmsnorm_rope<<<dim3(SEQ, NQH), 128>>>(q, qnw, rope, pos, QDIM);
    rmsnorm_rope<<<dim3(SEQ, NKVH), 128>>>(k, knw, rope, pos, KVDIM);

    // Attention (fp32 flash)
    attn_kernel<<<dim3(SEG_LEN / 64, N_SEG, NQH), 256, SMEM_ATTN>>>(q, k, v, o);

    // Output projection
    run_split(o, oh, ol, SEQ * QDIM);
    gemm_splitbf16<<<dim3(DIM / BN, SEQ / BM), 256, GEMM_SMEM>>>(oh, ol, woh, wol, (float*)d_out, SEQ, DIM, QDIM);
}

// round 4
// speedup vs baseline: 3.0262x; 1.3608x over previous
#include <cuda_runtime.h>
#include <cuda_bf16.h>
#include <math_constants.h>
#include <cstdint>

// ---------------------------------------------------------------------------
// Problem constants
// ---------------------------------------------------------------------------
#define SEQ      2048
#define DIM      4096
#define NQH      32
#define NKVH     8
#define HD       128
#define SEG_LEN  512
#define N_SEG    4
#define QDIM     (NQH * HD)    // 4096
#define KVDIM    (NKVH * HD)   // 1024
#define KVSTRIDE 2048          // fused K|V row stride
#define KC       (DIM / 32)    // 128 k-chunks (all GEMMs have K=4096)

// fp32 scratch
__device__ float g_q[SEQ * QDIM];
__device__ float g_kv[SEQ * KVSTRIDE];   // [tok][ k(0:1024) | v(1024:2048) ]
__device__ float g_o[SEQ * QDIM];

// packed + swizzled bf16 split operands
__device__ __nv_bfloat16 g_xh[SEQ * DIM],     g_xl[SEQ * DIM];       // A-layout (128-row blocks)
__device__ __nv_bfloat16 g_oh[SEQ * QDIM],    g_ol[SEQ * QDIM];      // A-layout
__device__ __nv_bfloat16 g_wqh[QDIM * DIM],   g_wql[QDIM * DIM];     // B-layout (256-row blocks)
__device__ __nv_bfloat16 g_wkvh[2048 * DIM],  g_wkvl[2048 * DIM];    // B-layout, wk rows 0-1023, wv 1024-2047
__device__ __nv_bfloat16 g_woh[DIM * QDIM],   g_wol[DIM * QDIM];     // B-layout

// ---------------------------------------------------------------------------
// PTX helpers (base-target instructions only: sm_90 bulk-async + sm_80 mma)
// ---------------------------------------------------------------------------
__device__ __forceinline__ uint32_t smem_u32(const void* p) {
    uint32_t a;
    asm("{ .reg .u64 t; cvta.to.shared.u64 t, %1; cvt.u32.u64 %0, t; }" : "=r"(a) : "l"(p));
    return a;
}
__device__ __forceinline__ void mbar_init(uint32_t addr, uint32_t cnt) {
    asm volatile("mbarrier.init.shared.b64 [%0], %1;" :: "r"(addr), "r"(cnt) : "memory");
}
__device__ __forceinline__ void mbar_expect_tx(uint32_t addr, uint32_t bytes) {
    asm volatile("mbarrier.arrive.expect_tx.shared.b64 _, [%0], %1;" :: "r"(addr), "r"(bytes) : "memory");
}
__device__ __forceinline__ void mbar_wait(uint32_t addr, uint32_t parity) {
    uint32_t done;
    asm volatile("{\n\t.reg .pred p;\n\t"
                 "mbarrier.try_wait.parity.acquire.cta.shared::cta.b64 p, [%1], %2;\n\t"
                 "selp.b32 %0, 1, 0, p;\n\t}"
                 : "=r"(done) : "r"(addr), "r"(parity) : "memory");
    if (!done) {
        asm volatile("{\n\t.reg .pred P1;\n\t"
                     "W_%=:\n\t"
                     "mbarrier.try_wait.parity.acquire.cta.shared::cta.b64 P1, [%0], %1, 0x989680;\n\t"
                     "@P1 bra.uni D_%=;\n\t"
                     "bra.uni W_%=;\n\t"
                     "D_%=:\n\t}"
                     :: "r"(addr), "r"(parity) : "memory");
    }
}
__device__ __forceinline__ void bulk_g2s(uint32_t dst, const void* src, uint32_t bytes, uint32_t mbar) {
    asm volatile("cp.async.bulk.shared::cluster.global.mbarrier::complete_tx::bytes [%0], [%1], %2, [%3];"
                 :: "r"(dst), "l"(src), "r"(bytes), "r"(mbar) : "memory");
}
__device__ __forceinline__ void ldsm_x4(uint32_t addr, uint32_t& r0, uint32_t& r1,
                                        uint32_t& r2, uint32_t& r3) {
    asm volatile("ldmatrix.sync.aligned.m8n8.x4.shared.b16 {%0,%1,%2,%3}, [%4];"
                 : "=r"(r0), "=r"(r1), "=r"(r2), "=r"(r3) : "r"(addr));
}
__device__ __forceinline__ void mma_bf16(float* d, const uint32_t* a, const uint32_t* b) {
    asm volatile("mma.sync.aligned.m16n8k16.row.col.f32.bf16.bf16.f32 "
                 "{%0,%1,%2,%3}, {%4,%5,%6,%7}, {%8,%9}, {%0,%1,%2,%3};"
                 : "+f"(d[0]), "+f"(d[1]), "+f"(d[2]), "+f"(d[3])
                 : "r"(a[0]), "r"(a[1]), "r"(a[2]), "r"(a[3]), "r"(b[0]), "r"(b[1]));
}
// 64B-row swizzle: XOR 16B-unit index (bits 4-5) with row bits 1-2 (bits 7-8)
__device__ __forceinline__ uint32_t sw64(uint32_t off) { return off ^ ((off >> 3) & 0x30); }

// ---------------------------------------------------------------------------
// Pack + split: in[R][4096] fp32 -> hi/lo bf16 packed [R/BR][128][BR][32],
// swizzled so smem image is ldmatrix-conflict-free after a raw bulk copy.
// One warp handles an 8-row x 32-col patch (one 512B swizzle unit).
// ---------------------------------------------------------------------------
template <int BR>
__global__ __launch_bounds__(256) void pack_split(const float* __restrict__ in,
                                                  __nv_bfloat16* __restrict__ hi,
                                                  __nv_bfloat16* __restrict__ lo,
                                                  int R) {
    const int K = DIM;
    const int w = (blockIdx.x * 256 + threadIdx.x) >> 5;
    const int lane = threadIdx.x & 31;
    const int nW = (R >> 3) * KC;
    if (w >= nW) return;
    const int rg = w / KC, kc = w % KC;
    const int r = rg * 8 + (lane >> 2);
    const int kq = lane & 3;
    const float4 v0 = *(const float4*)&in[(size_t)r * K + kc * 32 + kq * 8];
    const float4 v1 = *(const float4*)&in[(size_t)r * K + kc * 32 + kq * 8 + 4];

    float f[8] = {v0.x, v0.y, v0.z, v0.w, v1.x, v1.y, v1.z, v1.w};
    uint32_t hp[4], lp[4];
#pragma unroll
    for (int i = 0; i < 4; i++) {
        __nv_bfloat16 h0 = __float2bfloat16(f[2 * i]);
        __nv_bfloat16 h1 = __float2bfloat16(f[2 * i + 1]);
        __nv_bfloat16 l0 = __float2bfloat16(f[2 * i] - __bfloat162float(h0));
        __nv_bfloat16 l1 = __float2bfloat16(f[2 * i + 1] - __bfloat162float(h1));
        hp[i] = (uint32_t)*(unsigned short*)&h0 | ((uint32_t)*(unsigned short*)&h1 << 16);
        lp[i] = (uint32_t)*(unsigned short*)&l0 | ((uint32_t)*(unsigned short*)&l1 << 16);
    }
    const int rt = r / BR, row = r % BR;
    const size_t blk_bytes = ((size_t)rt * KC + kc) * (size_t)(BR * 64);
    const uint32_t sw = sw64((uint32_t)(row * 64 + kq * 16));
    *(uint4*)((char*)hi + blk_bytes + sw) = make_uint4(hp[0], hp[1], hp[2], hp[3]);
    *(uint4*)((char*)lo + blk_bytes + sw) = make_uint4(lp[0], lp[1], lp[2], lp[3]);
}

// ---------------------------------------------------------------------------
// Split-bf16 tensor-core GEMM, bulk-async fed.
// C[M,N] = A[M,K]*B[N,K]^T via Ah*Bh + Ah*Bl + Al*Bh (fp32 accum).
// CTA tile 128x256, BK=32, 3-stage mbarrier pipeline, 8 warps (2x4), 64x64/warp.
// A packed [M/128][128][128][32], B packed [N/256][128][256][32], pre-swizzled.
// ---------------------------------------------------------------------------
#define BM 128
#define BN 256
#define ABLK 8192              // 128*32*2
#define BBLK 16384             // 256*32*2
#define STG (2 * ABLK + 2 * BBLK)   // 49152
#define NST 3
#define GEMM_SMEM (NST * STG)       // 147456

__global__ __launch_bounds__(256) void gemm_tc(
    const __nv_bfloat16* __restrict__ Ah, const __nv_bfloat16* __restrict__ Al,
    const __nv_bfloat16* __restrict__ Bh, const __nv_bfloat16* __restrict__ Bl,
    float* __restrict__ C, int N)
{
    extern __shared__ char smg[];
    __shared__ uint64_t s_mbar[NST];

    const uint32_t sbase = smem_u32(smg);
    const int tid = threadIdx.x;
    const int wid = tid >> 5;
    const int lane = tid & 31;
    const int wm = wid & 1;            // 2 m-slabs of 64
    const int wn = wid >> 1;           // 4 n-slabs of 64
    const int bmb = blockIdx.y;        // M-block index
    const int bnb = blockIdx.x;        // N-block index

    uint32_t mb[NST];
#pragma unroll
    for (int i = 0; i < NST; i++) mb[i] = smem_u32(&s_mbar[i]);

    if (tid == 0)
        for (int i = 0; i < NST; i++) mbar_init(mb[i], 1);
    __syncthreads();

    const char* aHg = (const char*)Ah + (size_t)bmb * KC * ABLK;
    const char* aLg = (const char*)Al + (size_t)bmb * KC * ABLK;
    const char* bHg = (const char*)Bh + (size_t)bnb * KC * BBLK;
    const char* bLg = (const char*)Bl + (size_t)bnb * KC * BBLK;

    auto issue = [&](int c, int s) {
        const uint32_t d = sbase + s * STG;
        mbar_expect_tx(mb[s], STG);
        bulk_g2s(d,                    aHg + (size_t)c * ABLK, ABLK, mb[s]);
        bulk_g2s(d + ABLK,             aLg + (size_t)c * ABLK, ABLK, mb[s]);
        bulk_g2s(d + 2 * ABLK,         bHg + (size_t)c * BBLK, BBLK, mb[s]);
        bulk_g2s(d + 2 * ABLK + BBLK,  bLg + (size_t)c * BBLK, BBLK, mb[s]);
    };

    if (tid == 0) { issue(0, 0); issue(1, 1); issue(2, 2); }

    float acc[4][8][4];
#pragma unroll
    for (int mt = 0; mt < 4; mt++)
#pragma unroll
        for (int nt = 0; nt < 8; nt++)
#pragma unroll
            for (int j = 0; j < 4; j++) acc[mt][nt][j] = 0.f;

    const int g = lane >> 3, r = lane & 7;

    for (int c = 0; c < KC; c++) {
        const int s = c % NST;
        mbar_wait(mb[s], (c / NST) & 1);

        const uint32_t aH = sbase + s * STG;
        const uint32_t aL = aH + ABLK;
        const uint32_t bH = aH + 2 * ABLK;
        const uint32_t bL = bH + BBLK;

#pragma unroll
        for (int ks = 0; ks < 2; ks++) {
            uint32_t bh[8][2], bl[8][2];
#pragma unroll
            for (int p = 0; p < 4; p++) {
                const int nt = 2 * p + (g >> 1);
                const uint32_t a = sw64((uint32_t)((wn * 64 + nt * 8 + r) * 64 + ks * 32 + (g & 1) * 16));
                ldsm_x4(bH + a, bh[2 * p][0], bh[2 * p][1], bh[2 * p + 1][0], bh[2 * p + 1][1]);
                ldsm_x4(bL + a, bl[2 * p][0], bl[2 * p][1], bl[2 * p + 1][0], bl[2 * p + 1][1]);
            }
#pragma unroll
            for (int mt = 0; mt < 4; mt++) {
                const uint32_t a = sw64((uint32_t)((wm * 64 + mt * 16 + (g & 1) * 8 + r) * 64 + ks * 32 + (g >> 1) * 16));
                uint32_t ah[4], al[4];
                ldsm_x4(aH + a, ah[0], ah[1], ah[2], ah[3]);
                ldsm_x4(aL + a, al[0], al[1], al[2], al[3]);
#pragma unroll
                for (int nt = 0; nt < 8; nt++) {
                    mma_bf16(acc[mt][nt], ah, bh[nt]);
                    mma_bf16(acc[mt][nt], ah, bl[nt]);
                    mma_bf16(acc[mt][nt], al, bh[nt]);
                }
            }
        }
        __syncthreads();
        if (tid == 0 && c + NST < KC) issue(c + NST, s);
    }

    // epilogue
    const int er = lane >> 2, ec = (lane & 3) * 2;
#pragma unroll
    for (int mt = 0; mt < 4; mt++) {
#pragma unroll
        for (int nt = 0; nt < 8; nt++) {
            const int row = bmb * BM + wm * 64 + mt * 16 + er;
            const int col = bnb * BN + wn * 64 + nt * 8 + ec;
            *(float2*)&C[(size_t)row * N + col]       = make_float2(acc[mt][nt][0], acc[mt][nt][1]);
            *(float2*)&C[(size_t)(row + 8) * N + col] = make_float2(acc[mt][nt][2], acc[mt][nt][3]);
        }
    }
}

// ---------------------------------------------------------------------------
// Fused per-head RMSNorm + RoPE (in place). grid (SEQ, n_heads), 128 threads.
// ---------------------------------------------------------------------------
__global__ __launch_bounds__(128) void rmsnorm_rope(float* __restrict__ data,
                                                    const float* __restrict__ w,
                                                    const float* __restrict__ rope,
                                                    const int* __restrict__ pos,
                                                    int stride) {
    const int tok = blockIdx.x;
    const int h = blockIdx.y;
    const int t = threadIdx.x;

    float* p = data + (size_t)tok * stride + h * HD;
    float v = p[t];

    float ss = v * v;
#pragma unroll
    for (int off = 16; off; off >>= 1) ss += __shfl_xor_sync(0xffffffffu, ss, off);
    __shared__ float red[4];
    if ((t & 31) == 0) red[t >> 5] = ss;
    __syncthreads();
    float tot = red[0] + red[1] + red[2] + red[3];
    float inv = rsqrtf(tot * (1.0f / HD) + 1e-6f);
    float nv = v * inv * w[t];

    __shared__ float sh[HD];
    sh[t] = nv;
    __syncthreads();

    int pp = pos[tok];
    float out;
    if (t < 64) {
        float c = rope[(pp * 64 + t) * 2 + 0];
        float s = rope[(pp * 64 + t) * 2 + 1];
        out = nv * c - sh[t + 64] * s;
    } else {
        int f = t - 64;
        float c = rope[(pp * 64 + f) * 2 + 0];
        float s = rope[(pp * 64 + f) * 2 + 1];
        out = nv * c + sh[f] * s;
    }
    p[t] = out;
}

// ---------------------------------------------------------------------------
// Flash attention, segmented causal. BQ=BK=64, 256 threads.
// K rows at KV + tok*KVSTRIDE, V rows at KV + tok*KVSTRIDE + 1024.
// ---------------------------------------------------------------------------
#define KT_PITCH 65
#define SMEM_ATTN ((64 * 128 + 128 * KT_PITCH + 64 * 128 + 64 * 64) * 4)

__global__ __launch_bounds__(256) void attn_kernel(const float* __restrict__ Q,
                                                   const float* __restrict__ KV,
                                                   float* __restrict__ O) {
    const int qb = blockIdx.x;
    const int seg = blockIdx.y;
    const int qh = blockIdx.z;
    const int kvh = qh >> 2;

    extern __shared__ float sm[];
    float* Qs = sm;
    float* Kt = Qs + 64 * 128;
    float* Vs = Kt + 128 * KT_PITCH;
    float* Ps = Vs + 64 * 128;

    const int tid = threadIdx.x;
    const int tx = tid & 15;
    const int ty = tid >> 4;

    const float scale = 0.08838834764831845f;
    const int qtok0 = seg * SEG_LEN + qb * 64;

    for (int i = tid; i < 64 * 32; i += 256) {
        int r = i >> 5, c4 = i & 31;
        float4 v = *(const float4*)&Q[(size_t)(qtok0 + r) * QDIM + qh * HD + c4 * 4];
        v.x *= scale; v.y *= scale; v.z *= scale; v.w *= scale;
        *(float4*)&Qs[r * 128 + c4 * 4] = v;
    }

    float m[4], l[4], o[4][8];
#pragma unroll
    for (int rr = 0; rr < 4; rr++) {
        m[rr] = -CUDART_INF_F;
        l[rr] = 0.f;
#pragma unroll
        for (int j = 0; j < 8; j++) o[rr][j] = 0.f;
    }

    const int nkb = qb + 1;
    for (int kb = 0; kb < nkb; kb++) {
        __syncthreads();
        const int ktok0 = seg * SEG_LEN + kb * 64;
        for (int i = tid; i < 64 * 32; i += 256) {
            int r = i >> 5, c4 = i & 31;
            const float* kvrow = KV + (size_t)(ktok0 + r) * KVSTRIDE + kvh * HD;
            float4 kv = *(const float4*)(kvrow + c4 * 4);
            Kt[(c4 * 4 + 0) * KT_PITCH + r] = kv.x;
            Kt[(c4 * 4 + 1) * KT_PITCH + r] = kv.y;
            Kt[(c4 * 4 + 2) * KT_PITCH + r] = kv.z;
            Kt[(c4 * 4 + 3) * KT_PITCH + r] = kv.w;
            float4 vv = *(const float4*)(kvrow + 1024 + c4 * 4);
            *(float4*)&Vs[r * 128 + c4 * 4] = vv;
        }
        __syncthreads();

        float s[4][4];
#pragma unroll
        for (int rr = 0; rr < 4; rr++)
#pragma unroll
            for (int cc = 0; cc < 4; cc++) s[rr][cc] = 0.f;

        for (int d = 0; d < HD; d++) {
            float a[4], b[4];
#pragma unroll
            for (int rr = 0; rr < 4; rr++) a[rr] = Qs[(ty * 4 + rr) * 128 + d];
#pragma unroll
            for (int cc = 0; cc < 4; cc++) b[cc] = Kt[d * KT_PITCH + tx + cc * 16];
#pragma unroll
            for (int rr = 0; rr < 4; rr++)
#pragma unroll
                for (int cc = 0; cc < 4; cc++)
                    s[rr][cc] = fmaf(a[rr], b[cc], s[rr][cc]);
        }

        if (kb == qb) {
#pragma unroll
            for (int rr = 0; rr < 4; rr++)
#pragma unroll
                for (int cc = 0; cc < 4; cc++) {
                    int rq = ty * 4 + rr, cq = tx + cc * 16;
                    if (cq > rq) s[rr][cc] = -CUDART_INF_F;
                }
        }

#pragma unroll
        for (int rr = 0; rr < 4; rr++) {
            float mx = s[rr][0];
#pragma unroll
            for (int cc = 1; cc < 4; cc++) mx = fmaxf(mx, s[rr][cc]);
#pragma unroll
            for (int off = 8; off; off >>= 1)
                mx = fmaxf(mx, __shfl_xor_sync(0xffffffffu, mx, off));
            float mnew = fmaxf(m[rr], mx);
            float alpha = (m[rr] == -CUDART_INF_F) ? 0.f : __expf(m[rr] - mnew);
            float psum = 0.f;
#pragma unroll
            for (int cc = 0; cc < 4; cc++) {
                float pv = (s[rr][cc] == -CUDART_INF_F) ? 0.f : __expf(s[rr][cc] - mnew);
                s[rr][cc] = pv;
                psum += pv;
            }
#pragma unroll
            for (int off = 8; off; off >>= 1)
                psum += __shfl_xor_sync(0xffffffffu, psum, off);
            l[rr] = l[rr] * alpha + psum;
            m[rr] = mnew;
#pragma unroll
            for (int j = 0; j < 8; j++) o[rr][j] *= alpha;
        }

#pragma unroll
        for (int rr = 0; rr < 4; rr++)
#pragma unroll
            for (int cc = 0; cc < 4; cc++)
                Ps[(ty * 4 + rr) * 64 + tx + cc * 16] = s[rr][cc];
        __syncthreads();

        for (int c = 0; c < 64; c++) {
            float b[8];
#pragma unroll
            for (int j = 0; j < 8; j++) b[j] = Vs[c * 128 + tx + j * 16];
#pragma unroll
            for (int rr = 0; rr < 4; rr++) {
                float pv = Ps[(ty * 4 + rr) * 64 + c];
#pragma unroll
                for (int j = 0; j < 8; j++) o[rr][j] = fmaf(pv, b[j], o[rr][j]);
            }
        }
    }

#pragma unroll
    for (int rr = 0; rr < 4; rr++) {
        float linv = 1.0f / l[rr];
        int row = qtok0 + ty * 4 + rr;
#pragma unroll
        for (int j = 0; j < 8; j++)
            O[(size_t)row * QDIM + qh * HD + tx + j * 16] = o[rr][j] * linv;
    }
}

// ---------------------------------------------------------------------------
// Launch
// ---------------------------------------------------------------------------
extern "C" void kernel_launch(void* const* d_in, const int* in_sizes, int n_in,
                              void* d_out, int out_size) {
    const float* x    = (const float*)d_in[0];
    const float* wq   = (const float*)d_in[1];
    const float* wk   = (const float*)d_in[2];
    const float* wv   = (const float*)d_in[3];
    const float* wo   = (const float*)d_in[4];
    const float* qnw  = (const float*)d_in[5];
    const float* knw  = (const float*)d_in[6];
    const float* rope = (const float*)d_in[7];
    const int*   pos  = (const int*)d_in[8];

    float *q, *kv, *o;
    cudaGetSymbolAddress((void**)&q, g_q);
    cudaGetSymbolAddress((void**)&kv, g_kv);
    cudaGetSymbolAddress((void**)&o, g_o);

    __nv_bfloat16 *xh, *xl, *oh, *ol, *wqh, *wql, *wkvh, *wkvl, *woh, *wol;
    cudaGetSymbolAddress((void**)&xh, g_xh);     cudaGetSymbolAddress((void**)&xl, g_xl);
    cudaGetSymbolAddress((void**)&oh, g_oh);     cudaGetSymbolAddress((void**)&ol, g_ol);
    cudaGetSymbolAddress((void**)&wqh, g_wqh);   cudaGetSymbolAddress((void**)&wql, g_wql);
    cudaGetSymbolAddress((void**)&wkvh, g_wkvh); cudaGetSymbolAddress((void**)&wkvl, g_wkvl);
    cudaGetSymbolAddress((void**)&woh, g_woh);   cudaGetSymbolAddress((void**)&wol, g_wol);

    cudaFuncSetAttribute(gemm_tc, cudaFuncAttributeMaxDynamicSharedMemorySize, GEMM_SMEM);
    cudaFuncSetAttribute(attn_kernel, cudaFuncAttributeMaxDynamicSharedMemorySize, SMEM_ATTN);

    // wv-block byte offset within the fused KV B-buffer (blocks 4..7)
    const size_t wv_off = (size_t)4 * KC * 256 * 32;   // elements

    // Pack + split (A-layout for activations, B-layout for weights)
    {
        int nthr;
        nthr = (SEQ / 8) * KC * 32;
        pack_split<128><<<(nthr + 255) / 256, 256>>>(x, xh, xl, SEQ);
        nthr = (QDIM / 8) * KC * 32;
        pack_split<256><<<(nthr + 255) / 256, 256>>>(wq, wqh, wql, QDIM);
        nthr = (KVDIM / 8) * KC * 32;
        pack_split<256><<<(nthr + 255) / 256, 256>>>(wk, wkvh, wkvl, KVDIM);
        pack_split<256><<<(nthr + 255) / 256, 256>>>(wv, wkvh + wv_off, wkvl + wv_off, KVDIM);
        nthr = (DIM / 8) * KC * 32;
        pack_split<256><<<(nthr + 255) / 256, 256>>>(wo, woh, wol, DIM);
    }

    // Projections (tensor cores, bulk-async pipeline)
    gemm_tc<<<dim3(QDIM / BN, SEQ / BM), 256, GEMM_SMEM>>>(xh, xl, wqh, wql, q, QDIM);
    gemm_tc<<<dim3(KVSTRIDE / BN, SEQ / BM), 256, GEMM_SMEM>>>(xh, xl, wkvh, wkvl, kv, KVSTRIDE);

    // RMSNorm + RoPE
    rmsnorm_rope<<<dim3(SEQ, NQH), 128>>>(q, qnw, rope, pos, QDIM);
    rmsnorm_rope<<<dim3(SEQ, NKVH), 128>>>(kv, knw, rope, pos, KVSTRIDE);

    // Attention (fp32 flash)
    attn_kernel<<<dim3(SEG_LEN / 64, N_SEG, NQH), 256, SMEM_ATTN>>>(q, kv, o);

    // Output projection
    {
        int nthr = (SEQ / 8) * KC * 32;
        pack_split<128><<<(nthr + 255) / 256, 256>>>(o, oh, ol, SEQ);
    }
    gemm_tc<<<dim3(DIM / BN, SEQ / BM), 256, GEMM_SMEM>>>(oh, ol, woh, wol, (float*)d_out, DIM);
}

// round 6
// speedup vs baseline: 3.5674x; 1.1788x over previous
#include <cuda_runtime.h>
#include <cuda_bf16.h>
#include <math_constants.h>
#include <cstdint>

// ---------------------------------------------------------------------------
// Problem constants
// ---------------------------------------------------------------------------
#define SEQ      2048
#define DIM      4096
#define NQH      32
#define NKVH     8
#define HD       128
#define SEG_LEN  512
#define N_SEG    4
#define QDIM     (NQH * HD)    // 4096
#define KVD      (NKVH * HD)   // 1024
#define QKVD     6144          // fused q|k|v output width
#define KC       (DIM / 32)    // 128 k-chunks (all GEMMs have K=4096)

// fp32 scratch (fused qkv projection output)
__device__ float g_qkv[SEQ * QKVD];

// packed + swizzled bf16 split GEMM operands
__device__ __nv_bfloat16 g_xh[SEQ * DIM],     g_xl[SEQ * DIM];      // A-layout (128-row blocks)
__device__ __nv_bfloat16 g_oh[SEQ * QDIM],    g_ol[SEQ * QDIM];     // A-layout (written by attention)
__device__ __nv_bfloat16 g_wh[QKVD * DIM],    g_wl[QKVD * DIM];     // B-layout wq|wk|wv
__device__ __nv_bfloat16 g_woh[DIM * QDIM],   g_wol[DIM * QDIM];    // B-layout

// attention operands (bf16 split, linear layouts)
__device__ __nv_bfloat16 g_qsh[NQH * SEQ * HD],  g_qsl[NQH * SEQ * HD];   // [qh][tok][d]
__device__ __nv_bfloat16 g_ksh[NKVH * SEQ * HD], g_ksl[NKVH * SEQ * HD];  // [kvh][tok][d]
__device__ __nv_bfloat16 g_vth[NKVH * HD * SEQ], g_vtl[NKVH * HD * SEQ];  // [kvh*128+d][tok]

// ---------------------------------------------------------------------------
// PTX helpers (base-target instructions only)
// ---------------------------------------------------------------------------
__device__ __forceinline__ uint32_t smem_u32(const void* p) {
    uint32_t a;
    asm("{ .reg .u64 t; cvta.to.shared.u64 t, %1; cvt.u32.u64 %0, t; }" : "=r"(a) : "l"(p));
    return a;
}
__device__ __forceinline__ void mbar_init(uint32_t addr, uint32_t cnt) {
    asm volatile("mbarrier.init.shared.b64 [%0], %1;" :: "r"(addr), "r"(cnt) : "memory");
}
__device__ __forceinline__ void mbar_expect_tx(uint32_t addr, uint32_t bytes) {
    asm volatile("mbarrier.arrive.expect_tx.shared.b64 _, [%0], %1;" :: "r"(addr), "r"(bytes) : "memory");
}
__device__ __forceinline__ void mbar_wait(uint32_t addr, uint32_t parity) {
    uint32_t done;
    asm volatile("{\n\t.reg .pred p;\n\t"
                 "mbarrier.try_wait.parity.acquire.cta.shared::cta.b64 p, [%1], %2;\n\t"
                 "selp.b32 %0, 1, 0, p;\n\t}"
                 : "=r"(done) : "r"(addr), "r"(parity) : "memory");
    if (!done) {
        asm volatile("{\n\t.reg .pred P1;\n\t"
                     "W_%=:\n\t"
                     "mbarrier.try_wait.parity.acquire.cta.shared::cta.b64 P1, [%0], %1, 0x989680;\n\t"
                     "@P1 bra.uni D_%=;\n\t"
                     "bra.uni W_%=;\n\t"
                     "D_%=:\n\t}"
                     :: "r"(addr), "r"(parity) : "memory");
    }
}
__device__ __forceinline__ void bulk_g2s(uint32_t dst, const void* src, uint32_t bytes, uint32_t mbar) {
    asm volatile("cp.async.bulk.shared::cluster.global.mbarrier::complete_tx::bytes [%0], [%1], %2, [%3];"
                 :: "r"(dst), "l"(src), "r"(bytes), "r"(mbar) : "memory");
}
__device__ __forceinline__ void cp_async16(uint32_t dst, const void* src) {
    asm volatile("cp.async.cg.shared.global [%0], [%1], 16;" :: "r"(dst), "l"(src) : "memory");
}
__device__ __forceinline__ void cp_commit() { asm volatile("cp.async.commit_group;" ::: "memory"); }
__device__ __forceinline__ void cp_wait1()  { asm volatile("cp.async.wait_group 1;" ::: "memory"); }
__device__ __forceinline__ void cp_wait0()  { asm volatile("cp.async.wait_group 0;" ::: "memory"); }
__device__ __forceinline__ void ldsm_x4(uint32_t addr, uint32_t& r0, uint32_t& r1,
                                        uint32_t& r2, uint32_t& r3) {
    asm volatile("ldmatrix.sync.aligned.m8n8.x4.shared.b16 {%0,%1,%2,%3}, [%4];"
                 : "=r"(r0), "=r"(r1), "=r"(r2), "=r"(r3) : "r"(addr));
}
__device__ __forceinline__ void mma_bf16(float* d, const uint32_t* a, const uint32_t* b) {
    asm volatile("mma.sync.aligned.m16n8k16.row.col.f32.bf16.bf16.f32 "
                 "{%0,%1,%2,%3}, {%4,%5,%6,%7}, {%8,%9}, {%0,%1,%2,%3};"
                 : "+f"(d[0]), "+f"(d[1]), "+f"(d[2]), "+f"(d[3])
                 : "r"(a[0]), "r"(a[1]), "r"(a[2]), "r"(a[3]), "r"(b[0]), "r"(b[1]));
}
// swizzles: XOR 16B-unit index with (row & 7) for various row pitches
__device__ __forceinline__ uint32_t sw64(uint32_t off)  { return off ^ ((off >> 3) & 0x30); }  // 64B rows
__device__ __forceinline__ uint32_t sw128(uint32_t off) { return off ^ ((off >> 3) & 0x70); }  // 128B rows
__device__ __forceinline__ uint32_t sw256(uint32_t off) { return off ^ ((off >> 4) & 0x70); }  // 256B rows

__device__ __forceinline__ void split2(float x, float y, uint32_t& hi, uint32_t& lo) {
    __nv_bfloat16 hx = __float2bfloat16(x), hy = __float2bfloat16(y);
    __nv_bfloat16 lx = __float2bfloat16(x - __bfloat162float(hx));
    __nv_bfloat16 ly = __float2bfloat16(y - __bfloat162float(hy));
    hi = (uint32_t)*(unsigned short*)&hx | ((uint32_t)*(unsigned short*)&hy << 16);
    lo = (uint32_t)*(unsigned short*)&lx | ((uint32_t)*(unsigned short*)&ly << 16);
}

// ---------------------------------------------------------------------------
// Pack + split: in[R][4096] fp32 -> hi/lo bf16 packed [R/BR][128][BR][32],
// pre-swizzled so raw bulk copies land ldmatrix-conflict-free in smem.
// ---------------------------------------------------------------------------
template <int BR>
__global__ __launch_bounds__(256) void pack_split(const float* __restrict__ in,
                                                  __nv_bfloat16* __restrict__ hi,
                                                  __nv_bfloat16* __restrict__ lo,
                                                  int R) {
    const int K = DIM;
    const int w = (blockIdx.x * 256 + threadIdx.x) >> 5;
    const int lane = threadIdx.x & 31;
    const int nW = (R >> 3) * KC;
    if (w >= nW) return;
    const int rg = w / KC, kc = w % KC;
    const int r = rg * 8 + (lane >> 2);
    const int kq = lane & 3;
    const float4 v0 = *(const float4*)&in[(size_t)r * K + kc * 32 + kq * 8];
    const float4 v1 = *(const float4*)&in[(size_t)r * K + kc * 32 + kq * 8 + 4];

    float f[8] = {v0.x, v0.y, v0.z, v0.w, v1.x, v1.y, v1.z, v1.w};
    uint32_t hp[4], lp[4];
#pragma unroll
    for (int i = 0; i < 4; i++) split2(f[2 * i], f[2 * i + 1], hp[i], lp[i]);
    const int rt = r / BR, row = r % BR;
    const size_t blk_bytes = ((size_t)rt * KC + kc) * (size_t)(BR * 64);
    const uint32_t sw = sw64((uint32_t)(row * 64 + kq * 16));
    *(uint4*)((char*)hi + blk_bytes + sw) = make_uint4(hp[0], hp[1], hp[2], hp[3]);
    *(uint4*)((char*)lo + blk_bytes + sw) = make_uint4(lp[0], lp[1], lp[2], lp[3]);
}

// ---------------------------------------------------------------------------
// Split-bf16 tensor-core GEMM, bulk-async fed, 4-stage pipeline.
// ---------------------------------------------------------------------------
#define BM 128
#define BN 256
#define ABLK 8192
#define BBLK 16384
#define STG (2 * ABLK + 2 * BBLK)   // 49152
#define NST 4
#define GEMM_SMEM (NST * STG)       // 196608

__global__ __launch_bounds__(256) void gemm_tc(
    const __nv_bfloat16* __restrict__ Ah, const __nv_bfloat16* __restrict__ Al,
    const __nv_bfloat16* __restrict__ Bh, const __nv_bfloat16* __restrict__ Bl,
    float* __restrict__ C, int N)
{
    extern __shared__ char smg[];
    __shared__ uint64_t s_mbar[NST];

    const uint32_t sbase = smem_u32(smg);
    const int tid = threadIdx.x;
    const int wid = tid >> 5;
    const int lane = tid & 31;
    const int wm = wid & 1;
    const int wn = wid >> 1;
    const int bmb = blockIdx.y;
    const int bnb = blockIdx.x;

    uint32_t mb[NST];
#pragma unroll
    for (int i = 0; i < NST; i++) mb[i] = smem_u32(&s_mbar[i]);

    if (tid == 0)
        for (int i = 0; i < NST; i++) mbar_init(mb[i], 1);
    __syncthreads();

    const char* aHg = (const char*)Ah + (size_t)bmb * KC * ABLK;
    const char* aLg = (const char*)Al + (size_t)bmb * KC * ABLK;
    const char* bHg = (const char*)Bh + (size_t)bnb * KC * BBLK;
    const char* bLg = (const char*)Bl + (size_t)bnb * KC * BBLK;

    auto issue = [&](int c, int s) {
        const uint32_t d = sbase + s * STG;
        mbar_expect_tx(mb[s], STG);
        bulk_g2s(d,                    aHg + (size_t)c * ABLK, ABLK, mb[s]);
        bulk_g2s(d + ABLK,             aLg + (size_t)c * ABLK, ABLK, mb[s]);
        bulk_g2s(d + 2 * ABLK,         bHg + (size_t)c * BBLK, BBLK, mb[s]);
        bulk_g2s(d + 2 * ABLK + BBLK,  bLg + (size_t)c * BBLK, BBLK, mb[s]);
    };

    if (tid == 0) { issue(0, 0); issue(1, 1); issue(2, 2); issue(3, 3); }

    float acc[4][8][4];
#pragma unroll
    for (int mt = 0; mt < 4; mt++)
#pragma unroll
        for (int nt = 0; nt < 8; nt++)
#pragma unroll
            for (int j = 0; j < 4; j++) acc[mt][nt][j] = 0.f;

    const int g = lane >> 3, r = lane & 7;

    for (int c = 0; c < KC; c++) {
        const int s = c % NST;
        mbar_wait(mb[s], (c / NST) & 1);

        const uint32_t aH = sbase + s * STG;
        const uint32_t aL = aH + ABLK;
        const uint32_t bH = aH + 2 * ABLK;
        const uint32_t bL = bH + BBLK;

#pragma unroll
        for (int ks = 0; ks < 2; ks++) {
            uint32_t bh[8][2], bl[8][2];
#pragma unroll
            for (int p = 0; p < 4; p++) {
                const int nt = 2 * p + (g >> 1);
                const uint32_t a = sw64((uint32_t)((wn * 64 + nt * 8 + r) * 64 + ks * 32 + (g & 1) * 16));
                ldsm_x4(bH + a, bh[2 * p][0], bh[2 * p][1], bh[2 * p + 1][0], bh[2 * p + 1][1]);
                ldsm_x4(bL + a, bl[2 * p][0], bl[2 * p][1], bl[2 * p + 1][0], bl[2 * p + 1][1]);
            }
#pragma unroll
            for (int mt = 0; mt < 4; mt++) {
                const uint32_t a = sw64((uint32_t)((wm * 64 + mt * 16 + (g & 1) * 8 + r) * 64 + ks * 32 + (g >> 1) * 16));
                uint32_t ah[4], al[4];
                ldsm_x4(aH + a, ah[0], ah[1], ah[2], ah[3]);
                ldsm_x4(aL + a, al[0], al[1], al[2], al[3]);
#pragma unroll
                for (int nt = 0; nt < 8; nt++) {
                    mma_bf16(acc[mt][nt], ah, bh[nt]);
                    mma_bf16(acc[mt][nt], ah, bl[nt]);
                    mma_bf16(acc[mt][nt], al, bh[nt]);
                }
            }
        }
        __syncthreads();
        if (tid == 0 && c + NST < KC) issue(c + NST, s);
    }

    const int er = lane >> 2, ec = (lane & 3) * 2;
#pragma unroll
    for (int mt = 0; mt < 4; mt++) {
#pragma unroll
        for (int nt = 0; nt < 8; nt++) {
            const int row = bmb * BM + wm * 64 + mt * 16 + er;
            const int col = bnb * BN + wn * 64 + nt * 8 + ec;
            *(float2*)&C[(size_t)row * N + col]       = make_float2(acc[mt][nt][0], acc[mt][nt][1]);
            *(float2*)&C[(size_t)(row + 8) * N + col] = make_float2(acc[mt][nt][2], acc[mt][nt][3]);
        }
    }
}

// ---------------------------------------------------------------------------
// Fused RMSNorm + RoPE + scale + bf16 split. grid (SEQ, 40): h<32 -> Q head,
// h>=32 -> K head. Writes [head][tok][d] bf16 hi/lo.
// ---------------------------------------------------------------------------
__global__ __launch_bounds__(128) void rmsnorm_rope_split(
    const float* __restrict__ qkv,
    const float* __restrict__ qnw, const float* __restrict__ knw,
    const float* __restrict__ rope, const int* __restrict__ pos,
    __nv_bfloat16* __restrict__ qh, __nv_bfloat16* __restrict__ ql,
    __nv_bfloat16* __restrict__ kh, __nv_bfloat16* __restrict__ kl)
{
    const int tok = blockIdx.x;
    const int h = blockIdx.y;
    const int t = threadIdx.x;
    const bool isQ = h < NQH;
    const int col = isQ ? h * HD + t : QDIM + (h - NQH) * HD + t;

    float v = qkv[(size_t)tok * QKVD + col];

    float ss = v * v;
#pragma unroll
    for (int off = 16; off; off >>= 1) ss += __shfl_xor_sync(0xffffffffu, ss, off);
    __shared__ float red[4];
    if ((t & 31) == 0) red[t >> 5] = ss;
    __syncthreads();
    float tot = red[0] + red[1] + red[2] + red[3];
    float inv = rsqrtf(tot * (1.0f / HD) + 1e-6f);
    float nv = v * inv * (isQ ? qnw[t] : knw[t]);

    __shared__ float sh[HD];
    sh[t] = nv;
    __syncthreads();

    const int pp = pos[tok];
    float out;
    if (t < 64) {
        float c = rope[(pp * 64 + t) * 2 + 0];
        float s = rope[(pp * 64 + t) * 2 + 1];
        out = nv * c - sh[t + 64] * s;
    } else {
        int f = t - 64;
        float c = rope[(pp * 64 + f) * 2 + 0];
        float s = rope[(pp * 64 + f) * 2 + 1];
        out = nv * c + sh[f] * s;
    }
    if (isQ) out *= 0.08838834764831845f;   // 1/sqrt(128)

    __nv_bfloat16 hb = __float2bfloat16(out);
    __nv_bfloat16 lb = __float2bfloat16(out - __bfloat162float(hb));
    const size_t idx = isQ ? ((size_t)h * SEQ + tok) * HD + t
                           : ((size_t)(h - NQH) * SEQ + tok) * HD + t;
    if (isQ) { qh[idx] = hb; ql[idx] = lb; }
    else     { kh[idx] = hb; kl[idx] = lb; }
}

// ---------------------------------------------------------------------------
// V: transpose + split. qkv cols 5120..6143 -> vt[vrow=col-5120][tok] hi/lo.
// grid (SEQ/32, 1024/32), block (32, 8).
// ---------------------------------------------------------------------------
__global__ __launch_bounds__(256) void v_split_t(const float* __restrict__ qkv,
                                                 __nv_bfloat16* __restrict__ vh,
                                                 __nv_bfloat16* __restrict__ vl) {
    __shared__ float tile[32][33];
    const int tx = threadIdx.x, ty = threadIdx.y;
    const int tok0 = blockIdx.x * 32, c0 = blockIdx.y * 32;
#pragma unroll
    for (int j = ty; j < 32; j += 8)
        tile[j][tx] = qkv[(size_t)(tok0 + j) * QKVD + (QDIM + 1024) + c0 + tx];
    __syncthreads();
#pragma unroll
    for (int j = ty; j < 32; j += 8) {
        float v = tile[tx][j];
        __nv_bfloat16 hb = __float2bfloat16(v);
        __nv_bfloat16 lb = __float2bfloat16(v - __bfloat162float(hb));
        const size_t idx = (size_t)(c0 + j) * SEQ + tok0 + tx;
        vh[idx] = hb; vl[idx] = lb;
    }
}

// ---------------------------------------------------------------------------
// Tensor-core flash attention (segmented causal, GQA).
// BQ=BKV=64, 4 warps (each owns 16 q rows), 2-stage cp.async KV pipeline.
// S = Q K^T (3-term split) -> online softmax in accumulator layout ->
// P (hi/lo in registers via C->A fragment identity) @ V^T (3-term split).
// Epilogue writes O directly in packed split-bf16 GEMM-A layout.
// ---------------------------------------------------------------------------
#define ATT_SMEM (32768 + 2 * 65536)  // Q(hi/lo) + 2 stages of K/V(hi/lo)

__global__ __launch_bounds__(128) void attn_tc(
    const __nv_bfloat16* __restrict__ Qh, const __nv_bfloat16* __restrict__ Ql,
    const __nv_bfloat16* __restrict__ Kh, const __nv_bfloat16* __restrict__ Kl,
    const __nv_bfloat16* __restrict__ Vh, const __nv_bfloat16* __restrict__ Vl,
    __nv_bfloat16* __restrict__ Oh, __nv_bfloat16* __restrict__ Ol)
{
    extern __shared__ char sma[];
    const uint32_t sb = smem_u32(sma);
    const int tid = threadIdx.x, wid = tid >> 5, lane = tid & 31;
    const int qb = blockIdx.x, seg = blockIdx.y, qh = blockIdx.z;
    const int kvh = qh >> 2;
    const int qtok0 = seg * SEG_LEN + qb * 64;
    const int g = lane >> 3, r = lane & 7;

    const uint32_t QHs = sb, QLs = sb + 16384;

    // Q tile (group 0)
    {
        const char* srcH = (const char*)(Qh + ((size_t)qh * SEQ + qtok0) * HD);
        const char* srcL = (const char*)(Ql + ((size_t)qh * SEQ + qtok0) * HD);
        for (int i = tid; i < 1024; i += 128) {
            int row = i >> 4, u = i & 15;
            uint32_t off = sw256((uint32_t)(row * 256 + u * 16));
            cp_async16(QHs + off, srcH + row * 256 + u * 16);
            cp_async16(QLs + off, srcL + row * 256 + u * 16);
        }
        cp_commit();
    }

    auto issue_kv = [&](int kb, int s) {
        const int kt = seg * SEG_LEN + kb * 64;
        const uint32_t base = sb + 32768 + s * 65536;
        const char* kH = (const char*)(Kh + ((size_t)kvh * SEQ + kt) * HD);
        const char* kL = (const char*)(Kl + ((size_t)kvh * SEQ + kt) * HD);
        for (int i = tid; i < 1024; i += 128) {
            int row = i >> 4, u = i & 15;
            uint32_t off = sw256((uint32_t)(row * 256 + u * 16));
            cp_async16(base + off,         kH + row * 256 + u * 16);
            cp_async16(base + 16384 + off, kL + row * 256 + u * 16);
        }
        const char* vH = (const char*)Vh + ((size_t)kvh * HD * SEQ + kt) * 2;
        const char* vL = (const char*)Vl + ((size_t)kvh * HD * SEQ + kt) * 2;
        for (int i = tid; i < 1024; i += 128) {
            int row = i >> 3, u = i & 7;
            uint32_t off = sw128((uint32_t)(row * 128 + u * 16));
            cp_async16(base + 32768 + off, vH + (size_t)row * SEQ * 2 + u * 16);
            cp_async16(base + 49152 + off, vL + (size_t)row * SEQ * 2 + u * 16);
        }
        cp_commit();
    };

    issue_kv(0, 0);
    if (qb >= 1) issue_kv(1, 1); else cp_commit();

    float m0 = -CUDART_INF_F, m1 = -CUDART_INF_F, l0 = 0.f, l1 = 0.f;
    float o[16][4];
#pragma unroll
    for (int nt = 0; nt < 16; nt++)
#pragma unroll
        for (int j = 0; j < 4; j++) o[nt][j] = 0.f;

    for (int kb = 0; kb <= qb; kb++) {
        const int s = kb & 1;
        cp_wait1();
        __syncthreads();
        const uint32_t KHs = sb + 32768 + s * 65536;
        const uint32_t KLs = KHs + 16384;
        const uint32_t VHs = KHs + 32768;
        const uint32_t VLs = KHs + 49152;

        // ---- S = Q K^T (3-term) ----
        float sa[8][4];
#pragma unroll
        for (int nt = 0; nt < 8; nt++)
#pragma unroll
            for (int j = 0; j < 4; j++) sa[nt][j] = 0.f;

#pragma unroll
        for (int ks = 0; ks < 8; ks++) {
            const int arow = wid * 16 + (g & 1) * 8 + r;
            const uint32_t aoff = sw256((uint32_t)(arow * 256 + (ks * 2 + (g >> 1)) * 16));
            uint32_t ah[4], al[4];
            ldsm_x4(QHs + aoff, ah[0], ah[1], ah[2], ah[3]);
            ldsm_x4(QLs + aoff, al[0], al[1], al[2], al[3]);
            uint32_t bh[8][2], bl[8][2];
#pragma unroll
            for (int p = 0; p < 4; p++) {
                const int nrow = (2 * p + (g >> 1)) * 8 + r;
                const uint32_t boff = sw256((uint32_t)(nrow * 256 + (ks * 2 + (g & 1)) * 16));
                ldsm_x4(KHs + boff, bh[2 * p][0], bh[2 * p][1], bh[2 * p + 1][0], bh[2 * p + 1][1]);
                ldsm_x4(KLs + boff, bl[2 * p][0], bl[2 * p][1], bl[2 * p + 1][0], bl[2 * p + 1][1]);
            }
#pragma unroll
            for (int nt = 0; nt < 8; nt++) {
                mma_bf16(sa[nt], ah, bh[nt]);
                mma_bf16(sa[nt], ah, bl[nt]);
                mma_bf16(sa[nt], al, bh[nt]);
            }
        }

        // ---- causal mask on diagonal tile ----
        if (kb == qb) {
            const int r0 = wid * 16 + (lane >> 2);
#pragma unroll
            for (int nt = 0; nt < 8; nt++) {
                const int c = nt * 8 + (lane & 3) * 2;
                if (c     > r0)     sa[nt][0] = -CUDART_INF_F;
                if (c + 1 > r0)     sa[nt][1] = -CUDART_INF_F;
                if (c     > r0 + 8) sa[nt][2] = -CUDART_INF_F;
                if (c + 1 > r0 + 8) sa[nt][3] = -CUDART_INF_F;
            }
        }

        // ---- online softmax (rows r0 = lane>>2 and r0+8 per lane) ----
        {
            float mx0 = -CUDART_INF_F, mx1 = -CUDART_INF_F;
#pragma unroll
            for (int nt = 0; nt < 8; nt++) {
                mx0 = fmaxf(mx0, fmaxf(sa[nt][0], sa[nt][1]));
                mx1 = fmaxf(mx1, fmaxf(sa[nt][2], sa[nt][3]));
            }
            mx0 = fmaxf(mx0, __shfl_xor_sync(0xffffffffu, mx0, 1));
            mx0 = fmaxf(mx0, __shfl_xor_sync(0xffffffffu, mx0, 2));
            mx1 = fmaxf(mx1, __shfl_xor_sync(0xffffffffu, mx1, 1));
            mx1 = fmaxf(mx1, __shfl_xor_sync(0xffffffffu, mx1, 2));
            const float mn0 = fmaxf(m0, mx0), mn1 = fmaxf(m1, mx1);
            const float a0 = __expf(m0 - mn0), a1 = __expf(m1 - mn1);
            float sum0 = 0.f, sum1 = 0.f;
#pragma unroll
            for (int nt = 0; nt < 8; nt++) {
                sa[nt][0] = __expf(sa[nt][0] - mn0); sum0 += sa[nt][0];
                sa[nt][1] = __expf(sa[nt][1] - mn0); sum0 += sa[nt][1];
                sa[nt][2] = __expf(sa[nt][2] - mn1); sum1 += sa[nt][2];
                sa[nt][3] = __expf(sa[nt][3] - mn1); sum1 += sa[nt][3];
            }
            sum0 += __shfl_xor_sync(0xffffffffu, sum0, 1);
            sum0 += __shfl_xor_sync(0xffffffffu, sum0, 2);
            sum1 += __shfl_xor_sync(0xffffffffu, sum1, 1);
            sum1 += __shfl_xor_sync(0xffffffffu, sum1, 2);
            l0 = l0 * a0 + sum0;
            l1 = l1 * a1 + sum1;
            m0 = mn0; m1 = mn1;
#pragma unroll
            for (int nt = 0; nt < 16; nt++) {
                o[nt][0] *= a0; o[nt][1] *= a0;
                o[nt][2] *= a1; o[nt][3] *= a1;
            }
        }

        // ---- O += P V (3-term; P A-frags built from S accumulators) ----
#pragma unroll
        for (int kj = 0; kj < 4; kj++) {
            const int t0 = 2 * kj, t1 = t0 + 1;
            uint32_t ph[4], pl[4];
            split2(sa[t0][0], sa[t0][1], ph[0], pl[0]);
            split2(sa[t0][2], sa[t0][3], ph[1], pl[1]);
            split2(sa[t1][0], sa[t1][1], ph[2], pl[2]);
            split2(sa[t1][2], sa[t1][3], ph[3], pl[3]);
#pragma unroll
            for (int p = 0; p < 8; p++) {
                const int vrow = (2 * p + (g >> 1)) * 8 + r;
                const uint32_t voff = sw128((uint32_t)(vrow * 128 + (kj * 2 + (g & 1)) * 16));
                uint32_t vf0[2], vf1[2], wf0[2], wf1[2];
                ldsm_x4(VHs + voff, vf0[0], vf0[1], vf1[0], vf1[1]);
                ldsm_x4(VLs + voff, wf0[0], wf0[1], wf1[0], wf1[1]);
                mma_bf16(o[2 * p],     ph, vf0);
                mma_bf16(o[2 * p],     ph, wf0);
                mma_bf16(o[2 * p],     pl, vf0);
                mma_bf16(o[2 * p + 1], ph, vf1);
                mma_bf16(o[2 * p + 1], ph, wf1);
                mma_bf16(o[2 * p + 1], pl, vf1);
            }
        }

        __syncthreads();
        if (kb + 2 <= qb) issue_kv(kb + 2, s); else cp_commit();
    }
    cp_wait0();

    // ---- epilogue: write packed split-bf16 GEMM-A layout ----
    const float li0 = 1.f / l0, li1 = 1.f / l1;
    const int tk0 = qtok0 + wid * 16 + (lane >> 2);
    const int tk1 = tk0 + 8;
#pragma unroll
    for (int nt = 0; nt < 16; nt++) {
        const int d = qh * HD + nt * 8 + (lane & 3) * 2;
        const size_t blk = ((size_t)(tk0 >> 7) * KC + (d >> 5)) * (size_t)(128 * 64);
        const uint32_t col2 = (uint32_t)((d & 31) * 2);
        const uint32_t lo4 = col2 & 15u;
        const uint32_t in0 = sw64((uint32_t)((tk0 & 127) * 64) + (col2 & ~15u)) + lo4;
        const uint32_t in1 = sw64((uint32_t)((tk1 & 127) * 64) + (col2 & ~15u)) + lo4;
        uint32_t hi, lo;
        split2(o[nt][0] * li0, o[nt][1] * li0, hi, lo);
        *(uint32_t*)((char*)Oh + blk + in0) = hi;
        *(uint32_t*)((char*)Ol + blk + in0) = lo;
        split2(o[nt][2] * li1, o[nt][3] * li1, hi, lo);
        *(uint32_t*)((char*)Oh + blk + in1) = hi;
        *(uint32_t*)((char*)Ol + blk + in1) = lo;
    }
}

// ---------------------------------------------------------------------------
// Launch
// ---------------------------------------------------------------------------
extern "C" void kernel_launch(void* const* d_in, const int* in_sizes, int n_in,
                              void* d_out, int out_size) {
    const float* x    = (const float*)d_in[0];
    const float* wq   = (const float*)d_in[1];
    const float* wk   = (const float*)d_in[2];
    const float* wv   = (const float*)d_in[3];
    const float* wo   = (const float*)d_in[4];
    const float* qnw  = (const float*)d_in[5];
    const float* knw  = (const float*)d_in[6];
    const float* rope = (const float*)d_in[7];
    const int*   pos  = (const int*)d_in[8];

    float* qkv;
    cudaGetSymbolAddress((void**)&qkv, g_qkv);
    __nv_bfloat16 *xh, *xl, *oh, *ol, *wh, *wl, *woh, *wol;
    __nv_bfloat16 *qsh, *qsl, *ksh, *ksl, *vth, *vtl;
    cudaGetSymbolAddress((void**)&xh, g_xh);   cudaGetSymbolAddress((void**)&xl, g_xl);
    cudaGetSymbolAddress((void**)&oh, g_oh);   cudaGetSymbolAddress((void**)&ol, g_ol);
    cudaGetSymbolAddress((void**)&wh, g_wh);   cudaGetSymbolAddress((void**)&wl, g_wl);
    cudaGetSymbolAddress((void**)&woh, g_woh); cudaGetSymbolAddress((void**)&wol, g_wol);
    cudaGetSymbolAddress((void**)&qsh, g_qsh); cudaGetSymbolAddress((void**)&qsl, g_qsl);
    cudaGetSymbolAddress((void**)&ksh, g_ksh); cudaGetSymbolAddress((void**)&ksl, g_ksl);
    cudaGetSymbolAddress((void**)&vth, g_vth); cudaGetSymbolAddress((void**)&vtl, g_vtl);

    cudaFuncSetAttribute(gemm_tc, cudaFuncAttributeMaxDynamicSharedMemorySize, GEMM_SMEM);
    cudaFuncSetAttribute(attn_tc, cudaFuncAttributeMaxDynamicSharedMemorySize, ATT_SMEM);

    // Pack + split inputs
    {
        int nthr = (SEQ / 8) * KC * 32;
        pack_split<128><<<(nthr + 255) / 256, 256>>>(x, xh, xl, SEQ);
    }
    {
        int nthr = (QDIM / 8) * KC * 32;
        pack_split<256><<<(nthr + 255) / 256, 256>>>(wq, wh, wl, QDIM);
    }
    {
        int nthr = (KVD / 8) * KC * 32;
        pack_split<256><<<(nthr + 255) / 256, 256>>>(wk, wh + (size_t)QDIM * DIM, wl + (size_t)QDIM * DIM, KVD);
        pack_split<256><<<(nthr + 255) / 256, 256>>>(wv, wh + (size_t)(QDIM + KVD) * DIM, wl + (size_t)(QDIM + KVD) * DIM, KVD);
    }
    {
        int nthr = (DIM / 8) * KC * 32;
        pack_split<256><<<(nthr + 255) / 256, 256>>>(wo, woh, wol, DIM);
    }

    // Fused QKV projection
    gemm_tc<<<dim3(QKVD / BN, SEQ / BM), 256, GEMM_SMEM>>>(xh, xl, wh, wl, qkv, QKVD);

    // RMSNorm + RoPE + split (Q pre-scaled), and V transpose + split
    rmsnorm_rope_split<<<dim3(SEQ, NQH + NKVH), 128>>>(qkv, qnw, knw, rope, pos,
                                                       qsh, qsl, ksh, ksl);
    v_split_t<<<dim3(SEQ / 32, KVD / 32), dim3(32, 8)>>>(qkv, vth, vtl);

    // Tensor-core attention (writes packed O)
    attn_tc<<<dim3(SEG_LEN / 64, N_SEG, NQH), 128, ATT_SMEM>>>(qsh, qsl, ksh, ksl,
                                                               vth, vtl, oh, ol);

    // Output projection
    gemm_tc<<<dim3(DIM / BN, SEQ / BM), 256, GEMM_SMEM>>>(oh, ol, woh, wol, (float*)d_out, DIM);
}

// round 7
// speedup vs baseline: 7.8941x; 2.2129x over previous
#include <cuda_runtime.h>
#include <cuda_fp16.h>
#include <math_constants.h>
#include <cstdint>

// ---------------------------------------------------------------------------
// Problem constants
// ---------------------------------------------------------------------------
#define SEQ      2048
#define DIM      4096
#define NQH      32
#define NKVH     8
#define HD       128
#define SEG_LEN  512
#define N_SEG    4
#define QDIM     (NQH * HD)    // 4096
#define KVD      (NKVH * HD)   // 1024
#define QKVD     6144          // fused q|k|v output width
#define KC       (DIM / 32)    // 128 k-chunks (all GEMMs have K=4096)

// fp32 scratch (fused qkv projection output)
__device__ float g_qkv[SEQ * QKVD];

// packed + swizzled fp16 GEMM operands
__device__ __half g_xh[SEQ * DIM];       // A-layout (128-row blocks)
__device__ __half g_oh[SEQ * QDIM];      // A-layout (written by attention)
__device__ __half g_wh[QKVD * DIM];      // B-layout wq|wk|wv (256-row blocks)
__device__ __half g_woh[DIM * QDIM];     // B-layout

// attention operands (fp16, linear layouts)
__device__ __half g_qsh[NQH * SEQ * HD];    // [qh][tok][d]  (pre-scaled)
__device__ __half g_ksh[NKVH * SEQ * HD];   // [kvh][tok][d]
__device__ __half g_vth[NKVH * HD * SEQ];   // [kvh*128+d][tok]

// ---------------------------------------------------------------------------
// PTX helpers (base-target instructions only)
// ---------------------------------------------------------------------------
__device__ __forceinline__ uint32_t smem_u32(const void* p) {
    uint32_t a;
    asm("{ .reg .u64 t; cvta.to.shared.u64 t, %1; cvt.u32.u64 %0, t; }" : "=r"(a) : "l"(p));
    return a;
}
__device__ __forceinline__ void mbar_init(uint32_t addr, uint32_t cnt) {
    asm volatile("mbarrier.init.shared.b64 [%0], %1;" :: "r"(addr), "r"(cnt) : "memory");
}
__device__ __forceinline__ void mbar_expect_tx(uint32_t addr, uint32_t bytes) {
    asm volatile("mbarrier.arrive.expect_tx.shared.b64 _, [%0], %1;" :: "r"(addr), "r"(bytes) : "memory");
}
__device__ __forceinline__ void mbar_wait(uint32_t addr, uint32_t parity) {
    uint32_t done;
    asm volatile("{\n\t.reg .pred p;\n\t"
                 "mbarrier.try_wait.parity.acquire.cta.shared::cta.b64 p, [%1], %2;\n\t"
                 "selp.b32 %0, 1, 0, p;\n\t}"
                 : "=r"(done) : "r"(addr), "r"(parity) : "memory");
    if (!done) {
        asm volatile("{\n\t.reg .pred P1;\n\t"
                     "W_%=:\n\t"
                     "mbarrier.try_wait.parity.acquire.cta.shared::cta.b64 P1, [%0], %1, 0x989680;\n\t"
                     "@P1 bra.uni D_%=;\n\t"
                     "bra.uni W_%=;\n\t"
                     "D_%=:\n\t}"
                     :: "r"(addr), "r"(parity) : "memory");
    }
}
__device__ __forceinline__ void bulk_g2s(uint32_t dst, const void* src, uint32_t bytes, uint32_t mbar) {
    asm volatile("cp.async.bulk.shared::cluster.global.mbarrier::complete_tx::bytes [%0], [%1], %2, [%3];"
                 :: "r"(dst), "l"(src), "r"(bytes), "r"(mbar) : "memory");
}
__device__ __forceinline__ void cp_async16(uint32_t dst, const void* src) {
    asm volatile("cp.async.cg.shared.global [%0], [%1], 16;" :: "r"(dst), "l"(src) : "memory");
}
__device__ __forceinline__ void cp_commit() { asm volatile("cp.async.commit_group;" ::: "memory"); }
__device__ __forceinline__ void cp_wait1()  { asm volatile("cp.async.wait_group 1;" ::: "memory"); }
__device__ __forceinline__ void cp_wait0()  { asm volatile("cp.async.wait_group 0;" ::: "memory"); }
__device__ __forceinline__ void ldsm_x4(uint32_t addr, uint32_t& r0, uint32_t& r1,
                                        uint32_t& r2, uint32_t& r3) {
    asm volatile("ldmatrix.sync.aligned.m8n8.x4.shared.b16 {%0,%1,%2,%3}, [%4];"
                 : "=r"(r0), "=r"(r1), "=r"(r2), "=r"(r3) : "r"(addr));
}
__device__ __forceinline__ void mma_f16(float* d, const uint32_t* a, const uint32_t* b) {
    asm volatile("mma.sync.aligned.m16n8k16.row.col.f32.f16.f16.f32 "
                 "{%0,%1,%2,%3}, {%4,%5,%6,%7}, {%8,%9}, {%0,%1,%2,%3};"
                 : "+f"(d[0]), "+f"(d[1]), "+f"(d[2]), "+f"(d[3])
                 : "r"(a[0]), "r"(a[1]), "r"(a[2]), "r"(a[3]), "r"(b[0]), "r"(b[1]));
}
// swizzles: XOR 16B-unit index with row bits for various row pitches
__device__ __forceinline__ uint32_t sw64(uint32_t off)  { return off ^ ((off >> 3) & 0x30); }  // 64B rows
__device__ __forceinline__ uint32_t sw128(uint32_t off) { return off ^ ((off >> 3) & 0x70); }  // 128B rows
__device__ __forceinline__ uint32_t sw256(uint32_t off) { return off ^ ((off >> 4) & 0x70); }  // 256B rows

__device__ __forceinline__ uint32_t h2pack(float x, float y) {
    __half hx = __float2half_rn(x), hy = __float2half_rn(y);
    return (uint32_t)*(unsigned short*)&hx | ((uint32_t)*(unsigned short*)&hy << 16);
}

// ---------------------------------------------------------------------------
// Pack: in[R][4096] fp32 -> fp16 packed [R/BR][128][BR][32], pre-swizzled
// so raw bulk copies land ldmatrix-conflict-free in smem.
// ---------------------------------------------------------------------------
template <int BR>
__global__ __launch_bounds__(256) void pack_h(const float* __restrict__ in,
                                              __half* __restrict__ out, int R) {
    const int K = DIM;
    const int w = (blockIdx.x * 256 + threadIdx.x) >> 5;
    const int lane = threadIdx.x & 31;
    const int nW = (R >> 3) * KC;
    if (w >= nW) return;
    const int rg = w / KC, kc = w % KC;
    const int r = rg * 8 + (lane >> 2);
    const int kq = lane & 3;
    const float4 v0 = *(const float4*)&in[(size_t)r * K + kc * 32 + kq * 8];
    const float4 v1 = *(const float4*)&in[(size_t)r * K + kc * 32 + kq * 8 + 4];

    uint4 pk;
    pk.x = h2pack(v0.x, v0.y);
    pk.y = h2pack(v0.z, v0.w);
    pk.z = h2pack(v1.x, v1.y);
    pk.w = h2pack(v1.z, v1.w);

    const int rt = r / BR, row = r % BR;
    const size_t blk_bytes = ((size_t)rt * KC + kc) * (size_t)(BR * 64);
    const uint32_t sw = sw64((uint32_t)(row * 64 + kq * 16));
    *(uint4*)((char*)out + blk_bytes + sw) = pk;
}

// ---------------------------------------------------------------------------
// fp16 tensor-core GEMM, bulk-async fed, 6-stage pipeline.
// C[M,N] = A[M,K]*B[N,K]^T. CTA tile 128x256, BK=32, 8 warps (2x4), 64x64/warp.
// ---------------------------------------------------------------------------
#define BM 128
#define BN 256
#define ABLK 8192                 // 128*32*2
#define BBLK 16384                // 256*32*2
#define STG (ABLK + BBLK)         // 24576
#define NST 6
#define GEMM_SMEM (NST * STG)     // 147456

__global__ __launch_bounds__(256) void gemm_tc(
    const __half* __restrict__ A, const __half* __restrict__ B,
    float* __restrict__ C, int N)
{
    extern __shared__ char smg[];
    __shared__ uint64_t s_mbar[NST];

    const uint32_t sbase = smem_u32(smg);
    const int tid = threadIdx.x;
    const int wid = tid >> 5;
    const int lane = tid & 31;
    const int wm = wid & 1;
    const int wn = wid >> 1;
    const int bmb = blockIdx.y;
    const int bnb = blockIdx.x;

    uint32_t mb[NST];
#pragma unroll
    for (int i = 0; i < NST; i++) mb[i] = smem_u32(&s_mbar[i]);

    if (tid == 0)
        for (int i = 0; i < NST; i++) mbar_init(mb[i], 1);
    __syncthreads();

    const char* aG = (const char*)A + (size_t)bmb * KC * ABLK;
    const char* bG = (const char*)B + (size_t)bnb * KC * BBLK;

    auto issue = [&](int c, int s) {
        const uint32_t d = sbase + s * STG;
        mbar_expect_tx(mb[s], STG);
        bulk_g2s(d,        aG + (size_t)c * ABLK, ABLK, mb[s]);
        bulk_g2s(d + ABLK, bG + (size_t)c * BBLK, BBLK, mb[s]);
    };

    if (tid == 0)
        for (int i = 0; i < NST; i++) issue(i, i);

    float acc[4][8][4];
#pragma unroll
    for (int mt = 0; mt < 4; mt++)
#pragma unroll
        for (int nt = 0; nt < 8; nt++)
#pragma unroll
            for (int j = 0; j < 4; j++) acc[mt][nt][j] = 0.f;

    const int g = lane >> 3, r = lane & 7;

    for (int c = 0; c < KC; c++) {
        const int s = c % NST;
        mbar_wait(mb[s], (c / NST) & 1);

        const uint32_t aS = sbase + s * STG;
        const uint32_t bS = aS + ABLK;

#pragma unroll
        for (int ks = 0; ks < 2; ks++) {
            uint32_t bf[8][2];
#pragma unroll
            for (int p = 0; p < 4; p++) {
                const int nt = 2 * p + (g >> 1);
                const uint32_t a = sw64((uint32_t)((wn * 64 + nt * 8 + r) * 64 + ks * 32 + (g & 1) * 16));
                ldsm_x4(bS + a, bf[2 * p][0], bf[2 * p][1], bf[2 * p + 1][0], bf[2 * p + 1][1]);
            }
#pragma unroll
            for (int mt = 0; mt < 4; mt++) {
                const uint32_t a = sw64((uint32_t)((wm * 64 + mt * 16 + (g & 1) * 8 + r) * 64 + ks * 32 + (g >> 1) * 16));
                uint32_t af[4];
                ldsm_x4(aS + a, af[0], af[1], af[2], af[3]);
#pragma unroll
                for (int nt = 0; nt < 8; nt++)
                    mma_f16(acc[mt][nt], af, bf[nt]);
            }
        }
        __syncthreads();
        if (tid == 0 && c + NST < KC) issue(c + NST, s);
    }

    const int er = lane >> 2, ec = (lane & 3) * 2;
#pragma unroll
    for (int mt = 0; mt < 4; mt++) {
#pragma unroll
        for (int nt = 0; nt < 8; nt++) {
            const int row = bmb * BM + wm * 64 + mt * 16 + er;
            const int col = bnb * BN + wn * 64 + nt * 8 + ec;
            *(float2*)&C[(size_t)row * N + col]       = make_float2(acc[mt][nt][0], acc[mt][nt][1]);
            *(float2*)&C[(size_t)(row + 8) * N + col] = make_float2(acc[mt][nt][2], acc[mt][nt][3]);
        }
    }
}

// ---------------------------------------------------------------------------
// Fused RMSNorm + RoPE + scale + fp16 convert. grid (SEQ, 40).
// ---------------------------------------------------------------------------
__global__ __launch_bounds__(128) void rmsnorm_rope_h(
    const float* __restrict__ qkv,
    const float* __restrict__ qnw, const float* __restrict__ knw,
    const float* __restrict__ rope, const int* __restrict__ pos,
    __half* __restrict__ qo, __half* __restrict__ ko)
{
    const int tok = blockIdx.x;
    const int h = blockIdx.y;
    const int t = threadIdx.x;
    const bool isQ = h < NQH;
    const int col = isQ ? h * HD + t : QDIM + (h - NQH) * HD + t;

    float v = qkv[(size_t)tok * QKVD + col];

    float ss = v * v;
#pragma unroll
    for (int off = 16; off; off >>= 1) ss += __shfl_xor_sync(0xffffffffu, ss, off);
    __shared__ float red[4];
    if ((t & 31) == 0) red[t >> 5] = ss;
    __syncthreads();
    float tot = red[0] + red[1] + red[2] + red[3];
    float inv = rsqrtf(tot * (1.0f / HD) + 1e-6f);
    float nv = v * inv * (isQ ? qnw[t] : knw[t]);

    __shared__ float sh[HD];
    sh[t] = nv;
    __syncthreads();

    const int pp = pos[tok];
    float out;
    if (t < 64) {
        float c = rope[(pp * 64 + t) * 2 + 0];
        float s = rope[(pp * 64 + t) * 2 + 1];
        out = nv * c - sh[t + 64] * s;
    } else {
        int f = t - 64;
        float c = rope[(pp * 64 + f) * 2 + 0];
        float s = rope[(pp * 64 + f) * 2 + 1];
        out = nv * c + sh[f] * s;
    }
    if (isQ) out *= 0.08838834764831845f;   // 1/sqrt(128)

    const size_t idx = isQ ? ((size_t)h * SEQ + tok) * HD + t
                           : ((size_t)(h - NQH) * SEQ + tok) * HD + t;
    if (isQ) qo[idx] = __float2half_rn(out);
    else     ko[idx] = __float2half_rn(out);
}

// ---------------------------------------------------------------------------
// V: transpose + fp16 convert. grid (SEQ/32, 1024/32), block (32, 8).
// ---------------------------------------------------------------------------
__global__ __launch_bounds__(256) void v_t_h(const float* __restrict__ qkv,
                                             __half* __restrict__ vo) {
    __shared__ float tile[32][33];
    const int tx = threadIdx.x, ty = threadIdx.y;
    const int tok0 = blockIdx.x * 32, c0 = blockIdx.y * 32;
#pragma unroll
    for (int j = ty; j < 32; j += 8)
        tile[j][tx] = qkv[(size_t)(tok0 + j) * QKVD + (QDIM + KVD) + c0 + tx];
    __syncthreads();
#pragma unroll
    for (int j = ty; j < 32; j += 8)
        vo[(size_t)(c0 + j) * SEQ + tok0 + tx] = __float2half_rn(tile[tx][j]);
}

// ---------------------------------------------------------------------------
// fp16 tensor-core flash attention (segmented causal, GQA).
// BQ=BKV=64, 4 warps, 2-stage cp.async KV pipeline.
// Epilogue writes O directly in packed fp16 GEMM-A layout.
// ---------------------------------------------------------------------------
#define ATT_SMEM (16384 + 2 * 32768)  // Q + 2 stages of (K 16K | V 16K)

__global__ __launch_bounds__(128) void attn_tc(
    const __half* __restrict__ Q, const __half* __restrict__ K,
    const __half* __restrict__ V, __half* __restrict__ O)
{
    extern __shared__ char sma[];
    const uint32_t sb = smem_u32(sma);
    const int tid = threadIdx.x, wid = tid >> 5, lane = tid & 31;
    const int qb = blockIdx.x, seg = blockIdx.y, qh = blockIdx.z;
    const int kvh = qh >> 2;
    const int qtok0 = seg * SEG_LEN + qb * 64;
    const int g = lane >> 3, r = lane & 7;

    const uint32_t Qs = sb;

    // Q tile (group 0)
    {
        const char* src = (const char*)(Q + ((size_t)qh * SEQ + qtok0) * HD);
        for (int i = tid; i < 1024; i += 128) {
            int row = i >> 4, u = i & 15;
            uint32_t off = sw256((uint32_t)(row * 256 + u * 16));
            cp_async16(Qs + off, src + row * 256 + u * 16);
        }
        cp_commit();
    }

    auto issue_kv = [&](int kb, int s) {
        const int kt = seg * SEG_LEN + kb * 64;
        const uint32_t base = sb + 16384 + s * 32768;
        const char* kG = (const char*)(K + ((size_t)kvh * SEQ + kt) * HD);
        for (int i = tid; i < 1024; i += 128) {
            int row = i >> 4, u = i & 15;
            uint32_t off = sw256((uint32_t)(row * 256 + u * 16));
            cp_async16(base + off, kG + row * 256 + u * 16);
        }
        const char* vG = (const char*)V + ((size_t)kvh * HD * SEQ + kt) * 2;
        for (int i = tid; i < 1024; i += 128) {
            int row = i >> 3, u = i & 7;
            uint32_t off = sw128((uint32_t)(row * 128 + u * 16));
            cp_async16(base + 16384 + off, vG + (size_t)row * SEQ * 2 + u * 16);
        }
        cp_commit();
    };

    issue_kv(0, 0);
    if (qb >= 1) issue_kv(1, 1); else cp_commit();

    float m0 = -CUDART_INF_F, m1 = -CUDART_INF_F, l0 = 0.f, l1 = 0.f;
    float o[16][4];
#pragma unroll
    for (int nt = 0; nt < 16; nt++)
#pragma unroll
        for (int j = 0; j < 4; j++) o[nt][j] = 0.f;

    for (int kb = 0; kb <= qb; kb++) {
        const int s = kb & 1;
        cp_wait1();
        __syncthreads();
        const uint32_t Ks = sb + 16384 + s * 32768;
        const uint32_t Vs = Ks + 16384;

        // ---- S = Q K^T ----
        float sa[8][4];
#pragma unroll
        for (int nt = 0; nt < 8; nt++)
#pragma unroll
            for (int j = 0; j < 4; j++) sa[nt][j] = 0.f;

#pragma unroll
        for (int ks = 0; ks < 8; ks++) {
            const int arow = wid * 16 + (g & 1) * 8 + r;
            const uint32_t aoff = sw256((uint32_t)(arow * 256 + (ks * 2 + (g >> 1)) * 16));
            uint32_t af[4];
            ldsm_x4(Qs + aoff, af[0], af[1], af[2], af[3]);
            uint32_t bf[8][2];
#pragma unroll
            for (int p = 0; p < 4; p++) {
                const int nrow = (2 * p + (g >> 1)) * 8 + r;
                const uint32_t boff = sw256((uint32_t)(nrow * 256 + (ks * 2 + (g & 1)) * 16));
                ldsm_x4(Ks + boff, bf[2 * p][0], bf[2 * p][1], bf[2 * p + 1][0], bf[2 * p + 1][1]);
            }
#pragma unroll
            for (int nt = 0; nt < 8; nt++)
                mma_f16(sa[nt], af, bf[nt]);
        }

        // ---- causal mask on diagonal tile ----
        if (kb == qb) {
            const int r0 = wid * 16 + (lane >> 2);
#pragma unroll
            for (int nt = 0; nt < 8; nt++) {
                const int c = nt * 8 + (lane & 3) * 2;
                if (c     > r0)     sa[nt][0] = -CUDART_INF_F;
                if (c + 1 > r0)     sa[nt][1] = -CUDART_INF_F;
                if (c     > r0 + 8) sa[nt][2] = -CUDART_INF_F;
                if (c + 1 > r0 + 8) sa[nt][3] = -CUDART_INF_F;
            }
        }

        // ---- online softmax ----
        {
            float mx0 = -CUDART_INF_F, mx1 = -CUDART_INF_F;
#pragma unroll
            for (int nt = 0; nt < 8; nt++) {
                mx0 = fmaxf(mx0, fmaxf(sa[nt][0], sa[nt][1]));
                mx1 = fmaxf(mx1, fmaxf(sa[nt][2], sa[nt][3]));
            }
            mx0 = fmaxf(mx0, __shfl_xor_sync(0xffffffffu, mx0, 1));
            mx0 = fmaxf(mx0, __shfl_xor_sync(0xffffffffu, mx0, 2));
            mx1 = fmaxf(mx1, __shfl_xor_sync(0xffffffffu, mx1, 1));
            mx1 = fmaxf(mx1, __shfl_xor_sync(0xffffffffu, mx1, 2));
            const float mn0 = fmaxf(m0, mx0), mn1 = fmaxf(m1, mx1);
            const float a0 = __expf(m0 - mn0), a1 = __expf(m1 - mn1);
            float sum0 = 0.f, sum1 = 0.f;
#pragma unroll
            for (int nt = 0; nt < 8; nt++) {
                sa[nt][0] = __expf(sa[nt][0] - mn0); sum0 += sa[nt][0];
                sa[nt][1] = __expf(sa[nt][1] - mn0); sum0 += sa[nt][1];
                sa[nt][2] = __expf(sa[nt][2] - mn1); sum1 += sa[nt][2];
                sa[nt][3] = __expf(sa[nt][3] - mn1); sum1 += sa[nt][3];
            }
            sum0 += __shfl_xor_sync(0xffffffffu, sum0, 1);
            sum0 += __shfl_xor_sync(0xffffffffu, sum0, 2);
            sum1 += __shfl_xor_sync(0xffffffffu, sum1, 1);
            sum1 += __shfl_xor_sync(0xffffffffu, sum1, 2);
            l0 = l0 * a0 + sum0;
            l1 = l1 * a1 + sum1;
            m0 = mn0; m1 = mn1;
#pragma unroll
            for (int nt = 0; nt < 16; nt++) {
                o[nt][0] *= a0; o[nt][1] *= a0;
                o[nt][2] *= a1; o[nt][3] *= a1;
            }
        }

        // ---- O += P V (P A-frags from S accumulators, fp16) ----
#pragma unroll
        for (int kj = 0; kj < 4; kj++) {
            const int t0 = 2 * kj, t1 = t0 + 1;
            uint32_t pf[4];
            pf[0] = h2pack(sa[t0][0], sa[t0][1]);
            pf[1] = h2pack(sa[t0][2], sa[t0][3]);
            pf[2] = h2pack(sa[t1][0], sa[t1][1]);
            pf[3] = h2pack(sa[t1][2], sa[t1][3]);
#pragma unroll
            for (int p = 0; p < 8; p++) {
                const int vrow = (2 * p + (g >> 1)) * 8 + r;
                const uint32_t voff = sw128((uint32_t)(vrow * 128 + (kj * 2 + (g & 1)) * 16));
                uint32_t vf0[2], vf1[2];
                ldsm_x4(Vs + voff, vf0[0], vf0[1], vf1[0], vf1[1]);
                mma_f16(o[2 * p],     pf, vf0);
                mma_f16(o[2 * p + 1], pf, vf1);
            }
        }

        __syncthreads();
        if (kb + 2 <= qb) issue_kv(kb + 2, s); else cp_commit();
    }
    cp_wait0();

    // ---- epilogue: write packed fp16 GEMM-A layout ----
    const float li0 = 1.f / l0, li1 = 1.f / l1;
    const int tk0 = qtok0 + wid * 16 + (lane >> 2);
    const int tk1 = tk0 + 8;
#pragma unroll
    for (int nt = 0; nt < 16; nt++) {
        const int d = qh * HD + nt * 8 + (lane & 3) * 2;
        const size_t blk = ((size_t)(tk0 >> 7) * KC + (d >> 5)) * (size_t)(128 * 64);
        const uint32_t col2 = (uint32_t)((d & 31) * 2);
        const uint32_t lo4 = col2 & 15u;
        const uint32_t in0 = sw64((uint32_t)((tk0 & 127) * 64) + (col2 & ~15u)) + lo4;
        const uint32_t in1 = sw64((uint32_t)((tk1 & 127) * 64) + (col2 & ~15u)) + lo4;
        *(uint32_t*)((char*)O + blk + in0) = h2pack(o[nt][0] * li0, o[nt][1] * li0);
        *(uint32_t*)((char*)O + blk + in1) = h2pack(o[nt][2] * li1, o[nt][3] * li1);
    }
}

// ---------------------------------------------------------------------------
// Launch
// ---------------------------------------------------------------------------
extern "C" void kernel_launch(void* const* d_in, const int* in_sizes, int n_in,
                              void* d_out, int out_size) {
    const float* x    = (const float*)d_in[0];
    const float* wq   = (const float*)d_in[1];
    const float* wk   = (const float*)d_in[2];
    const float* wv   = (const float*)d_in[3];
    const float* wo   = (const float*)d_in[4];
    const float* qnw  = (const float*)d_in[5];
    const float* knw  = (const float*)d_in[6];
    const float* rope = (const float*)d_in[7];
    const int*   pos  = (const int*)d_in[8];

    float* qkv;
    cudaGetSymbolAddress((void**)&qkv, g_qkv);
    __half *xh, *oh, *wh, *woh, *qsh, *ksh, *vth;
    cudaGetSymbolAddress((void**)&xh, g_xh);
    cudaGetSymbolAddress((void**)&oh, g_oh);
    cudaGetSymbolAddress((void**)&wh, g_wh);
    cudaGetSymbolAddress((void**)&woh, g_woh);
    cudaGetSymbolAddress((void**)&qsh, g_qsh);
    cudaGetSymbolAddress((void**)&ksh, g_ksh);
    cudaGetSymbolAddress((void**)&vth, g_vth);

    cudaFuncSetAttribute(gemm_tc, cudaFuncAttributeMaxDynamicSharedMemorySize, GEMM_SMEM);
    cudaFuncSetAttribute(attn_tc, cudaFuncAttributeMaxDynamicSharedMemorySize, ATT_SMEM);

    // Pack inputs
    {
        int nthr = (SEQ / 8) * KC * 32;
        pack_h<128><<<(nthr + 255) / 256, 256>>>(x, xh, SEQ);
    }
    {
        int nthr = (QDIM / 8) * KC * 32;
        pack_h<256><<<(nthr + 255) / 256, 256>>>(wq, wh, QDIM);
    }
    {
        int nthr = (KVD / 8) * KC * 32;
        pack_h<256><<<(nthr + 255) / 256, 256>>>(wk, wh + (size_t)QDIM * DIM, KVD);
        pack_h<256><<<(nthr + 255) / 256, 256>>>(wv, wh + (size_t)(QDIM + KVD) * DIM, KVD);
    }
    {
        int nthr = (DIM / 8) * KC * 32;
        pack_h<256><<<(nthr + 255) / 256, 256>>>(wo, woh, DIM);
    }

    // Fused QKV projection
    gemm_tc<<<dim3(QKVD / BN, SEQ / BM), 256, GEMM_SMEM>>>(xh, wh, qkv, QKVD);

    // RMSNorm + RoPE + convert (Q pre-scaled), and V transpose + convert
    rmsnorm_rope_h<<<dim3(SEQ, NQH + NKVH), 128>>>(qkv, qnw, knw, rope, pos, qsh, ksh);
    v_t_h<<<dim3(SEQ / 32, KVD / 32), dim3(32, 8)>>>(qkv, vth);

    // Tensor-core attention (writes packed O)
    attn_tc<<<dim3(SEG_LEN / 64, N_SEG, NQH), 128, ATT_SMEM>>>(qsh, ksh, vth, oh);

    // Output projection
    gemm_tc<<<dim3(DIM / BN, SEQ / BM), 256, GEMM_SMEM>>>(oh, woh, (float*)d_out, DIM);
}

// round 8
// speedup vs baseline: 9.3592x; 1.1856x over previous
#include <cuda_runtime.h>
#include <cuda_fp16.h>
#include <math_constants.h>
#include <cstdint>

// ---------------------------------------------------------------------------
// Problem constants
// ---------------------------------------------------------------------------
#define SEQ      2048
#define DIM      4096
#define NQH      32
#define NKVH     8
#define HD       128
#define SEG_LEN  512
#define N_SEG    4
#define QDIM     (NQH * HD)    // 4096
#define KVD      (NKVH * HD)   // 1024
#define QKVD     6144          // fused q|k|v output width
#define KC       (DIM / 32)    // 128 k-chunks (all GEMMs have K=4096)

// fp32 scratch (fused qkv projection output)
__device__ float g_qkv[SEQ * QKVD];

// packed + swizzled fp16 GEMM operands (all 128-row blocks now)
__device__ __half g_xh[SEQ * DIM];       // A-layout
__device__ __half g_oh[SEQ * QDIM];      // A-layout (written by attention)
__device__ __half g_wh[QKVD * DIM];      // B-layout wq|wk|wv
__device__ __half g_woh[DIM * QDIM];     // B-layout

// attention operands (fp16, linear layouts)
__device__ __half g_qsh[NQH * SEQ * HD];    // [qh][tok][d]  (pre-scaled)
__device__ __half g_ksh[NKVH * SEQ * HD];   // [kvh][tok][d]
__device__ __half g_vth[NKVH * HD * SEQ];   // [kvh*128+d][tok]

// ---------------------------------------------------------------------------
// PTX helpers (base-target instructions only)
// ---------------------------------------------------------------------------
__device__ __forceinline__ uint32_t smem_u32(const void* p) {
    uint32_t a;
    asm("{ .reg .u64 t; cvta.to.shared.u64 t, %1; cvt.u32.u64 %0, t; }" : "=r"(a) : "l"(p));
    return a;
}
__device__ __forceinline__ void mbar_init(uint32_t addr, uint32_t cnt) {
    asm volatile("mbarrier.init.shared.b64 [%0], %1;" :: "r"(addr), "r"(cnt) : "memory");
}
__device__ __forceinline__ void mbar_expect_tx(uint32_t addr, uint32_t bytes) {
    asm volatile("mbarrier.arrive.expect_tx.shared.b64 _, [%0], %1;" :: "r"(addr), "r"(bytes) : "memory");
}
__device__ __forceinline__ void mbar_wait(uint32_t addr, uint32_t parity) {
    uint32_t done;
    asm volatile("{\n\t.reg .pred p;\n\t"
                 "mbarrier.try_wait.parity.acquire.cta.shared::cta.b64 p, [%1], %2;\n\t"
                 "selp.b32 %0, 1, 0, p;\n\t}"
                 : "=r"(done) : "r"(addr), "r"(parity) : "memory");
    if (!done) {
        asm volatile("{\n\t.reg .pred P1;\n\t"
                     "W_%=:\n\t"
                     "mbarrier.try_wait.parity.acquire.cta.shared::cta.b64 P1, [%0], %1, 0x989680;\n\t"
                     "@P1 bra.uni D_%=;\n\t"
                     "bra.uni W_%=;\n\t"
                     "D_%=:\n\t}"
                     :: "r"(addr), "r"(parity) : "memory");
    }
}
__device__ __forceinline__ void bulk_g2s(uint32_t dst, const void* src, uint32_t bytes, uint32_t mbar) {
    asm volatile("cp.async.bulk.shared::cluster.global.mbarrier::complete_tx::bytes [%0], [%1], %2, [%3];"
                 :: "r"(dst), "l"(src), "r"(bytes), "r"(mbar) : "memory");
}
__device__ __forceinline__ void cp_async16(uint32_t dst, const void* src) {
    asm volatile("cp.async.cg.shared.global [%0], [%1], 16;" :: "r"(dst), "l"(src) : "memory");
}
__device__ __forceinline__ void cp_commit() { asm volatile("cp.async.commit_group;" ::: "memory"); }
__device__ __forceinline__ void cp_wait1()  { asm volatile("cp.async.wait_group 1;" ::: "memory"); }
__device__ __forceinline__ void cp_wait0()  { asm volatile("cp.async.wait_group 0;" ::: "memory"); }
__device__ __forceinline__ void ldsm_x4(uint32_t addr, uint32_t& r0, uint32_t& r1,
                                        uint32_t& r2, uint32_t& r3) {
    asm volatile("ldmatrix.sync.aligned.m8n8.x4.shared.b16 {%0,%1,%2,%3}, [%4];"
                 : "=r"(r0), "=r"(r1), "=r"(r2), "=r"(r3) : "r"(addr));
}
__device__ __forceinline__ void mma_f16(float* d, const uint32_t* a, const uint32_t* b) {
    asm volatile("mma.sync.aligned.m16n8k16.row.col.f32.f16.f16.f32 "
                 "{%0,%1,%2,%3}, {%4,%5,%6,%7}, {%8,%9}, {%0,%1,%2,%3};"
                 : "+f"(d[0]), "+f"(d[1]), "+f"(d[2]), "+f"(d[3])
                 : "r"(a[0]), "r"(a[1]), "r"(a[2]), "r"(a[3]), "r"(b[0]), "r"(b[1]));
}
__device__ __forceinline__ uint32_t sw64(uint32_t off)  { return off ^ ((off >> 3) & 0x30); }
__device__ __forceinline__ uint32_t sw128(uint32_t off) { return off ^ ((off >> 3) & 0x70); }
__device__ __forceinline__ uint32_t sw256(uint32_t off) { return off ^ ((off >> 4) & 0x70); }

__device__ __forceinline__ uint32_t h2pack(float x, float y) {
    __half hx = __float2half_rn(x), hy = __float2half_rn(y);
    return (uint32_t)*(unsigned short*)&hx | ((uint32_t)*(unsigned short*)&hy << 16);
}

// ---------------------------------------------------------------------------
// Pack core: one warp packs 8 rows x 64 cols (2 k-chunks) of a [R,4096] fp32
// matrix into fp16 [R/128][128][128][32] pre-swizzled layout.
// ---------------------------------------------------------------------------
__device__ __forceinline__ void pack_warp(const float* __restrict__ in,
                                          __half* __restrict__ out,
                                          int rg, int kp, int lane) {
    const int r = rg * 8 + (lane >> 2);
    const int kq = lane & 3;
    const int rt = r >> 7, row = r & 127;
    const uint32_t sw = sw64((uint32_t)(row * 64 + kq * 16));
#pragma unroll
    for (int j = 0; j < 2; j++) {
        const int kc = kp * 2 + j;
        const float4 v0 = *(const float4*)&in[(size_t)r * DIM + kc * 32 + kq * 8];
        const float4 v1 = *(const float4*)&in[(size_t)r * DIM + kc * 32 + kq * 8 + 4];
        uint4 pk;
        pk.x = h2pack(v0.x, v0.y);
        pk.y = h2pack(v0.z, v0.w);
        pk.z = h2pack(v1.x, v1.y);
        pk.w = h2pack(v1.z, v1.w);
        const size_t blk = ((size_t)rt * KC + kc) * (size_t)(128 * 64);
        *(uint4*)((char*)out + blk + sw) = pk;
    }
}

__global__ __launch_bounds__(256) void pack_x(const float* __restrict__ in,
                                              __half* __restrict__ out, int R) {
    const int w = (blockIdx.x * 256 + threadIdx.x) >> 5;
    const int lane = threadIdx.x & 31;
    const int nW = (R >> 3) * (KC / 2);
    if (w >= nW) return;
    pack_warp(in, out, w / (KC / 2), w % (KC / 2), lane);
}

// Fused weight pack: wq|wk|wv -> g_wh (contiguous block ranges), wo -> g_woh.
__global__ __launch_bounds__(256) void pack_w(const float* __restrict__ wq,
                                              const float* __restrict__ wk,
                                              const float* __restrict__ wv,
                                              const float* __restrict__ wo,
                                              __half* __restrict__ wh,
                                              __half* __restrict__ woh) {
    const int w = (blockIdx.x * 256 + threadIdx.x) >> 5;
    const int lane = threadIdx.x & 31;
    const int rg = w / (KC / 2), kp = w % (KC / 2);
    const float* src;
    __half* dst;
    int rgl;
    if (rg < 512)      { src = wq; dst = wh;                              rgl = rg; }
    else if (rg < 640) { src = wk; dst = wh + (size_t)QDIM * DIM;         rgl = rg - 512; }
    else if (rg < 768) { src = wv; dst = wh + (size_t)(QDIM + KVD) * DIM; rgl = rg - 640; }
    else               { src = wo; dst = woh;                             rgl = rg - 768; }
    pack_warp(src, dst, rgl, kp, lane);
}

// ---------------------------------------------------------------------------
// fp16 tensor-core GEMM, bulk-async fed, 6-stage pipeline, 2 CTAs/SM.
// CTA tile 128x128, BK=32, 8 warps (2x4) of 64x32.
// ---------------------------------------------------------------------------
#define BM 128
#define BN 128
#define ABLK 8192                 // 128*32*2
#define BBLK 8192
#define STG (ABLK + BBLK)         // 16384
#define NST 6
#define GEMM_SMEM (NST * STG)     // 98304

__global__ __launch_bounds__(256, 2) void gemm_tc(
    const __half* __restrict__ A, const __half* __restrict__ B,
    float* __restrict__ C, int N)
{
    extern __shared__ char smg[];
    __shared__ uint64_t s_mbar[NST];

    const uint32_t sbase = smem_u32(smg);
    const int tid = threadIdx.x;
    const int wid = tid >> 5;
    const int lane = tid & 31;
    const int wm = wid & 1;            // 2 m-slabs of 64
    const int wn = wid >> 1;           // 4 n-slabs of 32
    const int bmb = blockIdx.y;
    const int bnb = blockIdx.x;

    uint32_t mb[NST];
#pragma unroll
    for (int i = 0; i < NST; i++) mb[i] = smem_u32(&s_mbar[i]);

    if (tid == 0)
        for (int i = 0; i < NST; i++) mbar_init(mb[i], 1);
    __syncthreads();

    const char* aG = (const char*)A + (size_t)bmb * KC * ABLK;
    const char* bG = (const char*)B + (size_t)bnb * KC * BBLK;

    auto issue = [&](int c, int s) {
        const uint32_t d = sbase + s * STG;
        mbar_expect_tx(mb[s], STG);
        bulk_g2s(d,        aG + (size_t)c * ABLK, ABLK, mb[s]);
        bulk_g2s(d + ABLK, bG + (size_t)c * BBLK, BBLK, mb[s]);
    };

    if (tid == 0)
        for (int i = 0; i < NST; i++) issue(i, i);

    float acc[4][4][4];
#pragma unroll
    for (int mt = 0; mt < 4; mt++)
#pragma unroll
        for (int nt = 0; nt < 4; nt++)
#pragma unroll
            for (int j = 0; j < 4; j++) acc[mt][nt][j] = 0.f;

    const int g = lane >> 3, r = lane & 7;

    for (int c = 0; c < KC; c++) {
        const int s = c % NST;
        mbar_wait(mb[s], (c / NST) & 1);

        const uint32_t aS = sbase + s * STG;
        const uint32_t bS = aS + ABLK;

#pragma unroll
        for (int ks = 0; ks < 2; ks++) {
            uint32_t bf[4][2];
#pragma unroll
            for (int p = 0; p < 2; p++) {
                const int nt = 2 * p + (g >> 1);
                const uint32_t a = sw64((uint32_t)((wn * 32 + nt * 8 + r) * 64 + ks * 32 + (g & 1) * 16));
                ldsm_x4(bS + a, bf[2 * p][0], bf[2 * p][1], bf[2 * p + 1][0], bf[2 * p + 1][1]);
            }
#pragma unroll
            for (int mt = 0; mt < 4; mt++) {
                const uint32_t a = sw64((uint32_t)((wm * 64 + mt * 16 + (g & 1) * 8 + r) * 64 + ks * 32 + (g >> 1) * 16));
                uint32_t af[4];
                ldsm_x4(aS + a, af[0], af[1], af[2], af[3]);
#pragma unroll
                for (int nt = 0; nt < 4; nt++)
                    mma_f16(acc[mt][nt], af, bf[nt]);
            }
        }
        __syncthreads();
        if (tid == 0 && c + NST < KC) issue(c + NST, s);
    }

    const int er = lane >> 2, ec = (lane & 3) * 2;
#pragma unroll
    for (int mt = 0; mt < 4; mt++) {
#pragma unroll
        for (int nt = 0; nt < 4; nt++) {
            const int row = bmb * BM + wm * 64 + mt * 16 + er;
            const int col = bnb * BN + wn * 32 + nt * 8 + ec;
            *(float2*)&C[(size_t)row * N + col]       = make_float2(acc[mt][nt][0], acc[mt][nt][1]);
            *(float2*)&C[(size_t)(row + 8) * N + col] = make_float2(acc[mt][nt][2], acc[mt][nt][3]);
        }
    }
}

// ---------------------------------------------------------------------------
// Fused RMSNorm + RoPE + scale + fp16 convert. grid (SEQ, 40).
// ---------------------------------------------------------------------------
__global__ __launch_bounds__(128) void rmsnorm_rope_h(
    const float* __restrict__ qkv,
    const float* __restrict__ qnw, const float* __restrict__ knw,
    const float* __restrict__ rope, const int* __restrict__ pos,
    __half* __restrict__ qo, __half* __restrict__ ko)
{
    const int tok = blockIdx.x;
    const int h = blockIdx.y;
    const int t = threadIdx.x;
    const bool isQ = h < NQH;
    const int col = isQ ? h * HD + t : QDIM + (h - NQH) * HD + t;

    float v = qkv[(size_t)tok * QKVD + col];

    float ss = v * v;
#pragma unroll
    for (int off = 16; off; off >>= 1) ss += __shfl_xor_sync(0xffffffffu, ss, off);
    __shared__ float red[4];
    if ((t & 31) == 0) red[t >> 5] = ss;
    __syncthreads();
    float tot = red[0] + red[1] + red[2] + red[3];
    float inv = rsqrtf(tot * (1.0f / HD) + 1e-6f);
    float nv = v * inv * (isQ ? qnw[t] : knw[t]);

    __shared__ float sh[HD];
    sh[t] = nv;
    __syncthreads();

    const int pp = pos[tok];
    float out;
    if (t < 64) {
        float c = rope[(pp * 64 + t) * 2 + 0];
        float s = rope[(pp * 64 + t) * 2 + 1];
        out = nv * c - sh[t + 64] * s;
    } else {
        int f = t - 64;
        float c = rope[(pp * 64 + f) * 2 + 0];
        float s = rope[(pp * 64 + f) * 2 + 1];
        out = nv * c + sh[f] * s;
    }
    if (isQ) out *= 0.08838834764831845f;   // 1/sqrt(128)

    const size_t idx = isQ ? ((size_t)h * SEQ + tok) * HD + t
                           : ((size_t)(h - NQH) * SEQ + tok) * HD + t;
    if (isQ) qo[idx] = __float2half_rn(out);
    else     ko[idx] = __float2half_rn(out);
}

// ---------------------------------------------------------------------------
// V: transpose + fp16 convert. grid (SEQ/32, 1024/32), block (32, 8).
// ---------------------------------------------------------------------------
__global__ __launch_bounds__(256) void v_t_h(const float* __restrict__ qkv,
                                             __half* __restrict__ vo) {
    __shared__ float tile[32][33];
    const int tx = threadIdx.x, ty = threadIdx.y;
    const int tok0 = blockIdx.x * 32, c0 = blockIdx.y * 32;
#pragma unroll
    for (int j = ty; j < 32; j += 8)
        tile[j][tx] = qkv[(size_t)(tok0 + j) * QKVD + (QDIM + KVD) + c0 + tx];
    __syncthreads();
#pragma unroll
    for (int j = ty; j < 32; j += 8)
        vo[(size_t)(c0 + j) * SEQ + tok0 + tx] = __float2half_rn(tile[tx][j]);
}

// ---------------------------------------------------------------------------
// fp16 tensor-core flash attention (segmented causal, GQA).
// BQ=BKV=64, 4 warps, 2-stage cp.async KV pipeline.
// Epilogue writes O directly in packed fp16 GEMM-A layout (128-row blocks).
// ---------------------------------------------------------------------------
#define ATT_SMEM (16384 + 2 * 32768)

__global__ __launch_bounds__(128) void attn_tc(
    const __half* __restrict__ Q, const __half* __restrict__ K,
    const __half* __restrict__ V, __half* __restrict__ O)
{
    extern __shared__ char sma[];
    const uint32_t sb = smem_u32(sma);
    const int tid = threadIdx.x, wid = tid >> 5, lane = tid & 31;
    const int qb = blockIdx.x, seg = blockIdx.y, qh = blockIdx.z;
    const int kvh = qh >> 2;
    const int qtok0 = seg * SEG_LEN + qb * 64;
    const int g = lane >> 3, r = lane & 7;

    const uint32_t Qs = sb;

    {
        const char* src = (const char*)(Q + ((size_t)qh * SEQ + qtok0) * HD);
        for (int i = tid; i < 1024; i += 128) {
            int row = i >> 4, u = i & 15;
            uint32_t off = sw256((uint32_t)(row * 256 + u * 16));
            cp_async16(Qs + off, src + row * 256 + u * 16);
        }
        cp_commit();
    }

    auto issue_kv = [&](int kb, int s) {
        const int kt = seg * SEG_LEN + kb * 64;
        const uint32_t base = sb + 16384 + s * 32768;
        const char* kG = (const char*)(K + ((size_t)kvh * SEQ + kt) * HD);
        for (int i = tid; i < 1024; i += 128) {
            int row = i >> 4, u = i & 15;
            uint32_t off = sw256((uint32_t)(row * 256 + u * 16));
            cp_async16(base + off, kG + row * 256 + u * 16);
        }
        const char* vG = (const char*)V + ((size_t)kvh * HD * SEQ + kt) * 2;
        for (int i = tid; i < 1024; i += 128) {
            int row = i >> 3, u = i & 7;
            uint32_t off = sw128((uint32_t)(row * 128 + u * 16));
            cp_async16(base + 16384 + off, vG + (size_t)row * SEQ * 2 + u * 16);
        }
        cp_commit();
    };

    issue_kv(0, 0);
    if (qb >= 1) issue_kv(1, 1); else cp_commit();

    float m0 = -CUDART_INF_F, m1 = -CUDART_INF_F, l0 = 0.f, l1 = 0.f;
    float o[16][4];
#pragma unroll
    for (int nt = 0; nt < 16; nt++)
#pragma unroll
        for (int j = 0; j < 4; j++) o[nt][j] = 0.f;

    for (int kb = 0; kb <= qb; kb++) {
        const int s = kb & 1;
        cp_wait1();
        __syncthreads();
        const uint32_t Ks = sb + 16384 + s * 32768;
        const uint32_t Vs = Ks + 16384;

        float sa[8][4];
#pragma unroll
        for (int nt = 0; nt < 8; nt++)
#pragma unroll
            for (int j = 0; j < 4; j++) sa[nt][j] = 0.f;

#pragma unroll
        for (int ks = 0; ks < 8; ks++) {
            const int arow = wid * 16 + (g & 1) * 8 + r;
            const uint32_t aoff = sw256((uint32_t)(arow * 256 + (ks * 2 + (g >> 1)) * 16));
            uint32_t af[4];
            ldsm_x4(Qs + aoff, af[0], af[1], af[2], af[3]);
            uint32_t bf[8][2];
#pragma unroll
            for (int p = 0; p < 4; p++) {
                const int nrow = (2 * p + (g >> 1)) * 8 + r;
                const uint32_t boff = sw256((uint32_t)(nrow * 256 + (ks * 2 + (g & 1)) * 16));
                ldsm_x4(Ks + boff, bf[2 * p][0], bf[2 * p][1], bf[2 * p + 1][0], bf[2 * p + 1][1]);
            }
#pragma unroll
            for (int nt = 0; nt < 8; nt++)
                mma_f16(sa[nt], af, bf[nt]);
        }

        if (kb == qb) {
            const int r0 = wid * 16 + (lane >> 2);
#pragma unroll
            for (int nt = 0; nt < 8; nt++) {
                const int c = nt * 8 + (lane & 3) * 2;
                if (c     > r0)     sa[nt][0] = -CUDART_INF_F;
                if (c + 1 > r0)     sa[nt][1] = -CUDART_INF_F;
                if (c     > r0 + 8) sa[nt][2] = -CUDART_INF_F;
                if (c + 1 > r0 + 8) sa[nt][3] = -CUDART_INF_F;
            }
        }

        {
            float mx0 = -CUDART_INF_F, mx1 = -CUDART_INF_F;
#pragma unroll
            for (int nt = 0; nt < 8; nt++) {
                mx0 = fmaxf(mx0, fmaxf(sa[nt][0], sa[nt][1]));
                mx1 = fmaxf(mx1, fmaxf(sa[nt][2], sa[nt][3]));
            }
            mx0 = fmaxf(mx0, __shfl_xor_sync(0xffffffffu, mx0, 1));
            mx0 = fmaxf(mx0, __shfl_xor_sync(0xffffffffu, mx0, 2));
            mx1 = fmaxf(mx1, __shfl_xor_sync(0xffffffffu, mx1, 1));
            mx1 = fmaxf(mx1, __shfl_xor_sync(0xffffffffu, mx1, 2));
            const float mn0 = fmaxf(m0, mx0), mn1 = fmaxf(m1, mx1);
            const float a0 = __expf(m0 - mn0), a1 = __expf(m1 - mn1);
            float sum0 = 0.f, sum1 = 0.f;
#pragma unroll
            for (int nt = 0; nt < 8; nt++) {
                sa[nt][0] = __expf(sa[nt][0] - mn0); sum0 += sa[nt][0];
                sa[nt][1] = __expf(sa[nt][1] - mn0); sum0 += sa[nt][1];
                sa[nt][2] = __expf(sa[nt][2] - mn1); sum1 += sa[nt][2];
                sa[nt][3] = __expf(sa[nt][3] - mn1); sum1 += sa[nt][3];
            }
            sum0 += __shfl_xor_sync(0xffffffffu, sum0, 1);
            sum0 += __shfl_xor_sync(0xffffffffu, sum0, 2);
            sum1 += __shfl_xor_sync(0xffffffffu, sum1, 1);
            sum1 += __shfl_xor_sync(0xffffffffu, sum1, 2);
            l0 = l0 * a0 + sum0;
            l1 = l1 * a1 + sum1;
            m0 = mn0; m1 = mn1;
#pragma unroll
            for (int nt = 0; nt < 16; nt++) {
                o[nt][0] *= a0; o[nt][1] *= a0;
                o[nt][2] *= a1; o[nt][3] *= a1;
            }
        }

#pragma unroll
        for (int kj = 0; kj < 4; kj++) {
            const int t0 = 2 * kj, t1 = t0 + 1;
            uint32_t pf[4];
            pf[0] = h2pack(sa[t0][0], sa[t0][1]);
            pf[1] = h2pack(sa[t0][2], sa[t0][3]);
            pf[2] = h2pack(sa[t1][0], sa[t1][1]);
            pf[3] = h2pack(sa[t1][2], sa[t1][3]);
#pragma unroll
            for (int p = 0; p < 8; p++) {
                const int vrow = (2 * p + (g >> 1)) * 8 + r;
                const uint32_t voff = sw128((uint32_t)(vrow * 128 + (kj * 2 + (g & 1)) * 16));
                uint32_t vf0[2], vf1[2];
                ldsm_x4(Vs + voff, vf0[0], vf0[1], vf1[0], vf1[1]);
                mma_f16(o[2 * p],     pf, vf0);
                mma_f16(o[2 * p + 1], pf, vf1);
            }
        }

        __syncthreads();
        if (kb + 2 <= qb) issue_kv(kb + 2, s); else cp_commit();
    }
    cp_wait0();

    const float li0 = 1.f / l0, li1 = 1.f / l1;
    const int tk0 = qtok0 + wid * 16 + (lane >> 2);
    const int tk1 = tk0 + 8;
#pragma unroll
    for (int nt = 0; nt < 16; nt++) {
        const int d = qh * HD + nt * 8 + (lane & 3) * 2;
        const size_t blk = ((size_t)(tk0 >> 7) * KC + (d >> 5)) * (size_t)(128 * 64);
        const uint32_t col2 = (uint32_t)((d & 31) * 2);
        const uint32_t lo4 = col2 & 15u;
        const uint32_t in0 = sw64((uint32_t)((tk0 & 127) * 64) + (col2 & ~15u)) + lo4;
        const uint32_t in1 = sw64((uint32_t)((tk1 & 127) * 64) + (col2 & ~15u)) + lo4;
        *(uint32_t*)((char*)O + blk + in0) = h2pack(o[nt][0] * li0, o[nt][1] * li0);
        *(uint32_t*)((char*)O + blk + in1) = h2pack(o[nt][2] * li1, o[nt][3] * li1);
    }
}

// ---------------------------------------------------------------------------
// Launch
// ---------------------------------------------------------------------------
extern "C" void kernel_launch(void* const* d_in, const int* in_sizes, int n_in,
                              void* d_out, int out_size) {
    const float* x    = (const float*)d_in[0];
    const float* wq   = (const float*)d_in[1];
    const float* wk   = (const float*)d_in[2];
    const float* wv   = (const float*)d_in[3];
    const float* wo   = (const float*)d_in[4];
    const float* qnw  = (const float*)d_in[5];
    const float* knw  = (const float*)d_in[6];
    const float* rope = (const float*)d_in[7];
    const int*   pos  = (const int*)d_in[8];

    float* qkv;
    cudaGetSymbolAddress((void**)&qkv, g_qkv);
    __half *xh, *oh, *wh, *woh, *qsh, *ksh, *vth;
    cudaGetSymbolAddress((void**)&xh, g_xh);
    cudaGetSymbolAddress((void**)&oh, g_oh);
    cudaGetSymbolAddress((void**)&wh, g_wh);
    cudaGetSymbolAddress((void**)&woh, g_woh);
    cudaGetSymbolAddress((void**)&qsh, g_qsh);
    cudaGetSymbolAddress((void**)&ksh, g_ksh);
    cudaGetSymbolAddress((void**)&vth, g_vth);

    cudaFuncSetAttribute(gemm_tc, cudaFuncAttributeMaxDynamicSharedMemorySize, GEMM_SMEM);
    cudaFuncSetAttribute(attn_tc, cudaFuncAttributeMaxDynamicSharedMemorySize, ATT_SMEM);

    // Packs: x (one launch) + all weights (one fused launch)
    {
        int nW = (SEQ / 8) * (KC / 2);                      // 16384 warps
        pack_x<<<(nW * 32 + 255) / 256, 256>>>(x, xh, SEQ);
        int nWw = ((QDIM + KVD + KVD + DIM) / 8) * (KC / 2); // 81920 warps
        pack_w<<<(nWw * 32 + 255) / 256, 256>>>(wq, wk, wv, wo, wh, woh);
    }

    // Fused QKV projection (grid 48 x 16)
    gemm_tc<<<dim3(QKVD / BN, SEQ / BM), 256, GEMM_SMEM>>>(xh, wh, qkv, QKVD);

    // RMSNorm + RoPE + convert (Q pre-scaled), and V transpose + convert
    rmsnorm_rope_h<<<dim3(SEQ, NQH + NKVH), 128>>>(qkv, qnw, knw, rope, pos, qsh, ksh);
    v_t_h<<<dim3(SEQ / 32, KVD / 32), dim3(32, 8)>>>(qkv, vth);

    // Tensor-core attention (writes packed O)
    attn_tc<<<dim3(SEG_LEN / 64, N_SEG, NQH), 128, ATT_SMEM>>>(qsh, ksh, vth, oh);

    // Output projection (grid 32 x 16)
    gemm_tc<<<dim3(DIM / BN, SEQ / BM), 256, GEMM_SMEM>>>(oh, woh, (float*)d_out, DIM);
}

// round 9
// speedup vs baseline: 9.9759x; 1.0659x over previous
#include <cuda_runtime.h>
#include <cuda_fp16.h>
#include <math_constants.h>
#include <cstdint>

// ---------------------------------------------------------------------------
// Problem constants
// ---------------------------------------------------------------------------
#define SEQ      2048
#define DIM      4096
#define NQH      32
#define NKVH     8
#define HD       128
#define SEG_LEN  512
#define N_SEG    4
#define QDIM     (NQH * HD)    // 4096
#define KVD      (NKVH * HD)   // 1024
#define QKVD     6144          // fused q|k|v output width
#define KC       (DIM / 32)    // 128 k-chunks (all GEMMs have K=4096)

// fp32 scratch (fused qkv projection output)
__device__ float g_qkv[SEQ * QKVD];

// packed + swizzled fp16 GEMM operands (128-row blocks)
__device__ __half g_xh[SEQ * DIM];       // A-layout
__device__ __half g_oh[SEQ * QDIM];      // A-layout (written by attention)
__device__ __half g_wh[QKVD * DIM];      // B-layout wq|wk|wv
__device__ __half g_woh[DIM * QDIM];     // B-layout

// attention operands (fp16, linear layouts)
__device__ __half g_qsh[NQH * SEQ * HD];    // [qh][tok][d]  (pre-scaled)
__device__ __half g_ksh[NKVH * SEQ * HD];   // [kvh][tok][d]
__device__ __half g_vth[NKVH * HD * SEQ];   // [kvh*128+d][tok]

// ---------------------------------------------------------------------------
// PTX helpers (base-target instructions only)
// ---------------------------------------------------------------------------
__device__ __forceinline__ uint32_t smem_u32(const void* p) {
    uint32_t a;
    asm("{ .reg .u64 t; cvta.to.shared.u64 t, %1; cvt.u32.u64 %0, t; }" : "=r"(a) : "l"(p));
    return a;
}
__device__ __forceinline__ void mbar_init(uint32_t addr, uint32_t cnt) {
    asm volatile("mbarrier.init.shared.b64 [%0], %1;" :: "r"(addr), "r"(cnt) : "memory");
}
__device__ __forceinline__ void mbar_expect_tx(uint32_t addr, uint32_t bytes) {
    asm volatile("mbarrier.arrive.expect_tx.shared.b64 _, [%0], %1;" :: "r"(addr), "r"(bytes) : "memory");
}
__device__ __forceinline__ void mbar_wait(uint32_t addr, uint32_t parity) {
    uint32_t done;
    asm volatile("{\n\t.reg .pred p;\n\t"
                 "mbarrier.try_wait.parity.acquire.cta.shared::cta.b64 p, [%1], %2;\n\t"
                 "selp.b32 %0, 1, 0, p;\n\t}"
                 : "=r"(done) : "r"(addr), "r"(parity) : "memory");
    if (!done) {
        asm volatile("{\n\t.reg .pred P1;\n\t"
                     "W_%=:\n\t"
                     "mbarrier.try_wait.parity.acquire.cta.shared::cta.b64 P1, [%0], %1, 0x989680;\n\t"
                     "@P1 bra.uni D_%=;\n\t"
                     "bra.uni W_%=;\n\t"
                     "D_%=:\n\t}"
                     :: "r"(addr), "r"(parity) : "memory");
    }
}
__device__ __forceinline__ void bulk_g2s(uint32_t dst, const void* src, uint32_t bytes, uint32_t mbar) {
    asm volatile("cp.async.bulk.shared::cluster.global.mbarrier::complete_tx::bytes [%0], [%1], %2, [%3];"
                 :: "r"(dst), "l"(src), "r"(bytes), "r"(mbar) : "memory");
}
__device__ __forceinline__ void cp_async16(uint32_t dst, const void* src) {
    asm volatile("cp.async.cg.shared.global [%0], [%1], 16;" :: "r"(dst), "l"(src) : "memory");
}
__device__ __forceinline__ void cp_commit() { asm volatile("cp.async.commit_group;" ::: "memory"); }
__device__ __forceinline__ void cp_wait1()  { asm volatile("cp.async.wait_group 1;" ::: "memory"); }
__device__ __forceinline__ void cp_wait0()  { asm volatile("cp.async.wait_group 0;" ::: "memory"); }
__device__ __forceinline__ void ldsm_x4(uint32_t addr, uint32_t& r0, uint32_t& r1,
                                        uint32_t& r2, uint32_t& r3) {
    asm volatile("ldmatrix.sync.aligned.m8n8.x4.shared.b16 {%0,%1,%2,%3}, [%4];"
                 : "=r"(r0), "=r"(r1), "=r"(r2), "=r"(r3) : "r"(addr));
}
__device__ __forceinline__ void mma_f16(float* d, const uint32_t* a, const uint32_t* b) {
    asm volatile("mma.sync.aligned.m16n8k16.row.col.f32.f16.f16.f32 "
                 "{%0,%1,%2,%3}, {%4,%5,%6,%7}, {%8,%9}, {%0,%1,%2,%3};"
                 : "+f"(d[0]), "+f"(d[1]), "+f"(d[2]), "+f"(d[3])
                 : "r"(a[0]), "r"(a[1]), "r"(a[2]), "r"(a[3]), "r"(b[0]), "r"(b[1]));
}
__device__ __forceinline__ uint32_t sw64(uint32_t off)  { return off ^ ((off >> 3) & 0x30); }
__device__ __forceinline__ uint32_t sw128(uint32_t off) { return off ^ ((off >> 3) & 0x70); }
__device__ __forceinline__ uint32_t sw256(uint32_t off) { return off ^ ((off >> 4) & 0x70); }

__device__ __forceinline__ uint32_t h2pack(float x, float y) {
    __half hx = __float2half_rn(x), hy = __float2half_rn(y);
    return (uint32_t)*(unsigned short*)&hx | ((uint32_t)*(unsigned short*)&hy << 16);
}

// ---------------------------------------------------------------------------
// Pack core: one warp packs 8 rows x 64 cols (2 k-chunks) of a [R,4096] fp32
// matrix into fp16 [R/128][128][128][32] pre-swizzled layout.
// ---------------------------------------------------------------------------
__device__ __forceinline__ void pack_warp(const float* __restrict__ in,
                                          __half* __restrict__ out,
                                          int rg, int kp, int lane) {
    const int r = rg * 8 + (lane >> 2);
    const int kq = lane & 3;
    const int rt = r >> 7, row = r & 127;
    const uint32_t sw = sw64((uint32_t)(row * 64 + kq * 16));
#pragma unroll
    for (int j = 0; j < 2; j++) {
        const int kc = kp * 2 + j;
        const float4 v0 = *(const float4*)&in[(size_t)r * DIM + kc * 32 + kq * 8];
        const float4 v1 = *(const float4*)&in[(size_t)r * DIM + kc * 32 + kq * 8 + 4];
        uint4 pk;
        pk.x = h2pack(v0.x, v0.y);
        pk.y = h2pack(v0.z, v0.w);
        pk.z = h2pack(v1.x, v1.y);
        pk.w = h2pack(v1.z, v1.w);
        const size_t blk = ((size_t)rt * KC + kc) * (size_t)(128 * 64);
        *(uint4*)((char*)out + blk + sw) = pk;
    }
}

// One fused pack for all five matrices: x | wq | wk | wv | wo.
// Row groups: x 0-255, wq 256-767, wk 768-895, wv 896-1023, wo 1024-1535.
__global__ __launch_bounds__(256) void pack_all(const float* __restrict__ x,
                                                const float* __restrict__ wq,
                                                const float* __restrict__ wk,
                                                const float* __restrict__ wv,
                                                const float* __restrict__ wo,
                                                __half* __restrict__ xh,
                                                __half* __restrict__ wh,
                                                __half* __restrict__ woh) {
    const int w = (blockIdx.x * 256 + threadIdx.x) >> 5;
    const int lane = threadIdx.x & 31;
    const int rg = w / (KC / 2), kp = w % (KC / 2);
    const float* src;
    __half* dst;
    int rgl;
    if (rg < 256)       { src = x;  dst = xh;                             rgl = rg; }
    else if (rg < 768)  { src = wq; dst = wh;                             rgl = rg - 256; }
    else if (rg < 896)  { src = wk; dst = wh + (size_t)QDIM * DIM;        rgl = rg - 768; }
    else if (rg < 1024) { src = wv; dst = wh + (size_t)(QDIM + KVD) * DIM; rgl = rg - 896; }
    else                { src = wo; dst = woh;                            rgl = rg - 1024; }
    pack_warp(src, dst, rgl, kp, lane);
}

// ---------------------------------------------------------------------------
// fp16 tensor-core GEMM, bulk-async fed, 6-stage pipeline, 2 CTAs/SM.
// CTA tile 128x128, BK=32, 8 warps (2x4) of 64x32.
// ---------------------------------------------------------------------------
#define BM 128
#define BN 128
#define ABLK 8192
#define BBLK 8192
#define STG (ABLK + BBLK)         // 16384
#define NST 6
#define GEMM_SMEM (NST * STG)     // 98304

__global__ __launch_bounds__(256, 2) void gemm_tc(
    const __half* __restrict__ A, const __half* __restrict__ B,
    float* __restrict__ C, int N)
{
    extern __shared__ char smg[];
    __shared__ uint64_t s_mbar[NST];

    const uint32_t sbase = smem_u32(smg);
    const int tid = threadIdx.x;
    const int wid = tid >> 5;
    const int lane = tid & 31;
    const int wm = wid & 1;
    const int wn = wid >> 1;
    const int bmb = blockIdx.y;
    const int bnb = blockIdx.x;

    uint32_t mb[NST];
#pragma unroll
    for (int i = 0; i < NST; i++) mb[i] = smem_u32(&s_mbar[i]);

    if (tid == 0)
        for (int i = 0; i < NST; i++) mbar_init(mb[i], 1);
    __syncthreads();

    const char* aG = (const char*)A + (size_t)bmb * KC * ABLK;
    const char* bG = (const char*)B + (size_t)bnb * KC * BBLK;

    auto issue = [&](int c, int s) {
        const uint32_t d = sbase + s * STG;
        mbar_expect_tx(mb[s], STG);
        bulk_g2s(d,        aG + (size_t)c * ABLK, ABLK, mb[s]);
        bulk_g2s(d + ABLK, bG + (size_t)c * BBLK, BBLK, mb[s]);
    };

    if (tid == 0)
        for (int i = 0; i < NST; i++) issue(i, i);

    float acc[4][4][4];
#pragma unroll
    for (int mt = 0; mt < 4; mt++)
#pragma unroll
        for (int nt = 0; nt < 4; nt++)
#pragma unroll
            for (int j = 0; j < 4; j++) acc[mt][nt][j] = 0.f;

    const int g = lane >> 3, r = lane & 7;

    for (int c = 0; c < KC; c++) {
        const int s = c % NST;
        mbar_wait(mb[s], (c / NST) & 1);

        const uint32_t aS = sbase + s * STG;
        const uint32_t bS = aS + ABLK;

#pragma unroll
        for (int ks = 0; ks < 2; ks++) {
            uint32_t bf[4][2];
#pragma unroll
            for (int p = 0; p < 2; p++) {
                const int nt = 2 * p + (g >> 1);
                const uint32_t a = sw64((uint32_t)((wn * 32 + nt * 8 + r) * 64 + ks * 32 + (g & 1) * 16));
                ldsm_x4(bS + a, bf[2 * p][0], bf[2 * p][1], bf[2 * p + 1][0], bf[2 * p + 1][1]);
            }
#pragma unroll
            for (int mt = 0; mt < 4; mt++) {
                const uint32_t a = sw64((uint32_t)((wm * 64 + mt * 16 + (g & 1) * 8 + r) * 64 + ks * 32 + (g >> 1) * 16));
                uint32_t af[4];
                ldsm_x4(aS + a, af[0], af[1], af[2], af[3]);
#pragma unroll
                for (int nt = 0; nt < 4; nt++)
                    mma_f16(acc[mt][nt], af, bf[nt]);
            }
        }
        __syncthreads();
        if (tid == 0 && c + NST < KC) issue(c + NST, s);
    }

    const int er = lane >> 2, ec = (lane & 3) * 2;
#pragma unroll
    for (int mt = 0; mt < 4; mt++) {
#pragma unroll
        for (int nt = 0; nt < 4; nt++) {
            const int row = bmb * BM + wm * 64 + mt * 16 + er;
            const int col = bnb * BN + wn * 32 + nt * 8 + ec;
            *(float2*)&C[(size_t)row * N + col]       = make_float2(acc[mt][nt][0], acc[mt][nt][1]);
            *(float2*)&C[(size_t)(row + 8) * N + col] = make_float2(acc[mt][nt][2], acc[mt][nt][3]);
        }
    }
}

// ---------------------------------------------------------------------------
// Warp-per-head RMSNorm + RoPE + scale + fp16 convert. No smem, no barriers.
// Global warp w -> (tok = w/40, h = w%40); h<32 Q head, else K head.
// Lane holds 4 consecutive d values; RoPE partner is lane^16.
// ---------------------------------------------------------------------------
__global__ __launch_bounds__(256) void rmsnorm_rope_h(
    const float* __restrict__ qkv,
    const float* __restrict__ qnw, const float* __restrict__ knw,
    const float* __restrict__ rope, const int* __restrict__ pos,
    __half* __restrict__ qo, __half* __restrict__ ko)
{
    const int w = (blockIdx.x * 256 + threadIdx.x) >> 5;
    const int lane = threadIdx.x & 31;
    const int tok = w / (NQH + NKVH);
    const int h = w % (NQH + NKVH);
    const bool isQ = h < NQH;
    const int colbase = isQ ? h * HD : QDIM + (h - NQH) * HD;

    const float4 v = *(const float4*)&qkv[(size_t)tok * QKVD + colbase + lane * 4];

    float ss = v.x * v.x + v.y * v.y + v.z * v.z + v.w * v.w;
#pragma unroll
    for (int off = 16; off; off >>= 1) ss += __shfl_xor_sync(0xffffffffu, ss, off);
    const float inv = rsqrtf(ss * (1.0f / HD) + 1e-6f);

    const float4 wt = *(const float4*)&(isQ ? qnw : knw)[lane * 4];
    float n0 = v.x * inv * wt.x, n1 = v.y * inv * wt.y;
    float n2 = v.z * inv * wt.z, n3 = v.w * inv * wt.w;

    // RoPE partner values from lane^16
    const float p0 = __shfl_xor_sync(0xffffffffu, n0, 16);
    const float p1 = __shfl_xor_sync(0xffffffffu, n1, 16);
    const float p2 = __shfl_xor_sync(0xffffffffu, n2, 16);
    const float p3 = __shfl_xor_sync(0xffffffffu, n3, 16);

    const int pp = pos[tok];
    const int f = (lane & 15) * 4;                      // freq base for this lane
    const float4 cs0 = *(const float4*)&rope[(size_t)(pp * 64 + f) * 2];      // c0,s0,c1,s1
    const float4 cs1 = *(const float4*)&rope[(size_t)(pp * 64 + f) * 2 + 4];  // c2,s2,c3,s3

    float o0, o1, o2, o3;
    if (lane < 16) {
        o0 = n0 * cs0.x - p0 * cs0.y;
        o1 = n1 * cs0.z - p1 * cs0.w;
        o2 = n2 * cs1.x - p2 * cs1.y;
        o3 = n3 * cs1.z - p3 * cs1.w;
    } else {
        o0 = n0 * cs0.x + p0 * cs0.y;
        o1 = n1 * cs0.z + p1 * cs0.w;
        o2 = n2 * cs1.x + p2 * cs1.y;
        o3 = n3 * cs1.z + p3 * cs1.w;
    }
    if (isQ) {
        const float sc = 0.08838834764831845f;   // 1/sqrt(128)
        o0 *= sc; o1 *= sc; o2 *= sc; o3 *= sc;
    }

    uint2 outp = make_uint2(h2pack(o0, o1), h2pack(o2, o3));
    const size_t idx = isQ ? ((size_t)h * SEQ + tok) * HD + lane * 4
                           : ((size_t)(h - NQH) * SEQ + tok) * HD + lane * 4;
    if (isQ) *(uint2*)&qo[idx] = outp;
    else     *(uint2*)&ko[idx] = outp;
}

// ---------------------------------------------------------------------------
// V: transpose + fp16 convert. grid (SEQ/32, 1024/32), block (32, 8).
// ---------------------------------------------------------------------------
__global__ __launch_bounds__(256) void v_t_h(const float* __restrict__ qkv,
                                             __half* __restrict__ vo) {
    __shared__ float tile[32][33];
    const int tx = threadIdx.x, ty = threadIdx.y;
    const int tok0 = blockIdx.x * 32, c0 = blockIdx.y * 32;
#pragma unroll
    for (int j = ty; j < 32; j += 8)
        tile[j][tx] = qkv[(size_t)(tok0 + j) * QKVD + (QDIM + KVD) + c0 + tx];
    __syncthreads();
#pragma unroll
    for (int j = ty; j < 32; j += 8)
        vo[(size_t)(c0 + j) * SEQ + tok0 + tx] = __float2half_rn(tile[tx][j]);
}

// ---------------------------------------------------------------------------
// fp16 tensor-core flash attention (segmented causal, GQA). 2 CTAs/SM.
// BQ=BKV=64, 4 warps, 2-stage cp.async KV pipeline.
// Epilogue writes O directly in packed fp16 GEMM-A layout.
// ---------------------------------------------------------------------------
#define ATT_SMEM (16384 + 2 * 32768)

__global__ __launch_bounds__(128, 2) void attn_tc(
    const __half* __restrict__ Q, const __half* __restrict__ K,
    const __half* __restrict__ V, __half* __restrict__ O)
{
    extern __shared__ char sma[];
    const uint32_t sb = smem_u32(sma);
    const int tid = threadIdx.x, wid = tid >> 5, lane = tid & 31;
    const int qb = blockIdx.x, seg = blockIdx.y, qh = blockIdx.z;
    const int kvh = qh >> 2;
    const int qtok0 = seg * SEG_LEN + qb * 64;
    const int g = lane >> 3, r = lane & 7;

    const uint32_t Qs = sb;

    {
        const char* src = (const char*)(Q + ((size_t)qh * SEQ + qtok0) * HD);
        for (int i = tid; i < 1024; i += 128) {
            int row = i >> 4, u = i & 15;
            uint32_t off = sw256((uint32_t)(row * 256 + u * 16));
            cp_async16(Qs + off, src + row * 256 + u * 16);
        }
        cp_commit();
    }

    auto issue_kv = [&](int kb, int s) {
        const int kt = seg * SEG_LEN + kb * 64;
        const uint32_t base = sb + 16384 + s * 32768;
        const char* kG = (const char*)(K + ((size_t)kvh * SEQ + kt) * HD);
        for (int i = tid; i < 1024; i += 128) {
            int row = i >> 4, u = i & 15;
            uint32_t off = sw256((uint32_t)(row * 256 + u * 16));
            cp_async16(base + off, kG + row * 256 + u * 16);
        }
        const char* vG = (const char*)V + ((size_t)kvh * HD * SEQ + kt) * 2;
        for (int i = tid; i < 1024; i += 128) {
            int row = i >> 3, u = i & 7;
            uint32_t off = sw128((uint32_t)(row * 128 + u * 16));
            cp_async16(base + 16384 + off, vG + (size_t)row * SEQ * 2 + u * 16);
        }
        cp_commit();
    };

    issue_kv(0, 0);
    if (qb >= 1) issue_kv(1, 1); else cp_commit();

    float m0 = -CUDART_INF_F, m1 = -CUDART_INF_F, l0 = 0.f, l1 = 0.f;
    float o[16][4];
#pragma unroll
    for (int nt = 0; nt < 16; nt++)
#pragma unroll
        for (int j = 0; j < 4; j++) o[nt][j] = 0.f;

    for (int kb = 0; kb <= qb; kb++) {
        const int s = kb & 1;
        cp_wait1();
        __syncthreads();
        const uint32_t Ks = sb + 16384 + s * 32768;
        const uint32_t Vs = Ks + 16384;

        float sa[8][4];
#pragma unroll
        for (int nt = 0; nt < 8; nt++)
#pragma unroll
            for (int j = 0; j < 4; j++) sa[nt][j] = 0.f;

#pragma unroll
        for (int ks = 0; ks < 8; ks++) {
            const int arow = wid * 16 + (g & 1) * 8 + r;
            const uint32_t aoff = sw256((uint32_t)(arow * 256 + (ks * 2 + (g >> 1)) * 16));
            uint32_t af[4];
            ldsm_x4(Qs + aoff, af[0], af[1], af[2], af[3]);
            uint32_t bf[8][2];
#pragma unroll
            for (int p = 0; p < 4; p++) {
                const int nrow = (2 * p + (g >> 1)) * 8 + r;
                const uint32_t boff = sw256((uint32_t)(nrow * 256 + (ks * 2 + (g & 1)) * 16));
                ldsm_x4(Ks + boff, bf[2 * p][0], bf[2 * p][1], bf[2 * p + 1][0], bf[2 * p + 1][1]);
            }
#pragma unroll
            for (int nt = 0; nt < 8; nt++)
                mma_f16(sa[nt], af, bf[nt]);
        }

        if (kb == qb) {
            const int r0 = wid * 16 + (lane >> 2);
#pragma unroll
            for (int nt = 0; nt < 8; nt++) {
                const int c = nt * 8 + (lane & 3) * 2;
                if (c     > r0)     sa[nt][0] = -CUDART_INF_F;
                if (c + 1 > r0)     sa[nt][1] = -CUDART_INF_F;
                if (c     > r0 + 8) sa[nt][2] = -CUDART_INF_F;
                if (c + 1 > r0 + 8) sa[nt][3] = -CUDART_INF_F;
            }
        }

        {
            float mx0 = -CUDART_INF_F, mx1 = -CUDART_INF_F;
#pragma unroll
            for (int nt = 0; nt < 8; nt++) {
                mx0 = fmaxf(mx0, fmaxf(sa[nt][0], sa[nt][1]));
                mx1 = fmaxf(mx1, fmaxf(sa[nt][2], sa[nt][3]));
            }
            mx0 = fmaxf(mx0, __shfl_xor_sync(0xffffffffu, mx0, 1));
            mx0 = fmaxf(mx0, __shfl_xor_sync(0xffffffffu, mx0, 2));
            mx1 = fmaxf(mx1, __shfl_xor_sync(0xffffffffu, mx1, 1));
            mx1 = fmaxf(mx1, __shfl_xor_sync(0xffffffffu, mx1, 2));
            const float mn0 = fmaxf(m0, mx0), mn1 = fmaxf(m1, mx1);
            const float a0 = __expf(m0 - mn0), a1 = __expf(m1 - mn1);
            float sum0 = 0.f, sum1 = 0.f;
#pragma unroll
            for (int nt = 0; nt < 8; nt++) {
                sa[nt][0] = __expf(sa[nt][0] - mn0); sum0 += sa[nt][0];
                sa[nt][1] = __expf(sa[nt][1] - mn0); sum0 += sa[nt][1];
                sa[nt][2] = __expf(sa[nt][2] - mn1); sum1 += sa[nt][2];
                sa[nt][3] = __expf(sa[nt][3] - mn1); sum1 += sa[nt][3];
            }
            sum0 += __shfl_xor_sync(0xffffffffu, sum0, 1);
            sum0 += __shfl_xor_sync(0xffffffffu, sum0, 2);
            sum1 += __shfl_xor_sync(0xffffffffu, sum1, 1);
            sum1 += __shfl_xor_sync(0xffffffffu, sum1, 2);
            l0 = l0 * a0 + sum0;
            l1 = l1 * a1 + sum1;
            m0 = mn0; m1 = mn1;
#pragma unroll
            for (int nt = 0; nt < 16; nt++) {
                o[nt][0] *= a0; o[nt][1] *= a0;
                o[nt][2] *= a1; o[nt][3] *= a1;
            }
        }

#pragma unroll
        for (int kj = 0; kj < 4; kj++) {
            const int t0 = 2 * kj, t1 = t0 + 1;
            uint32_t pf[4];
            pf[0] = h2pack(sa[t0][0], sa[t0][1]);
            pf[1] = h2pack(sa[t0][2], sa[t0][3]);
            pf[2] = h2pack(sa[t1][0], sa[t1][1]);
            pf[3] = h2pack(sa[t1][2], sa[t1][3]);
#pragma unroll
            for (int p = 0; p < 8; p++) {
                const int vrow = (2 * p + (g >> 1)) * 8 + r;
                const uint32_t voff = sw128((uint32_t)(vrow * 128 + (kj * 2 + (g & 1)) * 16));
                uint32_t vf0[2], vf1[2];
                ldsm_x4(Vs + voff, vf0[0], vf0[1], vf1[0], vf1[1]);
                mma_f16(o[2 * p],     pf, vf0);
                mma_f16(o[2 * p + 1], pf, vf1);
            }
        }

        __syncthreads();
        if (kb + 2 <= qb) issue_kv(kb + 2, s); else cp_commit();
    }
    cp_wait0();

    const float li0 = 1.f / l0, li1 = 1.f / l1;
    const int tk0 = qtok0 + wid * 16 + (lane >> 2);
    const int tk1 = tk0 + 8;
#pragma unroll
    for (int nt = 0; nt < 16; nt++) {
        const int d = qh * HD + nt * 8 + (lane & 3) * 2;
        const size_t blk = ((size_t)(tk0 >> 7) * KC + (d >> 5)) * (size_t)(128 * 64);
        const uint32_t col2 = (uint32_t)((d & 31) * 2);
        const uint32_t lo4 = col2 & 15u;
        const uint32_t in0 = sw64((uint32_t)((tk0 & 127) * 64) + (col2 & ~15u)) + lo4;
        const uint32_t in1 = sw64((uint32_t)((tk1 & 127) * 64) + (col2 & ~15u)) + lo4;
        *(uint32_t*)((char*)O + blk + in0) = h2pack(o[nt][0] * li0, o[nt][1] * li0);
        *(uint32_t*)((char*)O + blk + in1) = h2pack(o[nt][2] * li1, o[nt][3] * li1);
    }
}

// ---------------------------------------------------------------------------
// Launch
// ---------------------------------------------------------------------------
extern "C" void kernel_launch(void* const* d_in, const int* in_sizes, int n_in,
                              void* d_out, int out_size) {
    const float* x    = (const float*)d_in[0];
    const float* wq   = (const float*)d_in[1];
    const float* wk   = (const float*)d_in[2];
    const float* wv   = (const float*)d_in[3];
    const float* wo   = (const float*)d_in[4];
    const float* qnw  = (const float*)d_in[5];
    const float* knw  = (const float*)d_in[6];
    const float* rope = (const float*)d_in[7];
    const int*   pos  = (const int*)d_in[8];

    float* qkv;
    cudaGetSymbolAddress((void**)&qkv, g_qkv);
    __half *xh, *oh, *wh, *woh, *qsh, *ksh, *vth;
    cudaGetSymbolAddress((void**)&xh, g_xh);
    cudaGetSymbolAddress((void**)&oh, g_oh);
    cudaGetSymbolAddress((void**)&wh, g_wh);
    cudaGetSymbolAddress((void**)&woh, g_woh);
    cudaGetSymbolAddress((void**)&qsh, g_qsh);
    cudaGetSymbolAddress((void**)&ksh, g_ksh);
    cudaGetSymbolAddress((void**)&vth, g_vth);

    cudaFuncSetAttribute(gemm_tc, cudaFuncAttributeMaxDynamicSharedMemorySize, GEMM_SMEM);
    cudaFuncSetAttribute(attn_tc, cudaFuncAttributeMaxDynamicSharedMemorySize, ATT_SMEM);

    // One fused pack for all inputs: 1536 row-groups x 64 k-pairs = 98304 warps
    {
        int nW = ((SEQ + QDIM + KVD + KVD + DIM) / 8) * (KC / 2);
        pack_all<<<(nW * 32 + 255) / 256, 256>>>(x, wq, wk, wv, wo, xh, wh, woh);
    }

    // Fused QKV projection (grid 48 x 16)
    gemm_tc<<<dim3(QKVD / BN, SEQ / BM), 256, GEMM_SMEM>>>(xh, wh, qkv, QKVD);

    // Warp-per-head RMSNorm + RoPE + convert; V transpose + convert
    {
        int nW = SEQ * (NQH + NKVH);   // 81920 warps
        rmsnorm_rope_h<<<(nW * 32 + 255) / 256, 256>>>(qkv, qnw, knw, rope, pos, qsh, ksh);
    }
    v_t_h<<<dim3(SEQ / 32, KVD / 32), dim3(32, 8)>>>(qkv, vth);

    // Tensor-core attention (writes packed O)
    attn_tc<<<dim3(SEG_LEN / 64, N_SEG, NQH), 128, ATT_SMEM>>>(qsh, ksh, vth, oh);

    // Output projection (grid 32 x 16)
    gemm_tc<<<dim3(DIM / BN, SEQ / BM), 256, GEMM_SMEM>>>(oh, woh, (float*)d_out, DIM);
}

// round 12
// speedup vs baseline: 9.9935x; 1.0018x over previous
#include <cuda_runtime.h>
#include <cuda_fp16.h>
#include <math_constants.h>
#include <cstdint>

// ---------------------------------------------------------------------------
// Problem constants
// ---------------------------------------------------------------------------
#define SEQ      2048
#define DIM      4096
#define NQH      32
#define NKVH     8
#define HD       128
#define SEG_LEN  512
#define N_SEG    4
#define QDIM     (NQH * HD)    // 4096
#define KVD      (NKVH * HD)   // 1024
#define QKVD     6144
#define KC       (DIM / 32)    // 128 k-chunks

// fp32 scratch (fused qkv projection output)
__device__ float g_qkv[SEQ * QKVD];

// packed + swizzled fp16 GEMM operands (128-row blocks)
__device__ __half g_xh[SEQ * DIM];       // A-layout
__device__ __half g_oh[SEQ * QDIM];      // A-layout (written by attention)
__device__ __half g_wh[QKVD * DIM];      // B-layout wq|wk|wv
__device__ __half g_woh[DIM * QDIM];     // B-layout

// attention operands (fp16)
__device__ __half g_qsh[NQH * SEQ * HD];    // [qh][tok][d]  (pre-scaled)
__device__ __half g_ksh[NKVH * SEQ * HD];   // [kvh][tok][d]
__device__ __half g_vth[NKVH * HD * SEQ];   // [kvh*128+d][tok]

// ---------------------------------------------------------------------------
// PTX helpers
// ---------------------------------------------------------------------------
__device__ __forceinline__ uint32_t smem_u32(const void* p) {
    uint32_t a;
    asm("{ .reg .u64 t; cvta.to.shared.u64 t, %1; cvt.u32.u64 %0, t; }" : "=r"(a) : "l"(p));
    return a;
}
__device__ __forceinline__ void mbar_init(uint32_t addr, uint32_t cnt) {
    asm volatile("mbarrier.init.shared.b64 [%0], %1;" :: "r"(addr), "r"(cnt) : "memory");
}
__device__ __forceinline__ void fence_proxy_async() {
    asm volatile("fence.proxy.async.shared::cta;" ::: "memory");
}
__device__ __forceinline__ void mbar_expect_tx(uint32_t addr, uint32_t bytes) {
    asm volatile("mbarrier.arrive.expect_tx.shared.b64 _, [%0], %1;" :: "r"(addr), "r"(bytes) : "memory");
}
__device__ __forceinline__ void mbar_wait(uint32_t addr, uint32_t parity) {
    uint32_t done;
    asm volatile("{\n\t.reg .pred p;\n\t"
                 "mbarrier.try_wait.parity.acquire.cta.shared::cta.b64 p, [%1], %2;\n\t"
                 "selp.b32 %0, 1, 0, p;\n\t}"
                 : "=r"(done) : "r"(addr), "r"(parity) : "memory");
    if (!done) {
        asm volatile("{\n\t.reg .pred P1;\n\t"
                     "W_%=:\n\t"
                     "mbarrier.try_wait.parity.acquire.cta.shared::cta.b64 P1, [%0], %1, 0x989680;\n\t"
                     "@P1 bra.uni D_%=;\n\t"
                     "bra.uni W_%=;\n\t"
                     "D_%=:\n\t}"
                     :: "r"(addr), "r"(parity) : "memory");
    }
}
__device__ __forceinline__ void bulk_g2s(uint32_t dst, const void* src, uint32_t bytes, uint32_t mbar) {
    asm volatile("cp.async.bulk.shared::cluster.global.mbarrier::complete_tx::bytes [%0], [%1], %2, [%3];"
                 :: "r"(dst), "l"(src), "r"(bytes), "r"(mbar) : "memory");
}
__device__ __forceinline__ void cp_async16(uint32_t dst, const void* src) {
    asm volatile("cp.async.cg.shared.global [%0], [%1], 16;" :: "r"(dst), "l"(src) : "memory");
}
__device__ __forceinline__ void cp_commit() { asm volatile("cp.async.commit_group;" ::: "memory"); }
__device__ __forceinline__ void cp_wait1()  { asm volatile("cp.async.wait_group 1;" ::: "memory"); }
__device__ __forceinline__ void cp_wait0()  { asm volatile("cp.async.wait_group 0;" ::: "memory"); }
__device__ __forceinline__ void ldsm_x4(uint32_t addr, uint32_t& r0, uint32_t& r1,
                                        uint32_t& r2, uint32_t& r3) {
    asm volatile("ldmatrix.sync.aligned.m8n8.x4.shared.b16 {%0,%1,%2,%3}, [%4];"
                 : "=r"(r0), "=r"(r1), "=r"(r2), "=r"(r3) : "r"(addr));
}
__device__ __forceinline__ void mma_f16(float* d, const uint32_t* a, const uint32_t* b) {
    asm volatile("mma.sync.aligned.m16n8k16.row.col.f32.f16.f16.f32 "
                 "{%0,%1,%2,%3}, {%4,%5,%6,%7}, {%8,%9}, {%0,%1,%2,%3};"
                 : "+f"(d[0]), "+f"(d[1]), "+f"(d[2]), "+f"(d[3])
                 : "r"(a[0]), "r"(a[1]), "r"(a[2]), "r"(a[3]), "r"(b[0]), "r"(b[1]));
}
__device__ __forceinline__ uint32_t sw64(uint32_t off)  { return off ^ ((off >> 3) & 0x30); }
__device__ __forceinline__ uint32_t sw128(uint32_t off) { return off ^ ((off >> 3) & 0x70); }
__device__ __forceinline__ uint32_t sw256(uint32_t off) { return off ^ ((off >> 4) & 0x70); }

__device__ __forceinline__ uint32_t h2pack(float x, float y) {
    __half hx = __float2half_rn(x), hy = __float2half_rn(y);
    return (uint32_t)*(unsigned short*)&hx | ((uint32_t)*(unsigned short*)&hy << 16);
}

// ---------------------------------------------------------------------------
// Fused pack: x | wq | wk | wv | wo. One warp: 8 rows x 4 k-chunks.
// ---------------------------------------------------------------------------
__global__ __launch_bounds__(256) void pack_all(const float* __restrict__ x,
                                                const float* __restrict__ wq,
                                                const float* __restrict__ wk,
                                                const float* __restrict__ wv,
                                                const float* __restrict__ wo,
                                                __half* __restrict__ xh,
                                                __half* __restrict__ wh,
                                                __half* __restrict__ woh) {
    const int w = (blockIdx.x * 256 + threadIdx.x) >> 5;
    const int lane = threadIdx.x & 31;
    const int rg = w >> 5, kp = w & 31;
    const float* src;
    __half* dst;
    int rgl;
    if (rg < 256)       { src = x;  dst = xh;                              rgl = rg; }
    else if (rg < 768)  { src = wq; dst = wh;                              rgl = rg - 256; }
    else if (rg < 896)  { src = wk; dst = wh + (size_t)QDIM * DIM;         rgl = rg - 768; }
    else if (rg < 1024) { src = wv; dst = wh + (size_t)(QDIM + KVD) * DIM; rgl = rg - 896; }
    else                { src = wo; dst = woh;                             rgl = rg - 1024; }

    const int r = rgl * 8 + (lane >> 2);
    const int kq = lane & 3;
    const int rt = r >> 7, row = r & 127;
    const uint32_t sw = sw64((uint32_t)(row * 64 + kq * 16));

    float4 v0[4], v1[4];
#pragma unroll
    for (int j = 0; j < 4; j++) {
        const int kc = kp * 4 + j;
        v0[j] = *(const float4*)&src[(size_t)r * DIM + kc * 32 + kq * 8];
        v1[j] = *(const float4*)&src[(size_t)r * DIM + kc * 32 + kq * 8 + 4];
    }
#pragma unroll
    for (int j = 0; j < 4; j++) {
        const int kc = kp * 4 + j;
        uint4 pk;
        pk.x = h2pack(v0[j].x, v0[j].y);
        pk.y = h2pack(v0[j].z, v0[j].w);
        pk.z = h2pack(v1[j].x, v1[j].y);
        pk.w = h2pack(v1[j].z, v1[j].w);
        const size_t blk = ((size_t)rt * KC + kc) * (size_t)(128 * 64);
        *(uint4*)((char*)dst + blk + sw) = pk;
    }
}

// ---------------------------------------------------------------------------
// fp16 tensor-core GEMM (R9-proven), bulk-async, 6-stage, 2 CTAs/SM.
// CTA tile 128x128, BK=32, 8 warps (2x4) of 64x32. Plain fp32 store.
// ---------------------------------------------------------------------------
#define BM 128
#define BN 128
#define ABLK 8192
#define BBLK 8192
#define STG (ABLK + BBLK)
#define NST 6
#define GEMM_SMEM (NST * STG)     // 98304

__global__ __launch_bounds__(256, 2) void gemm_tc(
    const __half* __restrict__ A, const __half* __restrict__ B,
    float* __restrict__ C, int N)
{
    extern __shared__ char smg[];
    __shared__ uint64_t s_mbar[NST];

    const uint32_t sbase = smem_u32(smg);
    const int tid = threadIdx.x;
    const int wid = tid >> 5;
    const int lane = tid & 31;
    const int wm = wid & 1;
    const int wn = wid >> 1;
    const int bmb = blockIdx.y;
    const int bnb = blockIdx.x;

    uint32_t mb[NST];
#pragma unroll
    for (int i = 0; i < NST; i++) mb[i] = smem_u32(&s_mbar[i]);

    if (tid == 0) {
        for (int i = 0; i < NST; i++) mbar_init(mb[i], 1);
        fence_proxy_async();
    }
    __syncthreads();

    const char* aG = (const char*)A + (size_t)bmb * KC * ABLK;
    const char* bG = (const char*)B + (size_t)bnb * KC * BBLK;

    auto issue = [&](int c, int s) {
        const uint32_t d = sbase + s * STG;
        mbar_expect_tx(mb[s], STG);
        bulk_g2s(d,        aG + (size_t)c * ABLK, ABLK, mb[s]);
        bulk_g2s(d + ABLK, bG + (size_t)c * BBLK, BBLK, mb[s]);
    };

    if (tid == 0)
        for (int i = 0; i < NST; i++) issue(i, i);

    float acc[4][4][4];
#pragma unroll
    for (int mt = 0; mt < 4; mt++)
#pragma unroll
        for (int nt = 0; nt < 4; nt++)
#pragma unroll
            for (int j = 0; j < 4; j++) acc[mt][nt][j] = 0.f;

    const int g = lane >> 3, r = lane & 7;

    for (int c = 0; c < KC; c++) {
        const int s = c % NST;
        mbar_wait(mb[s], (c / NST) & 1);

        const uint32_t aS = sbase + s * STG;
        const uint32_t bS = aS + ABLK;

#pragma unroll
        for (int ks = 0; ks < 2; ks++) {
            uint32_t bf[4][2];
#pragma unroll
            for (int p = 0; p < 2; p++) {
                const int nt = 2 * p + (g >> 1);
                const uint32_t a = sw64((uint32_t)((wn * 32 + nt * 8 + r) * 64 + ks * 32 + (g & 1) * 16));
                ldsm_x4(bS + a, bf[2 * p][0], bf[2 * p][1], bf[2 * p + 1][0], bf[2 * p + 1][1]);
            }
#pragma unroll
            for (int mt = 0; mt < 4; mt++) {
                const uint32_t a = sw64((uint32_t)((wm * 64 + mt * 16 + (g & 1) * 8 + r) * 64 + ks * 32 + (g >> 1) * 16));
                uint32_t af[4];
                ldsm_x4(aS + a, af[0], af[1], af[2], af[3]);
#pragma unroll
                for (int nt = 0; nt < 4; nt++)
                    mma_f16(acc[mt][nt], af, bf[nt]);
            }
        }
        __syncthreads();
        if (tid == 0 && c + NST < KC) issue(c + NST, s);
    }

    const int er = lane >> 2, ec = (lane & 3) * 2;
#pragma unroll
    for (int mt = 0; mt < 4; mt++) {
#pragma unroll
        for (int nt = 0; nt < 4; nt++) {
            const int row = bmb * BM + wm * 64 + mt * 16 + er;
            const int col = bnb * BN + wn * 32 + nt * 8 + ec;
            *(float2*)&C[(size_t)row * N + col]       = make_float2(acc[mt][nt][0], acc[mt][nt][1]);
            *(float2*)&C[(size_t)(row + 8) * N + col] = make_float2(acc[mt][nt][2], acc[mt][nt][3]);
        }
    }
}

// ---------------------------------------------------------------------------
// Warp-per-head RMSNorm + RoPE + scale + fp16 convert (R9-proven).
// Global warp w -> (tok = w/40, h = w%40). Stride QKVD.
// ---------------------------------------------------------------------------
__global__ __launch_bounds__(256) void rmsnorm_rope_h(
    const float* __restrict__ qkv,
    const float* __restrict__ qnw, const float* __restrict__ knw,
    const float* __restrict__ rope, const int* __restrict__ pos,
    __half* __restrict__ qo, __half* __restrict__ ko)
{
    const int w = (blockIdx.x * 256 + threadIdx.x) >> 5;
    const int lane = threadIdx.x & 31;
    const int tok = w / (NQH + NKVH);
    const int h = w % (NQH + NKVH);
    const bool isQ = h < NQH;
    const int colbase = isQ ? h * HD : QDIM + (h - NQH) * HD;

    const float4 v = *(const float4*)&qkv[(size_t)tok * QKVD + colbase + lane * 4];

    float ss = v.x * v.x + v.y * v.y + v.z * v.z + v.w * v.w;
#pragma unroll
    for (int off = 16; off; off >>= 1) ss += __shfl_xor_sync(0xffffffffu, ss, off);
    const float inv = rsqrtf(ss * (1.0f / HD) + 1e-6f);

    const float4 wt = *(const float4*)&(isQ ? qnw : knw)[lane * 4];
    float n0 = v.x * inv * wt.x, n1 = v.y * inv * wt.y;
    float n2 = v.z * inv * wt.z, n3 = v.w * inv * wt.w;

    const float p0 = __shfl_xor_sync(0xffffffffu, n0, 16);
    const float p1 = __shfl_xor_sync(0xffffffffu, n1, 16);
    const float p2 = __shfl_xor_sync(0xffffffffu, n2, 16);
    const float p3 = __shfl_xor_sync(0xffffffffu, n3, 16);

    const int pp = pos[tok];
    const int f = (lane & 15) * 4;
    const float4 cs0 = *(const float4*)&rope[(size_t)(pp * 64 + f) * 2];
    const float4 cs1 = *(const float4*)&rope[(size_t)(pp * 64 + f) * 2 + 4];

    float o0, o1, o2, o3;
    if (lane < 16) {
        o0 = n0 * cs0.x - p0 * cs0.y;
        o1 = n1 * cs0.z - p1 * cs0.w;
        o2 = n2 * cs1.x - p2 * cs1.y;
        o3 = n3 * cs1.z - p3 * cs1.w;
    } else {
        o0 = n0 * cs0.x + p0 * cs0.y;
        o1 = n1 * cs0.z + p1 * cs0.w;
        o2 = n2 * cs1.x + p2 * cs1.y;
        o3 = n3 * cs1.z + p3 * cs1.w;
    }
    if (isQ) {
        const float sc = 0.08838834764831845f;
        o0 *= sc; o1 *= sc; o2 *= sc; o3 *= sc;
    }

    uint2 outp = make_uint2(h2pack(o0, o1), h2pack(o2, o3));
    const size_t idx = isQ ? ((size_t)h * SEQ + tok) * HD + lane * 4
                           : ((size_t)(h - NQH) * SEQ + tok) * HD + lane * 4;
    if (isQ) *(uint2*)&qo[idx] = outp;
    else     *(uint2*)&ko[idx] = outp;
}

// ---------------------------------------------------------------------------
// V: transpose + fp16 convert (R9-proven). grid (SEQ/32, 1024/32), block (32,8).
// ---------------------------------------------------------------------------
__global__ __launch_bounds__(256) void v_t_h(const float* __restrict__ qkv,
                                             __half* __restrict__ vo) {
    __shared__ float tile[32][33];
    const int tx = threadIdx.x, ty = threadIdx.y;
    const int tok0 = blockIdx.x * 32, c0 = blockIdx.y * 32;
#pragma unroll
    for (int j = ty; j < 32; j += 8)
        tile[j][tx] = qkv[(size_t)(tok0 + j) * QKVD + (QDIM + KVD) + c0 + tx];
    __syncthreads();
#pragma unroll
    for (int j = ty; j < 32; j += 8)
        vo[(size_t)(c0 + j) * SEQ + tok0 + tx] = __float2half_rn(tile[tx][j]);
}

// ---------------------------------------------------------------------------
// fp16 tensor-core flash attention (R9-proven core), 2 CTAs/SM, reversed qb.
// BQ=BKV=64, 4 warps, 2-stage cp.async KV pipeline.
// Epilogue writes O in packed fp16 GEMM-A layout.
// ---------------------------------------------------------------------------
#define ATT_SMEM (16384 + 2 * 32768)

__global__ __launch_bounds__(128, 2) void attn_tc(
    const __half* __restrict__ Q, const __half* __restrict__ K,
    const __half* __restrict__ V, __half* __restrict__ O)
{
    extern __shared__ char sma[];
    const uint32_t sb = smem_u32(sma);
    const int tid = threadIdx.x, wid = tid >> 5, lane = tid & 31;
    const int qb = (SEG_LEN / 64 - 1) - blockIdx.x;   // heavy CTAs first
    const int seg = blockIdx.y, qh = blockIdx.z;
    const int kvh = qh >> 2;
    const int qtok0 = seg * SEG_LEN + qb * 64;
    const int g = lane >> 3, r = lane & 7;

    const uint32_t Qs = sb;

    {
        const char* src = (const char*)(Q + ((size_t)qh * SEQ + qtok0) * HD);
        for (int i = tid; i < 1024; i += 128) {
            int row = i >> 4, u = i & 15;
            uint32_t off = sw256((uint32_t)(row * 256 + u * 16));
            cp_async16(Qs + off, src + row * 256 + u * 16);
        }
        cp_commit();
    }

    auto issue_kv = [&](int kb, int s) {
        const int kt = seg * SEG_LEN + kb * 64;
        const uint32_t base = sb + 16384 + s * 32768;
        const char* kG = (const char*)(K + ((size_t)kvh * SEQ + kt) * HD);
        for (int i = tid; i < 1024; i += 128) {
            int row = i >> 4, u = i & 15;
            uint32_t off = sw256((uint32_t)(row * 256 + u * 16));
            cp_async16(base + off, kG + row * 256 + u * 16);
        }
        const char* vG = (const char*)V + ((size_t)kvh * HD * SEQ + kt) * 2;
        for (int i = tid; i < 1024; i += 128) {
            int row = i >> 3, u = i & 7;
            uint32_t off = sw128((uint32_t)(row * 128 + u * 16));
            cp_async16(base + 16384 + off, vG + (size_t)row * SEQ * 2 + u * 16);
        }
        cp_commit();
    };

    issue_kv(0, 0);
    if (qb >= 1) issue_kv(1, 1); else cp_commit();

    float m0 = -CUDART_INF_F, m1 = -CUDART_INF_F, l0 = 0.f, l1 = 0.f;
    float o[16][4];
#pragma unroll
    for (int nt = 0; nt < 16; nt++)
#pragma unroll
        for (int j = 0; j < 4; j++) o[nt][j] = 0.f;

    for (int kb = 0; kb <= qb; kb++) {
        const int s = kb & 1;
        cp_wait1();
        __syncthreads();
        const uint32_t Ks = sb + 16384 + s * 32768;
        const uint32_t Vs = Ks + 16384;

        float sa[8][4];
#pragma unroll
        for (int nt = 0; nt < 8; nt++)
#pragma unroll
            for (int j = 0; j < 4; j++) sa[nt][j] = 0.f;

#pragma unroll
        for (int ks = 0; ks < 8; ks++) {
            const int arow = wid * 16 + (g & 1) * 8 + r;
            const uint32_t aoff = sw256((uint32_t)(arow * 256 + (ks * 2 + (g >> 1)) * 16));
            uint32_t af[4];
            ldsm_x4(Qs + aoff, af[0], af[1], af[2], af[3]);
            uint32_t bf[8][2];
#pragma unroll
            for (int p = 0; p < 4; p++) {
                const int nrow = (2 * p + (g >> 1)) * 8 + r;
                const uint32_t boff = sw256((uint32_t)(nrow * 256 + (ks * 2 + (g & 1)) * 16));
                ldsm_x4(Ks + boff, bf[2 * p][0], bf[2 * p][1], bf[2 * p + 1][0], bf[2 * p + 1][1]);
            }
#pragma unroll
            for (int nt = 0; nt < 8; nt++)
                mma_f16(sa[nt], af, bf[nt]);
        }

        if (kb == qb) {
            const int r0 = wid * 16 + (lane >> 2);
#pragma unroll
            for (int nt = 0; nt < 8; nt++) {
                const int c = nt * 8 + (lane & 3) * 2;
                if (c     > r0)     sa[nt][0] = -CUDART_INF_F;
                if (c + 1 > r0)     sa[nt][1] = -CUDART_INF_F;
                if (c     > r0 + 8) sa[nt][2] = -CUDART_INF_F;
                if (c + 1 > r0 + 8) sa[nt][3] = -CUDART_INF_F;
            }
        }

        {
            float mx0 = -CUDART_INF_F, mx1 = -CUDART_INF_F;
#pragma unroll
            for (int nt = 0; nt < 8; nt++) {
                mx0 = fmaxf(mx0, fmaxf(sa[nt][0], sa[nt][1]));
                mx1 = fmaxf(mx1, fmaxf(sa[nt][2], sa[nt][3]));
            }
            mx0 = fmaxf(mx0, __shfl_xor_sync(0xffffffffu, mx0, 1));
            mx0 = fmaxf(mx0, __shfl_xor_sync(0xffffffffu, mx0, 2));
            mx1 = fmaxf(mx1, __shfl_xor_sync(0xffffffffu, mx1, 1));
            mx1 = fmaxf(mx1, __shfl_xor_sync(0xffffffffu, mx1, 2));
            const float mn0 = fmaxf(m0, mx0), mn1 = fmaxf(m1, mx1);
            const float a0 = __expf(m0 - mn0), a1 = __expf(m1 - mn1);
            float sum0 = 0.f, sum1 = 0.f;
#pragma unroll
            for (int nt = 0; nt < 8; nt++) {
                sa[nt][0] = __expf(sa[nt][0] - mn0); sum0 += sa[nt][0];
                sa[nt][1] = __expf(sa[nt][1] - mn0); sum0 += sa[nt][1];
                sa[nt][2] = __expf(sa[nt][2] - mn1); sum1 += sa[nt][2];
                sa[nt][3] = __expf(sa[nt][3] - mn1); sum1 += sa[nt][3];
            }
            sum0 += __shfl_xor_sync(0xffffffffu, sum0, 1);
            sum0 += __shfl_xor_sync(0xffffffffu, sum0, 2);
            sum1 += __shfl_xor_sync(0xffffffffu, sum1, 1);
            sum1 += __shfl_xor_sync(0xffffffffu, sum1, 2);
            l0 = l0 * a0 + sum0;
            l1 = l1 * a1 + sum1;
            m0 = mn0; m1 = mn1;
#pragma unroll
            for (int nt = 0; nt < 16; nt++) {
                o[nt][0] *= a0; o[nt][1] *= a0;
                o[nt][2] *= a1; o[nt][3] *= a1;
            }
        }

#pragma unroll
        for (int kj = 0; kj < 4; kj++) {
            const int t0 = 2 * kj, t1 = t0 + 1;
            uint32_t pf[4];
            pf[0] = h2pack(sa[t0][0], sa[t0][1]);
            pf[1] = h2pack(sa[t0][2], sa[t0][3]);
            pf[2] = h2pack(sa[t1][0], sa[t1][1]);
            pf[3] = h2pack(sa[t1][2], sa[t1][3]);
#pragma unroll
            for (int p = 0; p < 8; p++) {
                const int vrow = (2 * p + (g >> 1)) * 8 + r;
                const uint32_t voff = sw128((uint32_t)(vrow * 128 + (kj * 2 + (g & 1)) * 16));
                uint32_t vf0[2], vf1[2];
                ldsm_x4(Vs + voff, vf0[0], vf0[1], vf1[0], vf1[1]);
                mma_f16(o[2 * p],     pf, vf0);
                mma_f16(o[2 * p + 1], pf, vf1);
            }
        }

        __syncthreads();
        if (kb + 2 <= qb) issue_kv(kb + 2, s); else cp_commit();
    }
    cp_wait0();

    const float li0 = 1.f / l0, li1 = 1.f / l1;
    const int tk0 = qtok0 + wid * 16 + (lane >> 2);
    const int tk1 = tk0 + 8;
#pragma unroll
    for (int nt = 0; nt < 16; nt++) {
        const int d = qh * HD + nt * 8 + (lane & 3) * 2;
        const size_t blk = ((size_t)(tk0 >> 7) * KC + (d >> 5)) * (size_t)(128 * 64);
        const uint32_t col2 = (uint32_t)((d & 31) * 2);
        const uint32_t lo4 = col2 & 15u;
        const uint32_t in0 = sw64((uint32_t)((tk0 & 127) * 64) + (col2 & ~15u)) + lo4;
        const uint32_t in1 = sw64((uint32_t)((tk1 & 127) * 64) + (col2 & ~15u)) + lo4;
        *(uint32_t*)((char*)O + blk + in0) = h2pack(o[nt][0] * li0, o[nt][1] * li0);
        *(uint32_t*)((char*)O + blk + in1) = h2pack(o[nt][2] * li1, o[nt][3] * li1);
    }
}

// ---------------------------------------------------------------------------
// Launch
// ---------------------------------------------------------------------------
extern "C" void kernel_launch(void* const* d_in, const int* in_sizes, int n_in,
                              void* d_out, int out_size) {
    const float* x    = (const float*)d_in[0];
    const float* wq   = (const float*)d_in[1];
    const float* wk   = (const float*)d_in[2];
    const float* wv   = (const float*)d_in[3];
    const float* wo   = (const float*)d_in[4];
    const float* qnw  = (const float*)d_in[5];
    const float* knw  = (const float*)d_in[6];
    const float* rope = (const float*)d_in[7];
    const int*   pos  = (const int*)d_in[8];

    float* qkv;
    cudaGetSymbolAddress((void**)&qkv, g_qkv);
    __half *xh, *oh, *wh, *woh, *qsh, *ksh, *vth;
    cudaGetSymbolAddress((void**)&xh, g_xh);
    cudaGetSymbolAddress((void**)&oh, g_oh);
    cudaGetSymbolAddress((void**)&wh, g_wh);
    cudaGetSymbolAddress((void**)&woh, g_woh);
    cudaGetSymbolAddress((void**)&qsh, g_qsh);
    cudaGetSymbolAddress((void**)&ksh, g_ksh);
    cudaGetSymbolAddress((void**)&vth, g_vth);

    cudaFuncSetAttribute(gemm_tc, cudaFuncAttributeMaxDynamicSharedMemorySize, GEMM_SMEM);
    cudaFuncSetAttribute(attn_tc, cudaFuncAttributeMaxDynamicSharedMemorySize, ATT_SMEM);

    // Fused pack
    {
        int nW = ((SEQ + QDIM + KVD + KVD + DIM) / 8) * (KC / 4);
        pack_all<<<(nW * 32 + 255) / 256, 256>>>(x, wq, wk, wv, wo, xh, wh, woh);
    }

    // Fused QKV projection (fp32 out)
    gemm_tc<<<dim3(QKVD / BN, SEQ / BM), 256, GEMM_SMEM>>>(xh, wh, qkv, QKVD);

    // RMSNorm + RoPE + convert; V transpose + convert
    {
        int nW = SEQ * (NQH + NKVH);
        rmsnorm_rope_h<<<(nW * 32 + 255) / 256, 256>>>(qkv, qnw, knw, rope, pos, qsh, ksh);
    }
    v_t_h<<<dim3(SEQ / 32, KVD / 32), dim3(32, 8)>>>(qkv, vth);

    // Attention (writes packed O)
    attn_tc<<<dim3(SEG_LEN / 64, N_SEG, NQH), 128, ATT_SMEM>>>(qsh, ksh, vth, oh);

    // Output projection
    gemm_tc<<<dim3(DIM / BN, SEQ / BM), 256, GEMM_SMEM>>>(oh, woh, (float*)d_out, DIM);
}

// round 13
// speedup vs baseline: 10.1484x; 1.0155x over previous
#include <cuda_runtime.h>
#include <cuda_fp16.h>
#include <math_constants.h>
#include <cstdint>

// ---------------------------------------------------------------------------
// Problem constants
// ---------------------------------------------------------------------------
#define SEQ      2048
#define DIM      4096
#define NQH      32
#define NKVH     8
#define HD       128
#define SEG_LEN  512
#define N_SEG    4
#define QDIM     (NQH * HD)    // 4096
#define KVD      (NKVH * HD)   // 1024
#define QKVD     6144
#define KC       (DIM / 32)    // 128 k-chunks

// fp32 scratch (fused qkv projection output)
__device__ float g_qkv[SEQ * QKVD];

// packed + swizzled fp16 GEMM operands (128-row blocks)
__device__ __half g_xh[SEQ * DIM];       // A-layout
__device__ __half g_oh[SEQ * QDIM];      // A-layout (written by attention)
__device__ __half g_wh[QKVD * DIM];      // B-layout wq|wk|wv
__device__ __half g_woh[DIM * QDIM];     // B-layout

// attention operands (fp16)
__device__ __half g_qsh[NQH * SEQ * HD];    // [qh][tok][d]  (pre-scaled)
__device__ __half g_ksh[NKVH * SEQ * HD];   // [kvh][tok][d]
__device__ __half g_vth[NKVH * HD * SEQ];   // [kvh*128+d][tok]

// ---------------------------------------------------------------------------
// PTX helpers
// ---------------------------------------------------------------------------
__device__ __forceinline__ uint32_t smem_u32(const void* p) {
    uint32_t a;
    asm("{ .reg .u64 t; cvta.to.shared.u64 t, %1; cvt.u32.u64 %0, t; }" : "=r"(a) : "l"(p));
    return a;
}
__device__ __forceinline__ void mbar_init(uint32_t addr, uint32_t cnt) {
    asm volatile("mbarrier.init.shared.b64 [%0], %1;" :: "r"(addr), "r"(cnt) : "memory");
}
__device__ __forceinline__ void fence_proxy_async() {
    asm volatile("fence.proxy.async.shared::cta;" ::: "memory");
}
__device__ __forceinline__ void mbar_expect_tx(uint32_t addr, uint32_t bytes) {
    asm volatile("mbarrier.arrive.expect_tx.shared.b64 _, [%0], %1;" :: "r"(addr), "r"(bytes) : "memory");
}
__device__ __forceinline__ void mbar_wait(uint32_t addr, uint32_t parity) {
    uint32_t done;
    asm volatile("{\n\t.reg .pred p;\n\t"
                 "mbarrier.try_wait.parity.acquire.cta.shared::cta.b64 p, [%1], %2;\n\t"
                 "selp.b32 %0, 1, 0, p;\n\t}"
                 : "=r"(done) : "r"(addr), "r"(parity) : "memory");
    if (!done) {
        asm volatile("{\n\t.reg .pred P1;\n\t"
                     "W_%=:\n\t"
                     "mbarrier.try_wait.parity.acquire.cta.shared::cta.b64 P1, [%0], %1, 0x989680;\n\t"
                     "@P1 bra.uni D_%=;\n\t"
                     "bra.uni W_%=;\n\t"
                     "D_%=:\n\t}"
                     :: "r"(addr), "r"(parity) : "memory");
    }
}
__device__ __forceinline__ void bulk_g2s(uint32_t dst, const void* src, uint32_t bytes, uint32_t mbar) {
    asm volatile("cp.async.bulk.shared::cluster.global.mbarrier::complete_tx::bytes [%0], [%1], %2, [%3];"
                 :: "r"(dst), "l"(src), "r"(bytes), "r"(mbar) : "memory");
}
__device__ __forceinline__ void cp_async16(uint32_t dst, const void* src) {
    asm volatile("cp.async.cg.shared.global [%0], [%1], 16;" :: "r"(dst), "l"(src) : "memory");
}
__device__ __forceinline__ void cp_commit() { asm volatile("cp.async.commit_group;" ::: "memory"); }
__device__ __forceinline__ void cp_wait1()  { asm volatile("cp.async.wait_group 1;" ::: "memory"); }
__device__ __forceinline__ void cp_wait0()  { asm volatile("cp.async.wait_group 0;" ::: "memory"); }
__device__ __forceinline__ void ldsm_x4(uint32_t addr, uint32_t& r0, uint32_t& r1,
                                        uint32_t& r2, uint32_t& r3) {
    asm volatile("ldmatrix.sync.aligned.m8n8.x4.shared.b16 {%0,%1,%2,%3}, [%4];"
                 : "=r"(r0), "=r"(r1), "=r"(r2), "=r"(r3) : "r"(addr));
}
__device__ __forceinline__ void mma_f16(float* d, const uint32_t* a, const uint32_t* b) {
    asm volatile("mma.sync.aligned.m16n8k16.row.col.f32.f16.f16.f32 "
                 "{%0,%1,%2,%3}, {%4,%5,%6,%7}, {%8,%9}, {%0,%1,%2,%3};"
                 : "+f"(d[0]), "+f"(d[1]), "+f"(d[2]), "+f"(d[3])
                 : "r"(a[0]), "r"(a[1]), "r"(a[2]), "r"(a[3]), "r"(b[0]), "r"(b[1]));
}
__device__ __forceinline__ uint32_t sw64(uint32_t off)  { return off ^ ((off >> 3) & 0x30); }
__device__ __forceinline__ uint32_t sw128(uint32_t off) { return off ^ ((off >> 3) & 0x70); }
__device__ __forceinline__ uint32_t sw256(uint32_t off) { return off ^ ((off >> 4) & 0x70); }

__device__ __forceinline__ uint32_t h2pack(float x, float y) {
    __half hx = __float2half_rn(x), hy = __float2half_rn(y);
    return (uint32_t)*(unsigned short*)&hx | ((uint32_t)*(unsigned short*)&hy << 16);
}

// ---------------------------------------------------------------------------
// Fused pack: x | wq | wk | wv | wo. One warp: 8 rows x 4 k-chunks.
// ---------------------------------------------------------------------------
__global__ __launch_bounds__(256) void pack_all(const float* __restrict__ x,
                                                const float* __restrict__ wq,
                                                const float* __restrict__ wk,
                                                const float* __restrict__ wv,
                                                const float* __restrict__ wo,
                                                __half* __restrict__ xh,
                                                __half* __restrict__ wh,
                                                __half* __restrict__ woh) {
    const int w = (blockIdx.x * 256 + threadIdx.x) >> 5;
    const int lane = threadIdx.x & 31;
    const int rg = w >> 5, kp = w & 31;
    const float* src;
    __half* dst;
    int rgl;
    if (rg < 256)       { src = x;  dst = xh;                              rgl = rg; }
    else if (rg < 768)  { src = wq; dst = wh;                              rgl = rg - 256; }
    else if (rg < 896)  { src = wk; dst = wh + (size_t)QDIM * DIM;         rgl = rg - 768; }
    else if (rg < 1024) { src = wv; dst = wh + (size_t)(QDIM + KVD) * DIM; rgl = rg - 896; }
    else                { src = wo; dst = woh;                             rgl = rg - 1024; }

    const int r = rgl * 8 + (lane >> 2);
    const int kq = lane & 3;
    const int rt = r >> 7, row = r & 127;
    const uint32_t sw = sw64((uint32_t)(row * 64 + kq * 16));

    float4 v0[4], v1[4];
#pragma unroll
    for (int j = 0; j < 4; j++) {
        const int kc = kp * 4 + j;
        v0[j] = *(const float4*)&src[(size_t)r * DIM + kc * 32 + kq * 8];
        v1[j] = *(const float4*)&src[(size_t)r * DIM + kc * 32 + kq * 8 + 4];
    }
#pragma unroll
    for (int j = 0; j < 4; j++) {
        const int kc = kp * 4 + j;
        uint4 pk;
        pk.x = h2pack(v0[j].x, v0[j].y);
        pk.y = h2pack(v0[j].z, v0[j].w);
        pk.z = h2pack(v1[j].x, v1[j].y);
        pk.w = h2pack(v1[j].z, v1[j].w);
        const size_t blk = ((size_t)rt * KC + kc) * (size_t)(128 * 64);
        *(uint4*)((char*)dst + blk + sw) = pk;
    }
}

// ---------------------------------------------------------------------------
// fp16 tensor-core GEMM, bulk-async, 6-stage, 2 CTAs/SM.
// CTA tile 128x128, BK=32, 4 warps (2x2) of 64x64 — halves smem read traffic
// per MMA vs 64x32 warp tiles (128 B/MMA vs 192 B/MMA).
// ---------------------------------------------------------------------------
#define BM 128
#define BN 128
#define ABLK 8192
#define BBLK 8192
#define STG (ABLK + BBLK)
#define NST 6
#define GEMM_SMEM (NST * STG)     // 98304

__global__ __launch_bounds__(128, 2) void gemm_tc(
    const __half* __restrict__ A, const __half* __restrict__ B,
    float* __restrict__ C, int N)
{
    extern __shared__ char smg[];
    __shared__ uint64_t s_mbar[NST];

    const uint32_t sbase = smem_u32(smg);
    const int tid = threadIdx.x;
    const int wid = tid >> 5;
    const int lane = tid & 31;
    const int wm = wid & 1;            // 2 m-slabs of 64
    const int wn = wid >> 1;           // 2 n-slabs of 64
    const int bmb = blockIdx.y;
    const int bnb = blockIdx.x;

    uint32_t mb[NST];
#pragma unroll
    for (int i = 0; i < NST; i++) mb[i] = smem_u32(&s_mbar[i]);

    if (tid == 0) {
        for (int i = 0; i < NST; i++) mbar_init(mb[i], 1);
        fence_proxy_async();
    }
    __syncthreads();

    const char* aG = (const char*)A + (size_t)bmb * KC * ABLK;
    const char* bG = (const char*)B + (size_t)bnb * KC * BBLK;

    auto issue = [&](int c, int s) {
        const uint32_t d = sbase + s * STG;
        mbar_expect_tx(mb[s], STG);
        bulk_g2s(d,        aG + (size_t)c * ABLK, ABLK, mb[s]);
        bulk_g2s(d + ABLK, bG + (size_t)c * BBLK, BBLK, mb[s]);
    };

    if (tid == 0)
        for (int i = 0; i < NST; i++) issue(i, i);

    float acc[4][8][4];
#pragma unroll
    for (int mt = 0; mt < 4; mt++)
#pragma unroll
        for (int nt = 0; nt < 8; nt++)
#pragma unroll
            for (int j = 0; j < 4; j++) acc[mt][nt][j] = 0.f;

    const int g = lane >> 3, r = lane & 7;

    for (int c = 0; c < KC; c++) {
        const int s = c % NST;
        mbar_wait(mb[s], (c / NST) & 1);

        const uint32_t aS = sbase + s * STG;
        const uint32_t bS = aS + ABLK;

#pragma unroll
        for (int ks = 0; ks < 2; ks++) {
            uint32_t bf[8][2];
#pragma unroll
            for (int p = 0; p < 4; p++) {
                const int nt = 2 * p + (g >> 1);
                const uint32_t a = sw64((uint32_t)((wn * 64 + nt * 8 + r) * 64 + ks * 32 + (g & 1) * 16));
                ldsm_x4(bS + a, bf[2 * p][0], bf[2 * p][1], bf[2 * p + 1][0], bf[2 * p + 1][1]);
            }
#pragma unroll
            for (int mt = 0; mt < 4; mt++) {
                const uint32_t a = sw64((uint32_t)((wm * 64 + mt * 16 + (g & 1) * 8 + r) * 64 + ks * 32 + (g >> 1) * 16));
                uint32_t af[4];
                ldsm_x4(aS + a, af[0], af[1], af[2], af[3]);
#pragma unroll
                for (int nt = 0; nt < 8; nt++)
                    mma_f16(acc[mt][nt], af, bf[nt]);
            }
        }
        __syncthreads();
        if (tid == 0 && c + NST < KC) issue(c + NST, s);
    }

    const int er = lane >> 2, ec = (lane & 3) * 2;
#pragma unroll
    for (int mt = 0; mt < 4; mt++) {
#pragma unroll
        for (int nt = 0; nt < 8; nt++) {
            const int row = bmb * BM + wm * 64 + mt * 16 + er;
            const int col = bnb * BN + wn * 64 + nt * 8 + ec;
            *(float2*)&C[(size_t)row * N + col]       = make_float2(acc[mt][nt][0], acc[mt][nt][1]);
            *(float2*)&C[(size_t)(row + 8) * N + col] = make_float2(acc[mt][nt][2], acc[mt][nt][3]);
        }
    }
}

// ---------------------------------------------------------------------------
// Warp-per-head RMSNorm + RoPE + scale + fp16 convert (proven).
// ---------------------------------------------------------------------------
__global__ __launch_bounds__(256) void rmsnorm_rope_h(
    const float* __restrict__ qkv,
    const float* __restrict__ qnw, const float* __restrict__ knw,
    const float* __restrict__ rope, const int* __restrict__ pos,
    __half* __restrict__ qo, __half* __restrict__ ko)
{
    const int w = (blockIdx.x * 256 + threadIdx.x) >> 5;
    const int lane = threadIdx.x & 31;
    const int tok = w / (NQH + NKVH);
    const int h = w % (NQH + NKVH);
    const bool isQ = h < NQH;
    const int colbase = isQ ? h * HD : QDIM + (h - NQH) * HD;

    const float4 v = *(const float4*)&qkv[(size_t)tok * QKVD + colbase + lane * 4];

    float ss = v.x * v.x + v.y * v.y + v.z * v.z + v.w * v.w;
#pragma unroll
    for (int off = 16; off; off >>= 1) ss += __shfl_xor_sync(0xffffffffu, ss, off);
    const float inv = rsqrtf(ss * (1.0f / HD) + 1e-6f);

    const float4 wt = *(const float4*)&(isQ ? qnw : knw)[lane * 4];
    float n0 = v.x * inv * wt.x, n1 = v.y * inv * wt.y;
    float n2 = v.z * inv * wt.z, n3 = v.w * inv * wt.w;

    const float p0 = __shfl_xor_sync(0xffffffffu, n0, 16);
    const float p1 = __shfl_xor_sync(0xffffffffu, n1, 16);
    const float p2 = __shfl_xor_sync(0xffffffffu, n2, 16);
    const float p3 = __shfl_xor_sync(0xffffffffu, n3, 16);

    const int pp = pos[tok];
    const int f = (lane & 15) * 4;
    const float4 cs0 = *(const float4*)&rope[(size_t)(pp * 64 + f) * 2];
    const float4 cs1 = *(const float4*)&rope[(size_t)(pp * 64 + f) * 2 + 4];

    float o0, o1, o2, o3;
    if (lane < 16) {
        o0 = n0 * cs0.x - p0 * cs0.y;
        o1 = n1 * cs0.z - p1 * cs0.w;
        o2 = n2 * cs1.x - p2 * cs1.y;
        o3 = n3 * cs1.z - p3 * cs1.w;
    } else {
        o0 = n0 * cs0.x + p0 * cs0.y;
        o1 = n1 * cs0.z + p1 * cs0.w;
        o2 = n2 * cs1.x + p2 * cs1.y;
        o3 = n3 * cs1.z + p3 * cs1.w;
    }
    if (isQ) {
        const float sc = 0.08838834764831845f;
        o0 *= sc; o1 *= sc; o2 *= sc; o3 *= sc;
    }

    uint2 outp = make_uint2(h2pack(o0, o1), h2pack(o2, o3));
    const size_t idx = isQ ? ((size_t)h * SEQ + tok) * HD + lane * 4
                           : ((size_t)(h - NQH) * SEQ + tok) * HD + lane * 4;
    if (isQ) *(uint2*)&qo[idx] = outp;
    else     *(uint2*)&ko[idx] = outp;
}

// ---------------------------------------------------------------------------
// V: transpose + fp16 convert (proven).
// ---------------------------------------------------------------------------
__global__ __launch_bounds__(256) void v_t_h(const float* __restrict__ qkv,
                                             __half* __restrict__ vo) {
    __shared__ float tile[32][33];
    const int tx = threadIdx.x, ty = threadIdx.y;
    const int tok0 = blockIdx.x * 32, c0 = blockIdx.y * 32;
#pragma unroll
    for (int j = ty; j < 32; j += 8)
        tile[j][tx] = qkv[(size_t)(tok0 + j) * QKVD + (QDIM + KVD) + c0 + tx];
    __syncthreads();
#pragma unroll
    for (int j = ty; j < 32; j += 8)
        vo[(size_t)(c0 + j) * SEQ + tok0 + tx] = __float2half_rn(tile[tx][j]);
}

// ---------------------------------------------------------------------------
// fp16 tensor-core flash attention (proven), 2 CTAs/SM, reversed qb.
// ---------------------------------------------------------------------------
#define ATT_SMEM (16384 + 2 * 32768)

__global__ __launch_bounds__(128, 2) void attn_tc(
    const __half* __restrict__ Q, const __half* __restrict__ K,
    const __half* __restrict__ V, __half* __restrict__ O)
{
    extern __shared__ char sma[];
    const uint32_t sb = smem_u32(sma);
    const int tid = threadIdx.x, wid = tid >> 5, lane = tid & 31;
    const int qb = (SEG_LEN / 64 - 1) - blockIdx.x;
    const int seg = blockIdx.y, qh = blockIdx.z;
    const int kvh = qh >> 2;
    const int qtok0 = seg * SEG_LEN + qb * 64;
    const int g = lane >> 3, r = lane & 7;

    const uint32_t Qs = sb;

    {
        const char* src = (const char*)(Q + ((size_t)qh * SEQ + qtok0) * HD);
        for (int i = tid; i < 1024; i += 128) {
            int row = i >> 4, u = i & 15;
            uint32_t off = sw256((uint32_t)(row * 256 + u * 16));
            cp_async16(Qs + off, src + row * 256 + u * 16);
        }
        cp_commit();
    }

    auto issue_kv = [&](int kb, int s) {
        const int kt = seg * SEG_LEN + kb * 64;
        const uint32_t base = sb + 16384 + s * 32768;
        const char* kG = (const char*)(K + ((size_t)kvh * SEQ + kt) * HD);
        for (int i = tid; i < 1024; i += 128) {
            int row = i >> 4, u = i & 15;
            uint32_t off = sw256((uint32_t)(row * 256 + u * 16));
            cp_async16(base + off, kG + row * 256 + u * 16);
        }
        const char* vG = (const char*)V + ((size_t)kvh * HD * SEQ + kt) * 2;
        for (int i = tid; i < 1024; i += 128) {
            int row = i >> 3, u = i & 7;
            uint32_t off = sw128((uint32_t)(row * 128 + u * 16));
            cp_async16(base + 16384 + off, vG + (size_t)row * SEQ * 2 + u * 16);
        }
        cp_commit();
    };

    issue_kv(0, 0);
    if (qb >= 1) issue_kv(1, 1); else cp_commit();

    float m0 = -CUDART_INF_F, m1 = -CUDART_INF_F, l0 = 0.f, l1 = 0.f;
    float o[16][4];
#pragma unroll
    for (int nt = 0; nt < 16; nt++)
#pragma unroll
        for (int j = 0; j < 4; j++) o[nt][j] = 0.f;

    for (int kb = 0; kb <= qb; kb++) {
        const int s = kb & 1;
        cp_wait1();
        __syncthreads();
        const uint32_t Ks = sb + 16384 + s * 32768;
        const uint32_t Vs = Ks + 16384;

        float sa[8][4];
#pragma unroll
        for (int nt = 0; nt < 8; nt++)
#pragma unroll
            for (int j = 0; j < 4; j++) sa[nt][j] = 0.f;

#pragma unroll
        for (int ks = 0; ks < 8; ks++) {
            const int arow = wid * 16 + (g & 1) * 8 + r;
            const uint32_t aoff = sw256((uint32_t)(arow * 256 + (ks * 2 + (g >> 1)) * 16));
            uint32_t af[4];
            ldsm_x4(Qs + aoff, af[0], af[1], af[2], af[3]);
            uint32_t bf[8][2];
#pragma unroll
            for (int p = 0; p < 4; p++) {
                const int nrow = (2 * p + (g >> 1)) * 8 + r;
                const uint32_t boff = sw256((uint32_t)(nrow * 256 + (ks * 2 + (g & 1)) * 16));
                ldsm_x4(Ks + boff, bf[2 * p][0], bf[2 * p][1], bf[2 * p + 1][0], bf[2 * p + 1][1]);
            }
#pragma unroll
            for (int nt = 0; nt < 8; nt++)
                mma_f16(sa[nt], af, bf[nt]);
        }

        if (kb == qb) {
            const int r0 = wid * 16 + (lane >> 2);
#pragma unroll
            for (int nt = 0; nt < 8; nt++) {
                const int c = nt * 8 + (lane & 3) * 2;
                if (c     > r0)     sa[nt][0] = -CUDART_INF_F;
                if (c + 1 > r0)     sa[nt][1] = -CUDART_INF_F;
                if (c     > r0 + 8) sa[nt][2] = -CUDART_INF_F;
                if (c + 1 > r0 + 8) sa[nt][3] = -CUDART_INF_F;
            }
        }

        {
            float mx0 = -CUDART_INF_F, mx1 = -CUDART_INF_F;
#pragma unroll
            for (int nt = 0; nt < 8; nt++) {
                mx0 = fmaxf(mx0, fmaxf(sa[nt][0], sa[nt][1]));
                mx1 = fmaxf(mx1, fmaxf(sa[nt][2], sa[nt][3]));
            }
            mx0 = fmaxf(mx0, __shfl_xor_sync(0xffffffffu, mx0, 1));
            mx0 = fmaxf(mx0, __shfl_xor_sync(0xffffffffu, mx0, 2));
            mx1 = fmaxf(mx1, __shfl_xor_sync(0xffffffffu, mx1, 1));
            mx1 = fmaxf(mx1, __shfl_xor_sync(0xffffffffu, mx1, 2));
            const float mn0 = fmaxf(m0, mx0), mn1 = fmaxf(m1, mx1);
            const float a0 = __expf(m0 - mn0), a1 = __expf(m1 - mn1);
            float sum0 = 0.f, sum1 = 0.f;
#pragma unroll
            for (int nt = 0; nt < 8; nt++) {
                sa[nt][0] = __expf(sa[nt][0] - mn0); sum0 += sa[nt][0];
                sa[nt][1] = __expf(sa[nt][1] - mn0); sum0 += sa[nt][1];
                sa[nt][2] = __expf(sa[nt][2] - mn1); sum1 += sa[nt][2];
                sa[nt][3] = __expf(sa[nt][3] - mn1); sum1 += sa[nt][3];
            }
            sum0 += __shfl_xor_sync(0xffffffffu, sum0, 1);
            sum0 += __shfl_xor_sync(0xffffffffu, sum0, 2);
            sum1 += __shfl_xor_sync(0xffffffffu, sum1, 1);
            sum1 += __shfl_xor_sync(0xffffffffu, sum1, 2);
            l0 = l0 * a0 + sum0;
            l1 = l1 * a1 + sum1;
            m0 = mn0; m1 = mn1;
#pragma unroll
            for (int nt = 0; nt < 16; nt++) {
                o[nt][0] *= a0; o[nt][1] *= a0;
                o[nt][2] *= a1; o[nt][3] *= a1;
            }
        }

#pragma unroll
        for (int kj = 0; kj < 4; kj++) {
            const int t0 = 2 * kj, t1 = t0 + 1;
            uint32_t pf[4];
            pf[0] = h2pack(sa[t0][0], sa[t0][1]);
            pf[1] = h2pack(sa[t0][2], sa[t0][3]);
            pf[2] = h2pack(sa[t1][0], sa[t1][1]);
            pf[3] = h2pack(sa[t1][2], sa[t1][3]);
#pragma unroll
            for (int p = 0; p < 8; p++) {
                const int vrow = (2 * p + (g >> 1)) * 8 + r;
                const uint32_t voff = sw128((uint32_t)(vrow * 128 + (kj * 2 + (g & 1)) * 16));
                uint32_t vf0[2], vf1[2];
                ldsm_x4(Vs + voff, vf0[0], vf0[1], vf1[0], vf1[1]);
                mma_f16(o[2 * p],     pf, vf0);
                mma_f16(o[2 * p + 1], pf, vf1);
            }
        }

        __syncthreads();
        if (kb + 2 <= qb) issue_kv(kb + 2, s); else cp_commit();
    }
    cp_wait0();

    const float li0 = 1.f / l0, li1 = 1.f / l1;
    const int tk0 = qtok0 + wid * 16 + (lane >> 2);
    const int tk1 = tk0 + 8;
#pragma unroll
    for (int nt = 0; nt < 16; nt++) {
        const int d = qh * HD + nt * 8 + (lane & 3) * 2;
        const size_t blk = ((size_t)(tk0 >> 7) * KC + (d >> 5)) * (size_t)(128 * 64);
        const uint32_t col2 = (uint32_t)((d & 31) * 2);
        const uint32_t lo4 = col2 & 15u;
        const uint32_t in0 = sw64((uint32_t)((tk0 & 127) * 64) + (col2 & ~15u)) + lo4;
        const uint32_t in1 = sw64((uint32_t)((tk1 & 127) * 64) + (col2 & ~15u)) + lo4;
        *(uint32_t*)((char*)O + blk + in0) = h2pack(o[nt][0] * li0, o[nt][1] * li0);
        *(uint32_t*)((char*)O + blk + in1) = h2pack(o[nt][2] * li1, o[nt][3] * li1);
    }
}

// ---------------------------------------------------------------------------
// Launch
// ---------------------------------------------------------------------------
extern "C" void kernel_launch(void* const* d_in, const int* in_sizes, int n_in,
                              void* d_out, int out_size) {
    const float* x    = (const float*)d_in[0];
    const float* wq   = (const float*)d_in[1];
    const float* wk   = (const float*)d_in[2];
    const float* wv   = (const float*)d_in[3];
    const float* wo   = (const float*)d_in[4];
    const float* qnw  = (const float*)d_in[5];
    const float* knw  = (const float*)d_in[6];
    const float* rope = (const float*)d_in[7];
    const int*   pos  = (const int*)d_in[8];

    float* qkv;
    cudaGetSymbolAddress((void**)&qkv, g_qkv);
    __half *xh, *oh, *wh, *woh, *qsh, *ksh, *vth;
    cudaGetSymbolAddress((void**)&xh, g_xh);
    cudaGetSymbolAddress((void**)&oh, g_oh);
    cudaGetSymbolAddress((void**)&wh, g_wh);
    cudaGetSymbolAddress((void**)&woh, g_woh);
    cudaGetSymbolAddress((void**)&qsh, g_qsh);
    cudaGetSymbolAddress((void**)&ksh, g_ksh);
    cudaGetSymbolAddress((void**)&vth, g_vth);

    cudaFuncSetAttribute(gemm_tc, cudaFuncAttributeMaxDynamicSharedMemorySize, GEMM_SMEM);
    cudaFuncSetAttribute(attn_tc, cudaFuncAttributeMaxDynamicSharedMemorySize, ATT_SMEM);

    // Fused pack
    {
        int nW = ((SEQ + QDIM + KVD + KVD + DIM) / 8) * (KC / 4);
        pack_all<<<(nW * 32 + 255) / 256, 256>>>(x, wq, wk, wv, wo, xh, wh, woh);
    }

    // Fused QKV projection (fp32 out)
    gemm_tc<<<dim3(QKVD / BN, SEQ / BM), 128, GEMM_SMEM>>>(xh, wh, qkv, QKVD);

    // RMSNorm + RoPE + convert; V transpose + convert
    {
        int nW = SEQ * (NQH + NKVH);
        rmsnorm_rope_h<<<(nW * 32 + 255) / 256, 256>>>(qkv, qnw, knw, rope, pos, qsh, ksh);
    }
    v_t_h<<<dim3(SEQ / 32, KVD / 32), dim3(32, 8)>>>(qkv, vth);

    // Attention (writes packed O)
    attn_tc<<<dim3(SEG_LEN / 64, N_SEG, NQH), 128, ATT_SMEM>>>(qsh, ksh, vth, oh);

    // Output projection
    gemm_tc<<<dim3(DIM / BN, SEQ / BM), 128, GEMM_SMEM>>>(oh, woh, (float*)d_out, DIM);
}